// round 1
// baseline (speedup 1.0000x reference)
#include <cuda_runtime.h>
#include <math.h>
#include <stdint.h>

// Problem constants
#define S_LEN   2048
#define HID     4096
#define NH      32
#define NKV     8
#define HD      128
#define QKV_DIM 6144   // NH*HD + 2*NKV*HD
#define GROUPS  4

// Scratch (no allocations allowed -> device globals)
__device__ float g_qkv[S_LEN * QKV_DIM];   // [S, 6144]
__device__ float g_attn[S_LEN * HID];      // [S, 4096]
__device__ float g_cos[S_LEN * 64];
__device__ float g_sin[S_LEN * 64];

// ---------------------------------------------------------------------------
// RoPE cos/sin table.  Match reference: inv_freq = base^(-2i/HD) in fp32,
// angle = fl32(pos * inv_freq).  Explicit range reduction (in double, cheap:
// only 128K threads) so that fast-math __cosf cannot lose accuracy at |x|~2000.
// ---------------------------------------------------------------------------
__global__ void rope_table_kernel(const int* __restrict__ pos_ids) {
    int idx = blockIdx.x * blockDim.x + threadIdx.x;
    if (idx >= S_LEN * 64) return;
    int s = idx >> 6;
    int d = idx & 63;
    float expo = (float)(2 * d) * (1.0f / 128.0f);
    float invf = exp2f(-expo * 16.609640474436813f);   // log2(100000)
    float a = (float)((double)pos_ids[s] * (double)invf);
    double ar = (double)a;
    double k  = rint(ar * 0.15915494309189535);        // 1/(2*pi)
    ar -= k * 6.283185307179586;
    float r = (float)ar;
    g_cos[idx] = cosf(r);
    g_sin[idx] = sinf(r);
}

// ---------------------------------------------------------------------------
// Apply RoPE in-place to Q (32 heads) and K (8 heads) inside g_qkv.
// thread -> (s, head, d<64), handles the (d, d+64) pair.
// ---------------------------------------------------------------------------
__global__ void rope_apply_kernel(float* __restrict__ qkv) {
    int idx = blockIdx.x * blockDim.x + threadIdx.x;
    if (idx >= S_LEN * (NH + NKV) * 64) return;
    int d    = idx & 63;
    int rem  = idx >> 6;
    int head = rem % (NH + NKV);
    int s    = rem / (NH + NKV);
    float* base = qkv + (size_t)s * QKV_DIM +
                  (head < NH ? head * HD : HID + (head - NH) * HD);
    float c  = g_cos[(s << 6) + d];
    float sn = g_sin[(s << 6) + d];
    float x1 = base[d];
    float x2 = base[d + 64];
    base[d]      = x1 * c - x2 * sn;
    base[d + 64] = x2 * c + x1 * sn;
}

// ---------------------------------------------------------------------------
// SGEMM (NT): C[m,n] = sum_k A[m*K+k] * B[n*K+k]
// 128x128 block tile, BK=16, 256 threads, 8x8 register tile per thread.
// ---------------------------------------------------------------------------
#define BM 128
#define BN 128
#define BK 16

__global__ __launch_bounds__(256) void sgemm_nt_kernel(
    const float* __restrict__ A, const float* __restrict__ B,
    float* __restrict__ C, int M, int N, int K)
{
    __shared__ float As[BK][BM + 4];
    __shared__ float Bs[BK][BN + 4];

    int tid = threadIdx.x;
    int tx = tid & 15;
    int ty = tid >> 4;
    int m0 = blockIdx.y * BM;
    int n0 = blockIdx.x * BN;

    float acc[8][8];
#pragma unroll
    for (int i = 0; i < 8; i++)
#pragma unroll
        for (int j = 0; j < 8; j++) acc[i][j] = 0.0f;

    const float* Ab = A + (size_t)m0 * K;
    const float* Bb = B + (size_t)n0 * K;

    for (int k0 = 0; k0 < K; k0 += BK) {
        __syncthreads();
#pragma unroll
        for (int i = 0; i < 2; i++) {
            int f   = tid + i * 256;   // 0..511, 512 float4 = 128 rows x 16 k
            int row = f >> 2;
            int seg = f & 3;
            float4 va = *(const float4*)(Ab + (size_t)row * K + k0 + seg * 4);
            As[seg * 4 + 0][row] = va.x;
            As[seg * 4 + 1][row] = va.y;
            As[seg * 4 + 2][row] = va.z;
            As[seg * 4 + 3][row] = va.w;
            float4 vb = *(const float4*)(Bb + (size_t)row * K + k0 + seg * 4);
            Bs[seg * 4 + 0][row] = vb.x;
            Bs[seg * 4 + 1][row] = vb.y;
            Bs[seg * 4 + 2][row] = vb.z;
            Bs[seg * 4 + 3][row] = vb.w;
        }
        __syncthreads();

#pragma unroll
        for (int kk = 0; kk < BK; kk++) {
            float a[8], b[8];
            *(float4*)&a[0] = *(const float4*)&As[kk][ty * 8];
            *(float4*)&a[4] = *(const float4*)&As[kk][ty * 8 + 4];
            *(float4*)&b[0] = *(const float4*)&Bs[kk][tx * 8];
            *(float4*)&b[4] = *(const float4*)&Bs[kk][tx * 8 + 4];
#pragma unroll
            for (int i = 0; i < 8; i++)
#pragma unroll
                for (int j = 0; j < 8; j++)
                    acc[i][j] += a[i] * b[j];
        }
    }

#pragma unroll
    for (int i = 0; i < 8; i++) {
        float* Crow = C + (size_t)(m0 + ty * 8 + i) * N + n0 + tx * 8;
        float4 v0 = make_float4(acc[i][0], acc[i][1], acc[i][2], acc[i][3]);
        float4 v1 = make_float4(acc[i][4], acc[i][5], acc[i][6], acc[i][7]);
        *(float4*)(Crow)     = v0;
        *(float4*)(Crow + 4) = v1;
    }
}

// ---------------------------------------------------------------------------
// Flash attention (causal, GQA groups=4).
// grid = (S/64, NH); block = 256 (8 warps).  Each warp owns 8 q-rows.
// Lane owns k-columns {lane, lane+32} and output dims {lane, lane+32, +64, +96}.
// K tile stored with row stride 129 -> conflict-free per-lane row access.
// ---------------------------------------------------------------------------
#define ATT_BQ 64
#define ATT_BK 64
#define ATT_SMEM_FLOATS (64 * 128 + 64 * 129 + 64 * 128)

__global__ __launch_bounds__(256) void attn_kernel(
    const float* __restrict__ qkv, float* __restrict__ out)
{
    extern __shared__ float sm[];
    float* Qs = sm;                    // 64 x 128
    float* Ks = Qs + 64 * 128;         // 64 x 129
    float* Vs = Ks + 64 * 129;         // 64 x 128

    int h    = blockIdx.y;
    int q0   = blockIdx.x * ATT_BQ;
    int kvh  = h >> 2;
    int tid  = threadIdx.x;
    int w    = tid >> 5;
    int lane = tid & 31;
    const float scale = 0.08838834764831845f;  // 1/sqrt(128)

    // Load Q tile (scaled)
#pragma unroll
    for (int i = 0; i < 8; i++) {
        int f   = tid + i * 256;
        int row = f >> 5;
        int c4  = f & 31;
        float4 v = *(const float4*)(qkv + (size_t)(q0 + row) * QKV_DIM + h * HD + c4 * 4);
        v.x *= scale; v.y *= scale; v.z *= scale; v.w *= scale;
        *(float4*)(Qs + row * 128 + c4 * 4) = v;
    }

    float o[8][4];
    float m[8], l[8];
#pragma unroll
    for (int r = 0; r < 8; r++) {
        m[r] = -1e30f; l[r] = 0.0f;
        o[r][0] = o[r][1] = o[r][2] = o[r][3] = 0.0f;
    }

    int r0 = w * 8;
    int ntiles = blockIdx.x + 1;   // causal: tiles 0 .. floor((q0+63)/64)

    for (int kt = 0; kt < ntiles; kt++) {
        __syncthreads();
        int krow0 = kt * ATT_BK;
#pragma unroll
        for (int i = 0; i < 8; i++) {
            int f   = tid + i * 256;
            int row = f >> 5;
            int c4  = f & 31;
            const float* src = qkv + (size_t)(krow0 + row) * QKV_DIM + HID + kvh * HD;
            float4 kv = *(const float4*)(src + c4 * 4);
            float* kd = Ks + row * 129 + c4 * 4;
            kd[0] = kv.x; kd[1] = kv.y; kd[2] = kv.z; kd[3] = kv.w;
            float4 vv = *(const float4*)(src + NKV * HD + c4 * 4);
            *(float4*)(Vs + row * 128 + c4 * 4) = vv;
        }
        __syncthreads();

        // ---- scores: s[r][{0,1}] = q_r . k_{lane}, q_r . k_{lane+32}
        float s0[8], s1[8];
#pragma unroll
        for (int r = 0; r < 8; r++) { s0[r] = 0.0f; s1[r] = 0.0f; }
        const float* kp0 = Ks + lane * 129;
        const float* kp1 = Ks + (lane + 32) * 129;
#pragma unroll 4
        for (int d = 0; d < HD; d += 4) {
            float ka0 = kp0[d], ka1 = kp0[d + 1], ka2 = kp0[d + 2], ka3 = kp0[d + 3];
            float kb0 = kp1[d], kb1 = kp1[d + 1], kb2 = kp1[d + 2], kb3 = kp1[d + 3];
#pragma unroll
            for (int r = 0; r < 8; r++) {
                float4 q4 = *(const float4*)(Qs + (r0 + r) * 128 + d);
                s0[r] += q4.x * ka0; s0[r] += q4.y * ka1;
                s0[r] += q4.z * ka2; s0[r] += q4.w * ka3;
                s1[r] += q4.x * kb0; s1[r] += q4.y * kb1;
                s1[r] += q4.z * kb2; s1[r] += q4.w * kb3;
            }
        }

        // ---- causal mask
        int c0 = krow0 + lane;
        int c1 = c0 + 32;
#pragma unroll
        for (int r = 0; r < 8; r++) {
            int q = q0 + r0 + r;
            if (c0 > q) s0[r] = -1e30f;
            if (c1 > q) s1[r] = -1e30f;
        }

        // ---- online softmax update
#pragma unroll
        for (int r = 0; r < 8; r++) {
            float mx = fmaxf(s0[r], s1[r]);
#pragma unroll
            for (int off = 16; off; off >>= 1)
                mx = fmaxf(mx, __shfl_xor_sync(0xffffffffu, mx, off));
            float mn   = fmaxf(m[r], mx);
            float corr = __expf(m[r] - mn);
            m[r] = mn;
            s0[r] = __expf(s0[r] - mn);
            s1[r] = __expf(s1[r] - mn);
            float ps = s0[r] + s1[r];
#pragma unroll
            for (int off = 16; off; off >>= 1)
                ps += __shfl_xor_sync(0xffffffffu, ps, off);
            l[r] = l[r] * corr + ps;
            o[r][0] *= corr; o[r][1] *= corr; o[r][2] *= corr; o[r][3] *= corr;
        }

        // ---- PV accumulation: broadcast p[r][j] from owning lane
#pragma unroll 4
        for (int j = 0; j < ATT_BK; j++) {
            const float* vp = Vs + j * 128 + lane;
            float v0 = vp[0], v1 = vp[32], v2 = vp[64], v3 = vp[96];
            int src = j & 31;
#pragma unroll
            for (int r = 0; r < 8; r++) {
                float p = __shfl_sync(0xffffffffu, (j < 32) ? s0[r] : s1[r], src);
                o[r][0] += p * v0;
                o[r][1] += p * v1;
                o[r][2] += p * v2;
                o[r][3] += p * v3;
            }
        }
    }

    // ---- epilogue
#pragma unroll
    for (int r = 0; r < 8; r++) {
        float inv = 1.0f / l[r];
        int q = q0 + r0 + r;
        float* dst = out + (size_t)q * HID + h * HD + lane;
        dst[0]  = o[r][0] * inv;
        dst[32] = o[r][1] * inv;
        dst[64] = o[r][2] * inv;
        dst[96] = o[r][3] * inv;
    }
}

// ---------------------------------------------------------------------------
// Launch
// ---------------------------------------------------------------------------
extern "C" void kernel_launch(void* const* d_in, const int* in_sizes, int n_in,
                              void* d_out, int out_size)
{
    (void)in_sizes; (void)n_in; (void)out_size;
    const float* x     = (const float*)d_in[0];
    const int*   pos   = (const int*)d_in[1];
    const float* w_qkv = (const float*)d_in[2];
    const float* w_o   = (const float*)d_in[3];
    float*       out   = (float*)d_out;

    void *p_qkv, *p_attn;
    cudaGetSymbolAddress(&p_qkv, g_qkv);
    cudaGetSymbolAddress(&p_attn, g_attn);
    float* qkv  = (float*)p_qkv;
    float* attn = (float*)p_attn;

    cudaFuncSetAttribute(attn_kernel, cudaFuncAttributeMaxDynamicSharedMemorySize,
                         ATT_SMEM_FLOATS * (int)sizeof(float));

    // RoPE table (independent of GEMM)
    rope_table_kernel<<<(S_LEN * 64 + 255) / 256, 256>>>(pos);

    // QKV projection: [2048,4096] x [6144,4096]^T -> [2048,6144]
    sgemm_nt_kernel<<<dim3(QKV_DIM / BN, S_LEN / BM), 256>>>(
        x, w_qkv, qkv, S_LEN, QKV_DIM, HID);

    // RoPE on q and k
    rope_apply_kernel<<<(S_LEN * (NH + NKV) * 64 + 255) / 256, 256>>>(qkv);

    // Flash attention
    attn_kernel<<<dim3(S_LEN / ATT_BQ, NH), 256, ATT_SMEM_FLOATS * sizeof(float)>>>(
        qkv, attn);

    // Output projection: [2048,4096] x [4096,4096]^T -> [2048,4096]
    sgemm_nt_kernel<<<dim3(HID / BN, S_LEN / BM), 256>>>(
        attn, w_o, out, S_LEN, HID, HID);
}

// round 3
// speedup vs baseline: 1.7587x; 1.7587x over previous
#include <cuda_runtime.h>
#include <cuda_bf16.h>
#include <math.h>
#include <stdint.h>

// Problem constants
#define S_LEN   2048
#define HID     4096
#define NH      32
#define NKV     8
#define HD      128
#define QKV_DIM 6144   // NH*HD + 2*NKV*HD
#define GROUPS  4

// ---------------------------------------------------------------------------
// Device scratch (no allocations allowed)
// ---------------------------------------------------------------------------
__device__ float g_qkv[S_LEN * QKV_DIM];   // [S, 6144] fp32
__device__ float g_attn[S_LEN * HID];      // [S, 4096] fp32
__device__ float g_cos[S_LEN * 64];
__device__ float g_sin[S_LEN * 64];

__device__ __align__(128) __nv_bfloat16 g_x_hi[S_LEN * HID];
__device__ __align__(128) __nv_bfloat16 g_x_lo[S_LEN * HID];
__device__ __align__(128) __nv_bfloat16 g_wqkv_hi[QKV_DIM * HID];
__device__ __align__(128) __nv_bfloat16 g_wqkv_lo[QKV_DIM * HID];
__device__ __align__(128) __nv_bfloat16 g_attn_hi[S_LEN * HID];
__device__ __align__(128) __nv_bfloat16 g_attn_lo[S_LEN * HID];
__device__ __align__(128) __nv_bfloat16 g_wo_hi[HID * HID];
__device__ __align__(128) __nv_bfloat16 g_wo_lo[HID * HID];

// ---------------------------------------------------------------------------
// Helpers
// ---------------------------------------------------------------------------
static __device__ __forceinline__ uint32_t smem_u32(const void* p) {
    uint32_t a;
    asm("{ .reg .u64 t; cvta.to.shared.u64 t, %1; cvt.u32.u64 %0, t; }"
        : "=r"(a) : "l"(p));
    return a;
}

static __device__ __forceinline__ void cp16(uint32_t dst, const void* src) {
    asm volatile("cp.async.cg.shared.global [%0], [%1], 16;"
                 :: "r"(dst), "l"(src));
}

static __device__ __forceinline__ void ldsm_x4(uint32_t& r0, uint32_t& r1,
                                               uint32_t& r2, uint32_t& r3,
                                               uint32_t addr) {
    asm volatile("ldmatrix.sync.aligned.m8n8.x4.shared.b16 {%0,%1,%2,%3}, [%4];"
                 : "=r"(r0), "=r"(r1), "=r"(r2), "=r"(r3) : "r"(addr));
}

static __device__ __forceinline__ void ldsm_x2(uint32_t& r0, uint32_t& r1,
                                               uint32_t addr) {
    asm volatile("ldmatrix.sync.aligned.m8n8.x2.shared.b16 {%0,%1}, [%2];"
                 : "=r"(r0), "=r"(r1) : "r"(addr));
}

static __device__ __forceinline__ void mma16816(float* d, const uint32_t* a,
                                                const uint32_t* b) {
    asm volatile(
        "mma.sync.aligned.m16n8k16.row.col.f32.bf16.bf16.f32 "
        "{%0,%1,%2,%3}, {%4,%5,%6,%7}, {%8,%9}, {%0,%1,%2,%3};"
        : "+f"(d[0]), "+f"(d[1]), "+f"(d[2]), "+f"(d[3])
        : "r"(a[0]), "r"(a[1]), "r"(a[2]), "r"(a[3]), "r"(b[0]), "r"(b[1]));
}

// ---------------------------------------------------------------------------
// fp32 -> bf16 hi/lo split
// ---------------------------------------------------------------------------
__global__ void convert_split_kernel(const float* __restrict__ src,
                                     __nv_bfloat16* __restrict__ hi,
                                     __nv_bfloat16* __restrict__ lo, int n) {
    int i = blockIdx.x * blockDim.x + threadIdx.x;
    if (i >= n) return;
    float x = src[i];
    __nv_bfloat16 h = __float2bfloat16_rn(x);
    float r = x - __bfloat162float(h);
    hi[i] = h;
    lo[i] = __float2bfloat16_rn(r);
}

// ---------------------------------------------------------------------------
// RoPE table + apply (verified)
// ---------------------------------------------------------------------------
__global__ void rope_table_kernel(const int* __restrict__ pos_ids) {
    int idx = blockIdx.x * blockDim.x + threadIdx.x;
    if (idx >= S_LEN * 64) return;
    int s = idx >> 6;
    int d = idx & 63;
    float expo = (float)(2 * d) * (1.0f / 128.0f);
    float invf = exp2f(-expo * 16.609640474436813f);   // log2(100000)
    float a = (float)((double)pos_ids[s] * (double)invf);
    double ar = (double)a;
    double k  = rint(ar * 0.15915494309189535);
    ar -= k * 6.283185307179586;
    float r = (float)ar;
    g_cos[idx] = cosf(r);
    g_sin[idx] = sinf(r);
}

__global__ void rope_apply_kernel(float* __restrict__ qkv) {
    int idx = blockIdx.x * blockDim.x + threadIdx.x;
    if (idx >= S_LEN * (NH + NKV) * 64) return;
    int d    = idx & 63;
    int rem  = idx >> 6;
    int head = rem % (NH + NKV);
    int s    = rem / (NH + NKV);
    float* base = qkv + (size_t)s * QKV_DIM +
                  (head < NH ? head * HD : HID + (head - NH) * HD);
    float c  = g_cos[(s << 6) + d];
    float sn = g_sin[(s << 6) + d];
    float x1 = base[d];
    float x2 = base[d + 64];
    base[d]      = x1 * c - x2 * sn;
    base[d + 64] = x2 * c + x1 * sn;
}

// ---------------------------------------------------------------------------
// bf16-split GEMM via mma.sync (NT): C[m,n] = sum_k A[m,k]*B[n,k]
// CTA 128x128, BK=32, 256 threads (2x4 warps, warp tile 64x32).
// C = Ah*Bh + Ah*Bl + Al*Bh, fp32 accumulators.
// Smem rows padded to 80B -> conflict-free ldmatrix.
// ---------------------------------------------------------------------------
#define ROWB 80                       // bytes per smem row (32 bf16 + 8 pad)
#define T_BYTES (128 * ROWB)          // 10240 per tensor
#define OFF_AHI 0
#define OFF_ALO (1 * T_BYTES)
#define OFF_BHI (2 * T_BYTES)
#define OFF_BLO (3 * T_BYTES)
#define STAGE_BYTES (4 * T_BYTES)     // 40960
#define GEMM_SMEM (2 * STAGE_BYTES)   // 81920

__global__ __launch_bounds__(256) void gemm_mma_split_kernel(
    const __nv_bfloat16* __restrict__ Ahi, const __nv_bfloat16* __restrict__ Alo,
    const __nv_bfloat16* __restrict__ Bhi, const __nv_bfloat16* __restrict__ Blo,
    float* __restrict__ C, int K, int N)
{
    extern __shared__ char smc[];
    uint32_t sb = smem_u32(smc);
    int tid  = threadIdx.x;
    int wid  = tid >> 5;
    int lane = tid & 31;
    int wm = wid >> 2;     // 0..1
    int wn = wid & 3;      // 0..3
    int m0 = blockIdx.x * 128;
    int n0 = blockIdx.y * 128;

    const size_t rs = (size_t)K * 2;   // gmem row stride bytes
    const char* pAhi = (const char*)Ahi + (size_t)m0 * rs;
    const char* pAlo = (const char*)Alo + (size_t)m0 * rs;
    const char* pBhi = (const char*)Bhi + (size_t)n0 * rs;
    const char* pBlo = (const char*)Blo + (size_t)n0 * rs;

    // per-thread load slots: 512 16B-chunks per tensor, 2 per thread
    int row_a = tid >> 1;              // unused placeholder (kept simple below)
    (void)row_a;

    auto load_chunk = [&](int stage, int c) {
        uint32_t base = sb + stage * STAGE_BYTES;
        size_t kb = (size_t)c * 64;    // 32 bf16 = 64 bytes per chunk-row
#pragma unroll
        for (int i = 0; i < 2; i++) {
            int f = tid + i * 256;     // 0..511 = 128 rows x 4 segs
            int row = f >> 2;
            int seg = (f & 3) * 16;
            uint32_t so = (uint32_t)(row * ROWB + seg);
            const size_t go = (size_t)row * rs + kb + seg;
            cp16(base + OFF_AHI + so, pAhi + go);
            cp16(base + OFF_ALO + so, pAlo + go);
            cp16(base + OFF_BHI + so, pBhi + go);
            cp16(base + OFF_BLO + so, pBlo + go);
        }
        asm volatile("cp.async.commit_group;" ::: "memory");
    };

    float acc[16][4];
#pragma unroll
    for (int t = 0; t < 16; t++)
#pragma unroll
        for (int j = 0; j < 4; j++) acc[t][j] = 0.0f;

    // ldmatrix base offsets (within a tensor)
    uint32_t a_off = (uint32_t)((wm * 64 + (lane & 15)) * ROWB + (lane >> 4) * 16);
    uint32_t b_off = (uint32_t)((wn * 32 + (lane & 7)) * ROWB + ((lane >> 3) & 1) * 16);

    int nch = K / 32;
    load_chunk(0, 0);

    for (int c = 0; c < nch; c++) {
        int buf = c & 1;
        if (c + 1 < nch) {
            load_chunk(buf ^ 1, c + 1);
            asm volatile("cp.async.wait_group 1;" ::: "memory");
        } else {
            asm volatile("cp.async.wait_group 0;" ::: "memory");
        }
        __syncthreads();

        uint32_t tb = sb + buf * STAGE_BYTES;
#pragma unroll
        for (int ks = 0; ks < 2; ks++) {
            uint32_t ko = (uint32_t)(ks * 32);
            // B fragments (hi and lo), 4 n-tiles
            uint32_t bh[4][2], bl[4][2];
#pragma unroll
            for (int nt = 0; nt < 4; nt++) {
                uint32_t bo = b_off + ko + (uint32_t)(nt * 8 * ROWB);
                ldsm_x2(bh[nt][0], bh[nt][1], tb + OFF_BHI + bo);
                ldsm_x2(bl[nt][0], bl[nt][1], tb + OFF_BLO + bo);
            }
            // A hi fragments: Ah*Bh and Ah*Bl
#pragma unroll
            for (int mt = 0; mt < 4; mt++) {
                uint32_t ah[4];
                uint32_t ao = a_off + ko + (uint32_t)(mt * 16 * ROWB);
                ldsm_x4(ah[0], ah[1], ah[2], ah[3], tb + OFF_AHI + ao);
#pragma unroll
                for (int nt = 0; nt < 4; nt++) {
                    mma16816(acc[mt * 4 + nt], ah, bh[nt]);
                    mma16816(acc[mt * 4 + nt], ah, bl[nt]);
                }
            }
            // A lo fragments: Al*Bh
#pragma unroll
            for (int mt = 0; mt < 4; mt++) {
                uint32_t al[4];
                uint32_t ao = a_off + ko + (uint32_t)(mt * 16 * ROWB);
                ldsm_x4(al[0], al[1], al[2], al[3], tb + OFF_ALO + ao);
#pragma unroll
                for (int nt = 0; nt < 4; nt++)
                    mma16816(acc[mt * 4 + nt], al, bh[nt]);
            }
        }
        __syncthreads();
    }

    // Epilogue
    int mbase = m0 + wm * 64 + (lane >> 2);
    int nbase = n0 + wn * 32 + (lane & 3) * 2;
#pragma unroll
    for (int mt = 0; mt < 4; mt++) {
#pragma unroll
        for (int nt = 0; nt < 4; nt++) {
            float* d = acc[mt * 4 + nt];
            int r = mbase + mt * 16;
            int cc = nbase + nt * 8;
            *(float2*)(C + (size_t)r * N + cc)       = make_float2(d[0], d[1]);
            *(float2*)(C + (size_t)(r + 8) * N + cc) = make_float2(d[2], d[3]);
        }
    }
}

// ---------------------------------------------------------------------------
// Flash attention (causal, GQA groups=4) — unchanged (verified)
// ---------------------------------------------------------------------------
#define ATT_BQ 64
#define ATT_BK 64
#define ATT_SMEM_FLOATS (64 * 128 + 64 * 129 + 64 * 128)

__global__ __launch_bounds__(256) void attn_kernel(
    const float* __restrict__ qkv, float* __restrict__ out)
{
    extern __shared__ float sm[];
    float* Qs = sm;                    // 64 x 128
    float* Ks = Qs + 64 * 128;         // 64 x 129
    float* Vs = Ks + 64 * 129;         // 64 x 128

    int h    = blockIdx.y;
    int q0   = blockIdx.x * ATT_BQ;
    int kvh  = h >> 2;
    int tid  = threadIdx.x;
    int w    = tid >> 5;
    int lane = tid & 31;
    const float scale = 0.08838834764831845f;  // 1/sqrt(128)

#pragma unroll
    for (int i = 0; i < 8; i++) {
        int f   = tid + i * 256;
        int row = f >> 5;
        int c4  = f & 31;
        float4 v = *(const float4*)(qkv + (size_t)(q0 + row) * QKV_DIM + h * HD + c4 * 4);
        v.x *= scale; v.y *= scale; v.z *= scale; v.w *= scale;
        *(float4*)(Qs + row * 128 + c4 * 4) = v;
    }

    float o[8][4];
    float m[8], l[8];
#pragma unroll
    for (int r = 0; r < 8; r++) {
        m[r] = -1e30f; l[r] = 0.0f;
        o[r][0] = o[r][1] = o[r][2] = o[r][3] = 0.0f;
    }

    int r0 = w * 8;
    int ntiles = blockIdx.x + 1;

    for (int kt = 0; kt < ntiles; kt++) {
        __syncthreads();
        int krow0 = kt * ATT_BK;
#pragma unroll
        for (int i = 0; i < 8; i++) {
            int f   = tid + i * 256;
            int row = f >> 5;
            int c4  = f & 31;
            const float* src = qkv + (size_t)(krow0 + row) * QKV_DIM + HID + kvh * HD;
            float4 kv = *(const float4*)(src + c4 * 4);
            float* kd = Ks + row * 129 + c4 * 4;
            kd[0] = kv.x; kd[1] = kv.y; kd[2] = kv.z; kd[3] = kv.w;
            float4 vv = *(const float4*)(src + NKV * HD + c4 * 4);
            *(float4*)(Vs + row * 128 + c4 * 4) = vv;
        }
        __syncthreads();

        float s0[8], s1[8];
#pragma unroll
        for (int r = 0; r < 8; r++) { s0[r] = 0.0f; s1[r] = 0.0f; }
        const float* kp0 = Ks + lane * 129;
        const float* kp1 = Ks + (lane + 32) * 129;
#pragma unroll 4
        for (int d = 0; d < HD; d += 4) {
            float ka0 = kp0[d], ka1 = kp0[d + 1], ka2 = kp0[d + 2], ka3 = kp0[d + 3];
            float kb0 = kp1[d], kb1 = kp1[d + 1], kb2 = kp1[d + 2], kb3 = kp1[d + 3];
#pragma unroll
            for (int r = 0; r < 8; r++) {
                float4 q4 = *(const float4*)(Qs + (r0 + r) * 128 + d);
                s0[r] += q4.x * ka0; s0[r] += q4.y * ka1;
                s0[r] += q4.z * ka2; s0[r] += q4.w * ka3;
                s1[r] += q4.x * kb0; s1[r] += q4.y * kb1;
                s1[r] += q4.z * kb2; s1[r] += q4.w * kb3;
            }
        }

        int c0 = krow0 + lane;
        int c1 = c0 + 32;
#pragma unroll
        for (int r = 0; r < 8; r++) {
            int q = q0 + r0 + r;
            if (c0 > q) s0[r] = -1e30f;
            if (c1 > q) s1[r] = -1e30f;
        }

#pragma unroll
        for (int r = 0; r < 8; r++) {
            float mx = fmaxf(s0[r], s1[r]);
#pragma unroll
            for (int off = 16; off; off >>= 1)
                mx = fmaxf(mx, __shfl_xor_sync(0xffffffffu, mx, off));
            float mn   = fmaxf(m[r], mx);
            float corr = __expf(m[r] - mn);
            m[r] = mn;
            s0[r] = __expf(s0[r] - mn);
            s1[r] = __expf(s1[r] - mn);
            float ps = s0[r] + s1[r];
#pragma unroll
            for (int off = 16; off; off >>= 1)
                ps += __shfl_xor_sync(0xffffffffu, ps, off);
            l[r] = l[r] * corr + ps;
            o[r][0] *= corr; o[r][1] *= corr; o[r][2] *= corr; o[r][3] *= corr;
        }

#pragma unroll 4
        for (int j = 0; j < ATT_BK; j++) {
            const float* vp = Vs + j * 128 + lane;
            float v0 = vp[0], v1 = vp[32], v2 = vp[64], v3 = vp[96];
            int src = j & 31;
#pragma unroll
            for (int r = 0; r < 8; r++) {
                float p = __shfl_sync(0xffffffffu, (j < 32) ? s0[r] : s1[r], src);
                o[r][0] += p * v0;
                o[r][1] += p * v1;
                o[r][2] += p * v2;
                o[r][3] += p * v3;
            }
        }
    }

#pragma unroll
    for (int r = 0; r < 8; r++) {
        float inv = 1.0f / l[r];
        int q = q0 + r0 + r;
        float* dst = out + (size_t)q * HID + h * HD + lane;
        dst[0]  = o[r][0] * inv;
        dst[32] = o[r][1] * inv;
        dst[64] = o[r][2] * inv;
        dst[96] = o[r][3] * inv;
    }
}

// ---------------------------------------------------------------------------
// Launch
// ---------------------------------------------------------------------------
extern "C" void kernel_launch(void* const* d_in, const int* in_sizes, int n_in,
                              void* d_out, int out_size)
{
    (void)in_sizes; (void)n_in; (void)out_size;
    const float* x     = (const float*)d_in[0];
    const int*   pos   = (const int*)d_in[1];
    const float* w_qkv = (const float*)d_in[2];
    const float* w_o   = (const float*)d_in[3];
    float*       out   = (float*)d_out;

    void *p_qkv, *p_attn;
    void *p_xh, *p_xl, *p_wqh, *p_wql, *p_ah, *p_al, *p_woh, *p_wol;
    cudaGetSymbolAddress(&p_qkv, g_qkv);
    cudaGetSymbolAddress(&p_attn, g_attn);
    cudaGetSymbolAddress(&p_xh, g_x_hi);
    cudaGetSymbolAddress(&p_xl, g_x_lo);
    cudaGetSymbolAddress(&p_wqh, g_wqkv_hi);
    cudaGetSymbolAddress(&p_wql, g_wqkv_lo);
    cudaGetSymbolAddress(&p_ah, g_attn_hi);
    cudaGetSymbolAddress(&p_al, g_attn_lo);
    cudaGetSymbolAddress(&p_woh, g_wo_hi);
    cudaGetSymbolAddress(&p_wol, g_wo_lo);
    float* qkv  = (float*)p_qkv;
    float* attn = (float*)p_attn;

    cudaFuncSetAttribute(attn_kernel, cudaFuncAttributeMaxDynamicSharedMemorySize,
                         ATT_SMEM_FLOATS * (int)sizeof(float));
    cudaFuncSetAttribute(gemm_mma_split_kernel,
                         cudaFuncAttributeMaxDynamicSharedMemorySize, GEMM_SMEM);

    // RoPE table
    rope_table_kernel<<<(S_LEN * 64 + 255) / 256, 256>>>(pos);

    // Split inputs to bf16 hi/lo
    {
        int n1 = S_LEN * HID;
        convert_split_kernel<<<(n1 + 255) / 256, 256>>>(
            x, (__nv_bfloat16*)p_xh, (__nv_bfloat16*)p_xl, n1);
        int n2 = QKV_DIM * HID;
        convert_split_kernel<<<(n2 + 255) / 256, 256>>>(
            w_qkv, (__nv_bfloat16*)p_wqh, (__nv_bfloat16*)p_wql, n2);
        int n3 = HID * HID;
        convert_split_kernel<<<(n3 + 255) / 256, 256>>>(
            w_o, (__nv_bfloat16*)p_woh, (__nv_bfloat16*)p_wol, n3);
    }

    // QKV projection: [2048,4096] x [6144,4096]^T -> [2048,6144]
    gemm_mma_split_kernel<<<dim3(S_LEN / 128, QKV_DIM / 128), 256, GEMM_SMEM>>>(
        (const __nv_bfloat16*)p_xh, (const __nv_bfloat16*)p_xl,
        (const __nv_bfloat16*)p_wqh, (const __nv_bfloat16*)p_wql,
        qkv, HID, QKV_DIM);

    // RoPE
    rope_apply_kernel<<<(S_LEN * (NH + NKV) * 64 + 255) / 256, 256>>>(qkv);

    // Flash attention
    attn_kernel<<<dim3(S_LEN / ATT_BQ, NH), 256, ATT_SMEM_FLOATS * sizeof(float)>>>(
        qkv, attn);

    // Split attention output
    {
        int n4 = S_LEN * HID;
        convert_split_kernel<<<(n4 + 255) / 256, 256>>>(
            attn, (__nv_bfloat16*)p_ah, (__nv_bfloat16*)p_al, n4);
    }

    // Output projection: [2048,4096] x [4096,4096]^T -> [2048,4096]
    gemm_mma_split_kernel<<<dim3(S_LEN / 128, HID / 128), 256, GEMM_SMEM>>>(
        (const __nv_bfloat16*)p_ah, (const __nv_bfloat16*)p_al,
        (const __nv_bfloat16*)p_woh, (const __nv_bfloat16*)p_wol,
        out, HID, HID);
}

// round 4
// speedup vs baseline: 2.6001x; 1.4784x over previous
#include <cuda_runtime.h>
#include <cuda_bf16.h>
#include <math.h>
#include <stdint.h>

// Problem constants
#define S_LEN   2048
#define HID     4096
#define NH      32
#define NKV     8
#define HD      128
#define QKV_DIM 6144   // NH*HD + 2*NKV*HD
#define GROUPS  4

// ---------------------------------------------------------------------------
// Device scratch (no allocations allowed)
// ---------------------------------------------------------------------------
__device__ float g_qkv[S_LEN * QKV_DIM];   // [S, 6144] fp32 (QKV GEMM out)
__device__ float g_cos[S_LEN * 64];
__device__ float g_sin[S_LEN * 64];

__device__ __align__(128) __nv_bfloat16 g_x_hi[S_LEN * HID];
__device__ __align__(128) __nv_bfloat16 g_x_lo[S_LEN * HID];
__device__ __align__(128) __nv_bfloat16 g_wqkv_hi[QKV_DIM * HID];
__device__ __align__(128) __nv_bfloat16 g_wqkv_lo[QKV_DIM * HID];
__device__ __align__(128) __nv_bfloat16 g_wo_hi[HID * HID];
__device__ __align__(128) __nv_bfloat16 g_wo_lo[HID * HID];
// split (post-RoPE) qkv, and split attention output
__device__ __align__(128) __nv_bfloat16 g_qkvsp_hi[S_LEN * QKV_DIM];
__device__ __align__(128) __nv_bfloat16 g_qkvsp_lo[S_LEN * QKV_DIM];
__device__ __align__(128) __nv_bfloat16 g_attn_hi[S_LEN * HID];
__device__ __align__(128) __nv_bfloat16 g_attn_lo[S_LEN * HID];

// ---------------------------------------------------------------------------
// Helpers
// ---------------------------------------------------------------------------
static __device__ __forceinline__ uint32_t smem_u32(const void* p) {
    uint32_t a;
    asm("{ .reg .u64 t; cvta.to.shared.u64 t, %1; cvt.u32.u64 %0, t; }"
        : "=r"(a) : "l"(p));
    return a;
}

static __device__ __forceinline__ void cp16(uint32_t dst, const void* src) {
    asm volatile("cp.async.cg.shared.global [%0], [%1], 16;"
                 :: "r"(dst), "l"(src));
}

static __device__ __forceinline__ void ldsm_x4(uint32_t& r0, uint32_t& r1,
                                               uint32_t& r2, uint32_t& r3,
                                               uint32_t addr) {
    asm volatile("ldmatrix.sync.aligned.m8n8.x4.shared.b16 {%0,%1,%2,%3}, [%4];"
                 : "=r"(r0), "=r"(r1), "=r"(r2), "=r"(r3) : "r"(addr));
}

static __device__ __forceinline__ void ldsm_x4t(uint32_t& r0, uint32_t& r1,
                                                uint32_t& r2, uint32_t& r3,
                                                uint32_t addr) {
    asm volatile("ldmatrix.sync.aligned.m8n8.x4.trans.shared.b16 {%0,%1,%2,%3}, [%4];"
                 : "=r"(r0), "=r"(r1), "=r"(r2), "=r"(r3) : "r"(addr));
}

static __device__ __forceinline__ void ldsm_x2(uint32_t& r0, uint32_t& r1,
                                               uint32_t addr) {
    asm volatile("ldmatrix.sync.aligned.m8n8.x2.shared.b16 {%0,%1}, [%2];"
                 : "=r"(r0), "=r"(r1) : "r"(addr));
}

static __device__ __forceinline__ void mma16816(float* d, const uint32_t* a,
                                                const uint32_t* b) {
    asm volatile(
        "mma.sync.aligned.m16n8k16.row.col.f32.bf16.bf16.f32 "
        "{%0,%1,%2,%3}, {%4,%5,%6,%7}, {%8,%9}, {%0,%1,%2,%3};"
        : "+f"(d[0]), "+f"(d[1]), "+f"(d[2]), "+f"(d[3])
        : "r"(a[0]), "r"(a[1]), "r"(a[2]), "r"(a[3]), "r"(b[0]), "r"(b[1]));
}

// pack two fp32 into bf16x2: low half <- lo, high half <- hi
static __device__ __forceinline__ uint32_t pack_bf16x2(float lo, float hi) {
    uint32_t d;
    asm("cvt.rn.bf16x2.f32 %0, %1, %2;" : "=r"(d) : "f"(hi), "f"(lo));
    return d;
}
static __device__ __forceinline__ float bf16lo_f(uint32_t u) {
    return __uint_as_float(u << 16);
}
static __device__ __forceinline__ float bf16hi_f(uint32_t u) {
    return __uint_as_float(u & 0xffff0000u);
}

// ---------------------------------------------------------------------------
// fp32 -> bf16 hi/lo split
// ---------------------------------------------------------------------------
__global__ void convert_split_kernel(const float* __restrict__ src,
                                     __nv_bfloat16* __restrict__ hi,
                                     __nv_bfloat16* __restrict__ lo, int n) {
    int i = blockIdx.x * blockDim.x + threadIdx.x;
    if (i >= n) return;
    float x = src[i];
    __nv_bfloat16 h = __float2bfloat16_rn(x);
    float r = x - __bfloat162float(h);
    hi[i] = h;
    lo[i] = __float2bfloat16_rn(r);
}

// ---------------------------------------------------------------------------
// RoPE table (verified)
// ---------------------------------------------------------------------------
__global__ void rope_table_kernel(const int* __restrict__ pos_ids) {
    int idx = blockIdx.x * blockDim.x + threadIdx.x;
    if (idx >= S_LEN * 64) return;
    int s = idx >> 6;
    int d = idx & 63;
    float expo = (float)(2 * d) * (1.0f / 128.0f);
    float invf = exp2f(-expo * 16.609640474436813f);   // log2(100000)
    float a = (float)((double)pos_ids[s] * (double)invf);
    double ar = (double)a;
    double k  = rint(ar * 0.15915494309189535);
    ar -= k * 6.283185307179586;
    float r = (float)ar;
    g_cos[idx] = cosf(r);
    g_sin[idx] = sinf(r);
}

// ---------------------------------------------------------------------------
// Post-QKV: apply RoPE to q,k (fold 1/sqrt(HD) into q), split ALL of qkv
// into bf16 hi/lo.  head 0..31 = q (rope+scale), 32..39 = k (rope), 40..47 = v.
// ---------------------------------------------------------------------------
__global__ void postqkv_kernel(const float* __restrict__ qkv,
                               __nv_bfloat16* __restrict__ hi,
                               __nv_bfloat16* __restrict__ lo) {
    int idx = blockIdx.x * blockDim.x + threadIdx.x;
    if (idx >= S_LEN * 48 * 64) return;
    int d    = idx & 63;
    int rem  = idx >> 6;
    int head = rem % 48;
    int s    = rem / 48;
    size_t base = (size_t)s * QKV_DIM + head * 64 * 2;  // head*128
    const float* b = qkv + base;
    float x1 = b[d];
    float x2 = b[d + 64];
    if (head < 40) {
        float c  = g_cos[(s << 6) + d];
        float sn = g_sin[(s << 6) + d];
        float y1 = x1 * c - x2 * sn;
        float y2 = x2 * c + x1 * sn;
        if (head < 32) {
            y1 *= 0.08838834764831845f;   // 1/sqrt(128)
            y2 *= 0.08838834764831845f;
        }
        x1 = y1; x2 = y2;
    }
    __nv_bfloat16 h1 = __float2bfloat16_rn(x1);
    __nv_bfloat16 h2 = __float2bfloat16_rn(x2);
    hi[base + d]      = h1;
    lo[base + d]      = __float2bfloat16_rn(x1 - __bfloat162float(h1));
    hi[base + d + 64] = h2;
    lo[base + d + 64] = __float2bfloat16_rn(x2 - __bfloat162float(h2));
}

// ---------------------------------------------------------------------------
// bf16-split GEMM via mma.sync (NT) — unchanged from round 3 (verified)
// ---------------------------------------------------------------------------
#define ROWB 80
#define T_BYTES (128 * ROWB)
#define OFF_AHI 0
#define OFF_ALO (1 * T_BYTES)
#define OFF_BHI (2 * T_BYTES)
#define OFF_BLO (3 * T_BYTES)
#define STAGE_BYTES (4 * T_BYTES)
#define GEMM_SMEM (2 * STAGE_BYTES)

__global__ __launch_bounds__(256) void gemm_mma_split_kernel(
    const __nv_bfloat16* __restrict__ Ahi, const __nv_bfloat16* __restrict__ Alo,
    const __nv_bfloat16* __restrict__ Bhi, const __nv_bfloat16* __restrict__ Blo,
    float* __restrict__ C, int K, int N)
{
    extern __shared__ char smc[];
    uint32_t sb = smem_u32(smc);
    int tid  = threadIdx.x;
    int wid  = tid >> 5;
    int lane = tid & 31;
    int wm = wid >> 2;
    int wn = wid & 3;
    int m0 = blockIdx.x * 128;
    int n0 = blockIdx.y * 128;

    const size_t rs = (size_t)K * 2;
    const char* pAhi = (const char*)Ahi + (size_t)m0 * rs;
    const char* pAlo = (const char*)Alo + (size_t)m0 * rs;
    const char* pBhi = (const char*)Bhi + (size_t)n0 * rs;
    const char* pBlo = (const char*)Blo + (size_t)n0 * rs;

    auto load_chunk = [&](int stage, int c) {
        uint32_t base = sb + stage * STAGE_BYTES;
        size_t kb = (size_t)c * 64;
#pragma unroll
        for (int i = 0; i < 2; i++) {
            int f = tid + i * 256;
            int row = f >> 2;
            int seg = (f & 3) * 16;
            uint32_t so = (uint32_t)(row * ROWB + seg);
            const size_t go = (size_t)row * rs + kb + seg;
            cp16(base + OFF_AHI + so, pAhi + go);
            cp16(base + OFF_ALO + so, pAlo + go);
            cp16(base + OFF_BHI + so, pBhi + go);
            cp16(base + OFF_BLO + so, pBlo + go);
        }
        asm volatile("cp.async.commit_group;" ::: "memory");
    };

    float acc[16][4];
#pragma unroll
    for (int t = 0; t < 16; t++)
#pragma unroll
        for (int j = 0; j < 4; j++) acc[t][j] = 0.0f;

    uint32_t a_off = (uint32_t)((wm * 64 + (lane & 15)) * ROWB + (lane >> 4) * 16);
    uint32_t b_off = (uint32_t)((wn * 32 + (lane & 7)) * ROWB + ((lane >> 3) & 1) * 16);

    int nch = K / 32;
    load_chunk(0, 0);

    for (int c = 0; c < nch; c++) {
        int buf = c & 1;
        if (c + 1 < nch) {
            load_chunk(buf ^ 1, c + 1);
            asm volatile("cp.async.wait_group 1;" ::: "memory");
        } else {
            asm volatile("cp.async.wait_group 0;" ::: "memory");
        }
        __syncthreads();

        uint32_t tb = sb + buf * STAGE_BYTES;
#pragma unroll
        for (int ks = 0; ks < 2; ks++) {
            uint32_t ko = (uint32_t)(ks * 32);
            uint32_t bh[4][2], bl[4][2];
#pragma unroll
            for (int nt = 0; nt < 4; nt++) {
                uint32_t bo = b_off + ko + (uint32_t)(nt * 8 * ROWB);
                ldsm_x2(bh[nt][0], bh[nt][1], tb + OFF_BHI + bo);
                ldsm_x2(bl[nt][0], bl[nt][1], tb + OFF_BLO + bo);
            }
#pragma unroll
            for (int mt = 0; mt < 4; mt++) {
                uint32_t ah[4];
                uint32_t ao = a_off + ko + (uint32_t)(mt * 16 * ROWB);
                ldsm_x4(ah[0], ah[1], ah[2], ah[3], tb + OFF_AHI + ao);
#pragma unroll
                for (int nt = 0; nt < 4; nt++) {
                    mma16816(acc[mt * 4 + nt], ah, bh[nt]);
                    mma16816(acc[mt * 4 + nt], ah, bl[nt]);
                }
            }
#pragma unroll
            for (int mt = 0; mt < 4; mt++) {
                uint32_t al[4];
                uint32_t ao = a_off + ko + (uint32_t)(mt * 16 * ROWB);
                ldsm_x4(al[0], al[1], al[2], al[3], tb + OFF_ALO + ao);
#pragma unroll
                for (int nt = 0; nt < 4; nt++)
                    mma16816(acc[mt * 4 + nt], al, bh[nt]);
            }
        }
        __syncthreads();
    }

    int mbase = m0 + wm * 64 + (lane >> 2);
    int nbase = n0 + wn * 32 + (lane & 3) * 2;
#pragma unroll
    for (int mt = 0; mt < 4; mt++) {
#pragma unroll
        for (int nt = 0; nt < 4; nt++) {
            float* d = acc[mt * 4 + nt];
            int r = mbase + mt * 16;
            int cc = nbase + nt * 8;
            *(float2*)(C + (size_t)r * N + cc)       = make_float2(d[0], d[1]);
            *(float2*)(C + (size_t)(r + 8) * N + cc) = make_float2(d[2], d[3]);
        }
    }
}

// ---------------------------------------------------------------------------
// Tensor-core flash attention (causal, GQA).
// CTA: 128 q-rows x one head, 8 warps (16 q-rows each). k-tiles of 64.
// Split math: S = Qh*Kh + Qh*Kl + Ql*Kh ; O += Ph*Vh + Ph*Vl + Pl*Vh.
// 272B-padded smem rows -> conflict-free ldmatrix; V via ldmatrix.trans.
// Writes split bf16 attention output directly.
// ---------------------------------------------------------------------------
#define AROWB 272
#define A_QH 0
#define A_QL (128 * AROWB)                  // 34816
#define A_KH (2 * 128 * AROWB)              // 69632
#define A_KL (A_KH + 64 * AROWB)
#define A_VH (A_KL + 64 * AROWB)
#define A_VL (A_VH + 64 * AROWB)
#define ATTN_SMEM (A_VL + 64 * AROWB)       // 139264

__global__ __launch_bounds__(256, 1) void attn_mma_kernel(
    const __nv_bfloat16* __restrict__ qhi, const __nv_bfloat16* __restrict__ qlo,
    __nv_bfloat16* __restrict__ ohi, __nv_bfloat16* __restrict__ olo)
{
    extern __shared__ char smc[];
    uint32_t sb = smem_u32(smc);
    int tid  = threadIdx.x;
    int w    = tid >> 5;
    int lane = tid & 31;
    int h    = blockIdx.y;
    int bx   = (int)gridDim.x - 1 - (int)blockIdx.x;   // heavy tiles first
    int q0   = bx * 128;
    int kvh  = h >> 2;

    // ---- load Q tile (hi+lo), 4096 cp16 over 256 threads
#pragma unroll
    for (int i = 0; i < 16; i++) {
        int f   = tid + i * 256;
        int arr = f >> 11;          // 0 hi, 1 lo
        int rem = f & 2047;
        int row = rem >> 4;
        int seg = rem & 15;
        const __nv_bfloat16* src =
            (arr ? qlo : qhi) + (size_t)(q0 + row) * QKV_DIM + h * HD + seg * 8;
        cp16(sb + (arr ? A_QL : A_QH) + row * AROWB + seg * 16, src);
    }

    float oacc[16][4];
#pragma unroll
    for (int t = 0; t < 16; t++)
#pragma unroll
        for (int j = 0; j < 4; j++) oacc[t][j] = 0.0f;
    float mrow[2] = {-1e30f, -1e30f};
    float lrow[2] = {0.0f, 0.0f};

    int wmin = q0 + 16 * w;
    int nkt  = 2 * (bx + 1);

    for (int kt = 0; kt < nkt; kt++) {
        int k0 = kt * 64;
        // ---- load K/V tile (hi+lo)
#pragma unroll
        for (int i = 0; i < 16; i++) {
            int f   = tid + i * 256;
            int arr = f >> 10;      // 0 KH, 1 KL, 2 VH, 3 VL
            int rem = f & 1023;
            int row = rem >> 4;
            int seg = rem & 15;
            const __nv_bfloat16* base = (arr & 1) ? qlo : qhi;
            int off = (arr >> 1) ? (HID + NKV * HD) : HID;
            const __nv_bfloat16* src =
                base + (size_t)(k0 + row) * QKV_DIM + off + kvh * HD + seg * 8;
            uint32_t doff = (arr == 0) ? A_KH : (arr == 1) ? A_KL
                          : (arr == 2) ? A_VH : A_VL;
            cp16(sb + doff + row * AROWB + seg * 16, src);
        }
        asm volatile("cp.async.commit_group;\n\tcp.async.wait_group 0;" ::: "memory");
        __syncthreads();

        if (k0 <= wmin + 15) {     // warp has at least one unmasked row
            float sacc[8][4];
#pragma unroll
            for (int t = 0; t < 8; t++)
#pragma unroll
                for (int j = 0; j < 4; j++) sacc[t][j] = 0.0f;

            // ---- S = Q . K^T (3 split passes)
#pragma unroll
            for (int ks = 0; ks < 8; ks++) {
                uint32_t qh_[4], ql_[4];
                uint32_t ao = (uint32_t)((16 * w + (lane & 15)) * AROWB
                                         + ks * 32 + (lane >> 4) * 16);
                ldsm_x4(qh_[0], qh_[1], qh_[2], qh_[3], sb + A_QH + ao);
                ldsm_x4(ql_[0], ql_[1], ql_[2], ql_[3], sb + A_QL + ao);
#pragma unroll
                for (int np = 0; np < 4; np++) {
                    uint32_t kh_[4], kl_[4];
                    uint32_t bo = (uint32_t)((np * 16 + (lane & 7)
                                              + ((lane >> 4) << 3)) * AROWB
                                             + ks * 32 + ((lane >> 3) & 1) * 16);
                    ldsm_x4(kh_[0], kh_[1], kh_[2], kh_[3], sb + A_KH + bo);
                    ldsm_x4(kl_[0], kl_[1], kl_[2], kl_[3], sb + A_KL + bo);
                    mma16816(sacc[2 * np],     qh_, kh_);
                    mma16816(sacc[2 * np],     qh_, kl_);
                    mma16816(sacc[2 * np],     ql_, kh_);
                    mma16816(sacc[2 * np + 1], qh_, kh_ + 2);
                    mma16816(sacc[2 * np + 1], qh_, kl_ + 2);
                    mma16816(sacc[2 * np + 1], ql_, kh_ + 2);
                }
            }

            // ---- causal mask
            int r1 = wmin + (lane >> 2);
            if (k0 + 63 > wmin) {
#pragma unroll
                for (int nt = 0; nt < 8; nt++) {
                    int c0 = k0 + nt * 8 + (lane & 3) * 2;
                    if (c0     > r1)     sacc[nt][0] = -1e30f;
                    if (c0 + 1 > r1)     sacc[nt][1] = -1e30f;
                    if (c0     > r1 + 8) sacc[nt][2] = -1e30f;
                    if (c0 + 1 > r1 + 8) sacc[nt][3] = -1e30f;
                }
            }

            // ---- online softmax (per row-half)
#pragma unroll
            for (int hf = 0; hf < 2; hf++) {
                float mx = -1e30f;
#pragma unroll
                for (int nt = 0; nt < 8; nt++)
                    mx = fmaxf(mx, fmaxf(sacc[nt][2 * hf], sacc[nt][2 * hf + 1]));
                mx = fmaxf(mx, __shfl_xor_sync(0xffffffffu, mx, 1));
                mx = fmaxf(mx, __shfl_xor_sync(0xffffffffu, mx, 2));
                float mn   = fmaxf(mrow[hf], mx);
                float corr = __expf(mrow[hf] - mn);
                mrow[hf] = mn;
                float sum = 0.0f;
#pragma unroll
                for (int nt = 0; nt < 8; nt++) {
                    float p0 = __expf(sacc[nt][2 * hf]     - mn);
                    float p1 = __expf(sacc[nt][2 * hf + 1] - mn);
                    sacc[nt][2 * hf]     = p0;
                    sacc[nt][2 * hf + 1] = p1;
                    sum += p0 + p1;
                }
                sum += __shfl_xor_sync(0xffffffffu, sum, 1);
                sum += __shfl_xor_sync(0xffffffffu, sum, 2);
                lrow[hf] = lrow[hf] * corr + sum;
#pragma unroll
                for (int nt = 0; nt < 16; nt++) {
                    oacc[nt][2 * hf]     *= corr;
                    oacc[nt][2 * hf + 1] *= corr;
                }
            }

            // ---- O += P . V (3 split passes), P from registers
#pragma unroll
            for (int j = 0; j < 4; j++) {
                uint32_t ph_[4], pl_[4];
                ph_[0] = pack_bf16x2(sacc[2 * j][0],     sacc[2 * j][1]);
                ph_[1] = pack_bf16x2(sacc[2 * j][2],     sacc[2 * j][3]);
                ph_[2] = pack_bf16x2(sacc[2 * j + 1][0], sacc[2 * j + 1][1]);
                ph_[3] = pack_bf16x2(sacc[2 * j + 1][2], sacc[2 * j + 1][3]);
                pl_[0] = pack_bf16x2(sacc[2 * j][0]     - bf16lo_f(ph_[0]),
                                     sacc[2 * j][1]     - bf16hi_f(ph_[0]));
                pl_[1] = pack_bf16x2(sacc[2 * j][2]     - bf16lo_f(ph_[1]),
                                     sacc[2 * j][3]     - bf16hi_f(ph_[1]));
                pl_[2] = pack_bf16x2(sacc[2 * j + 1][0] - bf16lo_f(ph_[2]),
                                     sacc[2 * j + 1][1] - bf16hi_f(ph_[2]));
                pl_[3] = pack_bf16x2(sacc[2 * j + 1][2] - bf16lo_f(ph_[3]),
                                     sacc[2 * j + 1][3] - bf16hi_f(ph_[3]));
#pragma unroll
                for (int np = 0; np < 8; np++) {
                    uint32_t vh_[4], vl_[4];
                    uint32_t vo = (uint32_t)((j * 16 + (lane & 7)
                                              + ((lane >> 3) & 1) * 8) * AROWB
                                             + (np * 16 + ((lane >> 4) << 3)) * 2);
                    ldsm_x4t(vh_[0], vh_[1], vh_[2], vh_[3], sb + A_VH + vo);
                    ldsm_x4t(vl_[0], vl_[1], vl_[2], vl_[3], sb + A_VL + vo);
                    mma16816(oacc[2 * np],     ph_, vh_);
                    mma16816(oacc[2 * np],     ph_, vl_);
                    mma16816(oacc[2 * np],     pl_, vh_);
                    mma16816(oacc[2 * np + 1], ph_, vh_ + 2);
                    mma16816(oacc[2 * np + 1], ph_, vl_ + 2);
                    mma16816(oacc[2 * np + 1], pl_, vh_ + 2);
                }
            }
        }
        __syncthreads();
    }

    // ---- epilogue: normalize + split-write bf16 hi/lo
    float inv0 = 1.0f / lrow[0];
    float inv1 = 1.0f / lrow[1];
    int r1 = q0 + 16 * w + (lane >> 2);
    size_t base1 = (size_t)r1 * HID + h * HD + (lane & 3) * 2;
    size_t base2 = base1 + (size_t)8 * HID;
#pragma unroll
    for (int nt = 0; nt < 16; nt++) {
        float v0 = oacc[nt][0] * inv0;
        float v1 = oacc[nt][1] * inv0;
        uint32_t hiw = pack_bf16x2(v0, v1);
        uint32_t low = pack_bf16x2(v0 - bf16lo_f(hiw), v1 - bf16hi_f(hiw));
        *(uint32_t*)(ohi + base1 + nt * 8) = hiw;
        *(uint32_t*)(olo + base1 + nt * 8) = low;
        float v2 = oacc[nt][2] * inv1;
        float v3 = oacc[nt][3] * inv1;
        uint32_t hiw2 = pack_bf16x2(v2, v3);
        uint32_t low2 = pack_bf16x2(v2 - bf16lo_f(hiw2), v3 - bf16hi_f(hiw2));
        *(uint32_t*)(ohi + base2 + nt * 8) = hiw2;
        *(uint32_t*)(olo + base2 + nt * 8) = low2;
    }
}

// ---------------------------------------------------------------------------
// Launch
// ---------------------------------------------------------------------------
extern "C" void kernel_launch(void* const* d_in, const int* in_sizes, int n_in,
                              void* d_out, int out_size)
{
    (void)in_sizes; (void)n_in; (void)out_size;
    const float* x     = (const float*)d_in[0];
    const int*   pos   = (const int*)d_in[1];
    const float* w_qkv = (const float*)d_in[2];
    const float* w_o   = (const float*)d_in[3];
    float*       out   = (float*)d_out;

    void *p_qkv, *p_xh, *p_xl, *p_wqh, *p_wql, *p_woh, *p_wol;
    void *p_sph, *p_spl, *p_ah, *p_al;
    cudaGetSymbolAddress(&p_qkv, g_qkv);
    cudaGetSymbolAddress(&p_xh, g_x_hi);
    cudaGetSymbolAddress(&p_xl, g_x_lo);
    cudaGetSymbolAddress(&p_wqh, g_wqkv_hi);
    cudaGetSymbolAddress(&p_wql, g_wqkv_lo);
    cudaGetSymbolAddress(&p_woh, g_wo_hi);
    cudaGetSymbolAddress(&p_wol, g_wo_lo);
    cudaGetSymbolAddress(&p_sph, g_qkvsp_hi);
    cudaGetSymbolAddress(&p_spl, g_qkvsp_lo);
    cudaGetSymbolAddress(&p_ah, g_attn_hi);
    cudaGetSymbolAddress(&p_al, g_attn_lo);
    float* qkv = (float*)p_qkv;

    cudaFuncSetAttribute(gemm_mma_split_kernel,
                         cudaFuncAttributeMaxDynamicSharedMemorySize, GEMM_SMEM);
    cudaFuncSetAttribute(attn_mma_kernel,
                         cudaFuncAttributeMaxDynamicSharedMemorySize, ATTN_SMEM);

    // RoPE table
    rope_table_kernel<<<(S_LEN * 64 + 255) / 256, 256>>>(pos);

    // Split inputs to bf16 hi/lo
    {
        int n1 = S_LEN * HID;
        convert_split_kernel<<<(n1 + 255) / 256, 256>>>(
            x, (__nv_bfloat16*)p_xh, (__nv_bfloat16*)p_xl, n1);
        int n2 = QKV_DIM * HID;
        convert_split_kernel<<<(n2 + 255) / 256, 256>>>(
            w_qkv, (__nv_bfloat16*)p_wqh, (__nv_bfloat16*)p_wql, n2);
        int n3 = HID * HID;
        convert_split_kernel<<<(n3 + 255) / 256, 256>>>(
            w_o, (__nv_bfloat16*)p_woh, (__nv_bfloat16*)p_wol, n3);
    }

    // QKV projection
    gemm_mma_split_kernel<<<dim3(S_LEN / 128, QKV_DIM / 128), 256, GEMM_SMEM>>>(
        (const __nv_bfloat16*)p_xh, (const __nv_bfloat16*)p_xl,
        (const __nv_bfloat16*)p_wqh, (const __nv_bfloat16*)p_wql,
        qkv, HID, QKV_DIM);

    // RoPE + scale + split qkv -> bf16 hi/lo
    postqkv_kernel<<<(S_LEN * 48 * 64 + 255) / 256, 256>>>(
        qkv, (__nv_bfloat16*)p_sph, (__nv_bfloat16*)p_spl);

    // Tensor-core flash attention (writes split output)
    attn_mma_kernel<<<dim3(S_LEN / 128, NH), 256, ATTN_SMEM>>>(
        (const __nv_bfloat16*)p_sph, (const __nv_bfloat16*)p_spl,
        (__nv_bfloat16*)p_ah, (__nv_bfloat16*)p_al);

    // Output projection
    gemm_mma_split_kernel<<<dim3(S_LEN / 128, HID / 128), 256, GEMM_SMEM>>>(
        (const __nv_bfloat16*)p_ah, (const __nv_bfloat16*)p_al,
        (const __nv_bfloat16*)p_woh, (const __nv_bfloat16*)p_wol,
        out, HID, HID);
}

// round 5
// speedup vs baseline: 2.7914x; 1.0736x over previous
#include <cuda_runtime.h>
#include <cuda_bf16.h>
#include <math.h>
#include <stdint.h>

// Problem constants
#define S_LEN   2048
#define HID     4096
#define NH      32
#define NKV     8
#define HD      128
#define QKV_DIM 6144   // NH*HD + 2*NKV*HD
#define GROUPS  4

// ---------------------------------------------------------------------------
// Device scratch (no allocations allowed)
// ---------------------------------------------------------------------------
__device__ float g_qkv[S_LEN * QKV_DIM];   // [S, 6144] fp32 (QKV GEMM out)
__device__ float g_cos[S_LEN * 64];
__device__ float g_sin[S_LEN * 64];

__device__ __align__(128) __nv_bfloat16 g_x_hi[S_LEN * HID];
__device__ __align__(128) __nv_bfloat16 g_x_lo[S_LEN * HID];
__device__ __align__(128) __nv_bfloat16 g_wqkv_hi[QKV_DIM * HID];
__device__ __align__(128) __nv_bfloat16 g_wqkv_lo[QKV_DIM * HID];
__device__ __align__(128) __nv_bfloat16 g_wo_hi[HID * HID];
__device__ __align__(128) __nv_bfloat16 g_wo_lo[HID * HID];
__device__ __align__(128) __nv_bfloat16 g_qkvsp_hi[S_LEN * QKV_DIM];
__device__ __align__(128) __nv_bfloat16 g_qkvsp_lo[S_LEN * QKV_DIM];
__device__ __align__(128) __nv_bfloat16 g_attn_hi[S_LEN * HID];
__device__ __align__(128) __nv_bfloat16 g_attn_lo[S_LEN * HID];

// ---------------------------------------------------------------------------
// Helpers
// ---------------------------------------------------------------------------
static __device__ __forceinline__ uint32_t smem_u32(const void* p) {
    uint32_t a;
    asm("{ .reg .u64 t; cvta.to.shared.u64 t, %1; cvt.u32.u64 %0, t; }"
        : "=r"(a) : "l"(p));
    return a;
}

static __device__ __forceinline__ void cp16(uint32_t dst, const void* src) {
    asm volatile("cp.async.cg.shared.global [%0], [%1], 16;"
                 :: "r"(dst), "l"(src));
}

static __device__ __forceinline__ void ldsm_x4(uint32_t& r0, uint32_t& r1,
                                               uint32_t& r2, uint32_t& r3,
                                               uint32_t addr) {
    asm volatile("ldmatrix.sync.aligned.m8n8.x4.shared.b16 {%0,%1,%2,%3}, [%4];"
                 : "=r"(r0), "=r"(r1), "=r"(r2), "=r"(r3) : "r"(addr));
}

static __device__ __forceinline__ void ldsm_x4t(uint32_t& r0, uint32_t& r1,
                                                uint32_t& r2, uint32_t& r3,
                                                uint32_t addr) {
    asm volatile("ldmatrix.sync.aligned.m8n8.x4.trans.shared.b16 {%0,%1,%2,%3}, [%4];"
                 : "=r"(r0), "=r"(r1), "=r"(r2), "=r"(r3) : "r"(addr));
}

static __device__ __forceinline__ void mma16816(float* d, const uint32_t* a,
                                                const uint32_t* b) {
    asm volatile(
        "mma.sync.aligned.m16n8k16.row.col.f32.bf16.bf16.f32 "
        "{%0,%1,%2,%3}, {%4,%5,%6,%7}, {%8,%9}, {%0,%1,%2,%3};"
        : "+f"(d[0]), "+f"(d[1]), "+f"(d[2]), "+f"(d[3])
        : "r"(a[0]), "r"(a[1]), "r"(a[2]), "r"(a[3]), "r"(b[0]), "r"(b[1]));
}

static __device__ __forceinline__ uint32_t pack_bf16x2(float lo, float hi) {
    uint32_t d;
    asm("cvt.rn.bf16x2.f32 %0, %1, %2;" : "=r"(d) : "f"(hi), "f"(lo));
    return d;
}
static __device__ __forceinline__ float bf16lo_f(uint32_t u) {
    return __uint_as_float(u << 16);
}
static __device__ __forceinline__ float bf16hi_f(uint32_t u) {
    return __uint_as_float(u & 0xffff0000u);
}

// ---------------------------------------------------------------------------
// fp32 -> bf16 hi/lo split (vectorized: 4 elems/thread)
// ---------------------------------------------------------------------------
__global__ void convert_split_kernel(const float* __restrict__ src,
                                     __nv_bfloat16* __restrict__ hi,
                                     __nv_bfloat16* __restrict__ lo, int n4) {
    int i = blockIdx.x * blockDim.x + threadIdx.x;
    if (i >= n4) return;
    float4 x = *(const float4*)(src + (size_t)i * 4);
    uint32_t h0 = pack_bf16x2(x.x, x.y);
    uint32_t h1 = pack_bf16x2(x.z, x.w);
    uint32_t l0 = pack_bf16x2(x.x - bf16lo_f(h0), x.y - bf16hi_f(h0));
    uint32_t l1 = pack_bf16x2(x.z - bf16lo_f(h1), x.w - bf16hi_f(h1));
    *(uint2*)(hi + (size_t)i * 4) = make_uint2(h0, h1);
    *(uint2*)(lo + (size_t)i * 4) = make_uint2(l0, l1);
}

// ---------------------------------------------------------------------------
// RoPE table (verified)
// ---------------------------------------------------------------------------
__global__ void rope_table_kernel(const int* __restrict__ pos_ids) {
    int idx = blockIdx.x * blockDim.x + threadIdx.x;
    if (idx >= S_LEN * 64) return;
    int s = idx >> 6;
    int d = idx & 63;
    float expo = (float)(2 * d) * (1.0f / 128.0f);
    float invf = exp2f(-expo * 16.609640474436813f);   // log2(100000)
    float a = (float)((double)pos_ids[s] * (double)invf);
    double ar = (double)a;
    double k  = rint(ar * 0.15915494309189535);
    ar -= k * 6.283185307179586;
    float r = (float)ar;
    g_cos[idx] = cosf(r);
    g_sin[idx] = sinf(r);
}

// ---------------------------------------------------------------------------
// Post-QKV: RoPE on q,k (scale folded into q), split all of qkv to bf16 hi/lo
// ---------------------------------------------------------------------------
__global__ void postqkv_kernel(const float* __restrict__ qkv,
                               __nv_bfloat16* __restrict__ hi,
                               __nv_bfloat16* __restrict__ lo) {
    int idx = blockIdx.x * blockDim.x + threadIdx.x;
    if (idx >= S_LEN * 48 * 64) return;
    int d    = idx & 63;
    int rem  = idx >> 6;
    int head = rem % 48;
    int s    = rem / 48;
    size_t base = (size_t)s * QKV_DIM + head * 128;
    const float* b = qkv + base;
    float x1 = b[d];
    float x2 = b[d + 64];
    if (head < 40) {
        float c  = g_cos[(s << 6) + d];
        float sn = g_sin[(s << 6) + d];
        float y1 = x1 * c - x2 * sn;
        float y2 = x2 * c + x1 * sn;
        if (head < 32) {
            y1 *= 0.08838834764831845f;   // 1/sqrt(128)
            y2 *= 0.08838834764831845f;
        }
        x1 = y1; x2 = y2;
    }
    __nv_bfloat16 h1 = __float2bfloat16_rn(x1);
    __nv_bfloat16 h2 = __float2bfloat16_rn(x2);
    hi[base + d]      = h1;
    lo[base + d]      = __float2bfloat16_rn(x1 - __bfloat162float(h1));
    hi[base + d + 64] = h2;
    lo[base + d + 64] = __float2bfloat16_rn(x2 - __bfloat162float(h2));
}

// ---------------------------------------------------------------------------
// bf16-split GEMM via mma.sync (NT): C[m,n] = sum_k A[m,k]*B[n,k]
// CTA 256x128, BK=32, 256 threads (4x2 warps, warp tile 64x64).
// 3-stage cp.async pipeline.  C = Ah*Bh + Ah*Bl + Al*Bh, fp32 accum.
// ---------------------------------------------------------------------------
#define ROWB 80                         // 64B data + 16B pad
#define G_AHI 0
#define G_ALO (256 * ROWB)              // 20480
#define G_BHI (2 * 256 * ROWB)          // 40960
#define G_BLO (G_BHI + 128 * ROWB)      // 51200
#define G_STAGE (G_BLO + 128 * ROWB)    // 61440
#define GEMM_SMEM (3 * G_STAGE)         // 184320

__global__ __launch_bounds__(256, 1) void gemm_mma_split_kernel(
    const __nv_bfloat16* __restrict__ Ahi, const __nv_bfloat16* __restrict__ Alo,
    const __nv_bfloat16* __restrict__ Bhi, const __nv_bfloat16* __restrict__ Blo,
    float* __restrict__ C, int K, int N)
{
    extern __shared__ char smc[];
    uint32_t sb = smem_u32(smc);
    int tid  = threadIdx.x;
    int wid  = tid >> 5;
    int lane = tid & 31;
    int wm = wid >> 1;     // 0..3
    int wn = wid & 1;      // 0..1
    int m0 = blockIdx.x * 256;
    int n0 = blockIdx.y * 128;

    const size_t rs = (size_t)K * 2;
    const char* pAhi = (const char*)Ahi + (size_t)m0 * rs;
    const char* pAlo = (const char*)Alo + (size_t)m0 * rs;
    const char* pBhi = (const char*)Bhi + (size_t)n0 * rs;
    const char* pBlo = (const char*)Blo + (size_t)n0 * rs;

    auto load_chunk = [&](int stage, int c) {
        uint32_t base = sb + stage * G_STAGE;
        size_t kb = (size_t)c * 64;
        // A: 2048 chunks (hi 0..1023, lo 1024..2047)
#pragma unroll
        for (int i = 0; i < 8; i++) {
            int f   = tid + i * 256;
            int arr = f >> 10;
            int rem = f & 1023;
            int row = rem >> 2;
            int seg = (rem & 3) * 16;
            uint32_t so = (uint32_t)(row * ROWB + seg) + (arr ? G_ALO : G_AHI);
            const char* p = (arr ? pAlo : pAhi) + (size_t)row * rs + kb + seg;
            cp16(base + so, p);
        }
        // B: 1024 chunks (hi 0..511, lo 512..1023)
#pragma unroll
        for (int i = 0; i < 4; i++) {
            int f   = tid + i * 256;
            int arr = f >> 9;
            int rem = f & 511;
            int row = rem >> 2;
            int seg = (rem & 3) * 16;
            uint32_t so = (uint32_t)(row * ROWB + seg) + (arr ? G_BLO : G_BHI);
            const char* p = (arr ? pBlo : pBhi) + (size_t)row * rs + kb + seg;
            cp16(base + so, p);
        }
        asm volatile("cp.async.commit_group;" ::: "memory");
    };

    float acc[32][4];
#pragma unroll
    for (int t = 0; t < 32; t++)
#pragma unroll
        for (int j = 0; j < 4; j++) acc[t][j] = 0.0f;

    uint32_t a_off = (uint32_t)((wm * 64 + (lane & 15)) * ROWB + (lane >> 4) * 16);
    uint32_t b_base = (uint32_t)((wn * 64 + (lane & 7) + ((lane >> 4) << 3)) * ROWB
                                 + ((lane >> 3) & 1) * 16);

    int nch = K / 32;
    load_chunk(0, 0);
    load_chunk(1, 1);

    for (int c = 0; c < nch; c++) {
        if (c < nch - 1) {
            asm volatile("cp.async.wait_group 1;" ::: "memory");
        } else {
            asm volatile("cp.async.wait_group 0;" ::: "memory");
        }
        __syncthreads();
        if (c + 2 < nch) load_chunk((c + 2) % 3, c + 2);

        uint32_t tb = sb + (c % 3) * G_STAGE;
#pragma unroll
        for (int ks = 0; ks < 2; ks++) {
            uint32_t ko = (uint32_t)(ks * 32);
            uint32_t bh[4][4], bl[4][4];
#pragma unroll
            for (int np = 0; np < 4; np++) {
                uint32_t bo = b_base + ko + (uint32_t)(np * 16 * ROWB);
                ldsm_x4(bh[np][0], bh[np][1], bh[np][2], bh[np][3], tb + G_BHI + bo);
                ldsm_x4(bl[np][0], bl[np][1], bl[np][2], bl[np][3], tb + G_BLO + bo);
            }
#pragma unroll
            for (int mt = 0; mt < 4; mt++) {
                uint32_t ah[4];
                uint32_t ao = a_off + ko + (uint32_t)(mt * 16 * ROWB);
                ldsm_x4(ah[0], ah[1], ah[2], ah[3], tb + G_AHI + ao);
#pragma unroll
                for (int np = 0; np < 4; np++) {
                    mma16816(acc[mt * 8 + 2 * np],     ah, bh[np]);
                    mma16816(acc[mt * 8 + 2 * np],     ah, bl[np]);
                    mma16816(acc[mt * 8 + 2 * np + 1], ah, bh[np] + 2);
                    mma16816(acc[mt * 8 + 2 * np + 1], ah, bl[np] + 2);
                }
            }
#pragma unroll
            for (int mt = 0; mt < 4; mt++) {
                uint32_t al[4];
                uint32_t ao = a_off + ko + (uint32_t)(mt * 16 * ROWB);
                ldsm_x4(al[0], al[1], al[2], al[3], tb + G_ALO + ao);
#pragma unroll
                for (int np = 0; np < 4; np++) {
                    mma16816(acc[mt * 8 + 2 * np],     al, bh[np]);
                    mma16816(acc[mt * 8 + 2 * np + 1], al, bh[np] + 2);
                }
            }
        }
    }

    // Epilogue
    int mbase = m0 + wm * 64 + (lane >> 2);
    int nbase = n0 + wn * 64 + (lane & 3) * 2;
#pragma unroll
    for (int mt = 0; mt < 4; mt++) {
#pragma unroll
        for (int nt = 0; nt < 8; nt++) {
            float* d = acc[mt * 8 + nt];
            int r = mbase + mt * 16;
            int cc = nbase + nt * 8;
            *(float2*)(C + (size_t)r * N + cc)       = make_float2(d[0], d[1]);
            *(float2*)(C + (size_t)(r + 8) * N + cc) = make_float2(d[2], d[3]);
        }
    }
}

// ---------------------------------------------------------------------------
// Tensor-core flash attention (causal, GQA) — unchanged from round 4 (verified)
// ---------------------------------------------------------------------------
#define AROWB 272
#define A_QH 0
#define A_QL (128 * AROWB)
#define A_KH (2 * 128 * AROWB)
#define A_KL (A_KH + 64 * AROWB)
#define A_VH (A_KL + 64 * AROWB)
#define A_VL (A_VH + 64 * AROWB)
#define ATTN_SMEM (A_VL + 64 * AROWB)

__global__ __launch_bounds__(256, 1) void attn_mma_kernel(
    const __nv_bfloat16* __restrict__ qhi, const __nv_bfloat16* __restrict__ qlo,
    __nv_bfloat16* __restrict__ ohi, __nv_bfloat16* __restrict__ olo)
{
    extern __shared__ char smc[];
    uint32_t sb = smem_u32(smc);
    int tid  = threadIdx.x;
    int w    = tid >> 5;
    int lane = tid & 31;
    int h    = blockIdx.y;
    int bx   = (int)gridDim.x - 1 - (int)blockIdx.x;
    int q0   = bx * 128;
    int kvh  = h >> 2;

#pragma unroll
    for (int i = 0; i < 16; i++) {
        int f   = tid + i * 256;
        int arr = f >> 11;
        int rem = f & 2047;
        int row = rem >> 4;
        int seg = rem & 15;
        const __nv_bfloat16* src =
            (arr ? qlo : qhi) + (size_t)(q0 + row) * QKV_DIM + h * HD + seg * 8;
        cp16(sb + (arr ? A_QL : A_QH) + row * AROWB + seg * 16, src);
    }

    float oacc[16][4];
#pragma unroll
    for (int t = 0; t < 16; t++)
#pragma unroll
        for (int j = 0; j < 4; j++) oacc[t][j] = 0.0f;
    float mrow[2] = {-1e30f, -1e30f};
    float lrow[2] = {0.0f, 0.0f};

    int wmin = q0 + 16 * w;
    int nkt  = 2 * (bx + 1);

    for (int kt = 0; kt < nkt; kt++) {
        int k0 = kt * 64;
#pragma unroll
        for (int i = 0; i < 16; i++) {
            int f   = tid + i * 256;
            int arr = f >> 10;
            int rem = f & 1023;
            int row = rem >> 4;
            int seg = rem & 15;
            const __nv_bfloat16* base = (arr & 1) ? qlo : qhi;
            int off = (arr >> 1) ? (HID + NKV * HD) : HID;
            const __nv_bfloat16* src =
                base + (size_t)(k0 + row) * QKV_DIM + off + kvh * HD + seg * 8;
            uint32_t doff = (arr == 0) ? A_KH : (arr == 1) ? A_KL
                          : (arr == 2) ? A_VH : A_VL;
            cp16(sb + doff + row * AROWB + seg * 16, src);
        }
        asm volatile("cp.async.commit_group;\n\tcp.async.wait_group 0;" ::: "memory");
        __syncthreads();

        if (k0 <= wmin + 15) {
            float sacc[8][4];
#pragma unroll
            for (int t = 0; t < 8; t++)
#pragma unroll
                for (int j = 0; j < 4; j++) sacc[t][j] = 0.0f;

#pragma unroll
            for (int ks = 0; ks < 8; ks++) {
                uint32_t qh_[4], ql_[4];
                uint32_t ao = (uint32_t)((16 * w + (lane & 15)) * AROWB
                                         + ks * 32 + (lane >> 4) * 16);
                ldsm_x4(qh_[0], qh_[1], qh_[2], qh_[3], sb + A_QH + ao);
                ldsm_x4(ql_[0], ql_[1], ql_[2], ql_[3], sb + A_QL + ao);
#pragma unroll
                for (int np = 0; np < 4; np++) {
                    uint32_t kh_[4], kl_[4];
                    uint32_t bo = (uint32_t)((np * 16 + (lane & 7)
                                              + ((lane >> 4) << 3)) * AROWB
                                             + ks * 32 + ((lane >> 3) & 1) * 16);
                    ldsm_x4(kh_[0], kh_[1], kh_[2], kh_[3], sb + A_KH + bo);
                    ldsm_x4(kl_[0], kl_[1], kl_[2], kl_[3], sb + A_KL + bo);
                    mma16816(sacc[2 * np],     qh_, kh_);
                    mma16816(sacc[2 * np],     qh_, kl_);
                    mma16816(sacc[2 * np],     ql_, kh_);
                    mma16816(sacc[2 * np + 1], qh_, kh_ + 2);
                    mma16816(sacc[2 * np + 1], qh_, kl_ + 2);
                    mma16816(sacc[2 * np + 1], ql_, kh_ + 2);
                }
            }

            int r1 = wmin + (lane >> 2);
            if (k0 + 63 > wmin) {
#pragma unroll
                for (int nt = 0; nt < 8; nt++) {
                    int c0 = k0 + nt * 8 + (lane & 3) * 2;
                    if (c0     > r1)     sacc[nt][0] = -1e30f;
                    if (c0 + 1 > r1)     sacc[nt][1] = -1e30f;
                    if (c0     > r1 + 8) sacc[nt][2] = -1e30f;
                    if (c0 + 1 > r1 + 8) sacc[nt][3] = -1e30f;
                }
            }

#pragma unroll
            for (int hf = 0; hf < 2; hf++) {
                float mx = -1e30f;
#pragma unroll
                for (int nt = 0; nt < 8; nt++)
                    mx = fmaxf(mx, fmaxf(sacc[nt][2 * hf], sacc[nt][2 * hf + 1]));
                mx = fmaxf(mx, __shfl_xor_sync(0xffffffffu, mx, 1));
                mx = fmaxf(mx, __shfl_xor_sync(0xffffffffu, mx, 2));
                float mn   = fmaxf(mrow[hf], mx);
                float corr = __expf(mrow[hf] - mn);
                mrow[hf] = mn;
                float sum = 0.0f;
#pragma unroll
                for (int nt = 0; nt < 8; nt++) {
                    float p0 = __expf(sacc[nt][2 * hf]     - mn);
                    float p1 = __expf(sacc[nt][2 * hf + 1] - mn);
                    sacc[nt][2 * hf]     = p0;
                    sacc[nt][2 * hf + 1] = p1;
                    sum += p0 + p1;
                }
                sum += __shfl_xor_sync(0xffffffffu, sum, 1);
                sum += __shfl_xor_sync(0xffffffffu, sum, 2);
                lrow[hf] = lrow[hf] * corr + sum;
#pragma unroll
                for (int nt = 0; nt < 16; nt++) {
                    oacc[nt][2 * hf]     *= corr;
                    oacc[nt][2 * hf + 1] *= corr;
                }
            }

#pragma unroll
            for (int j = 0; j < 4; j++) {
                uint32_t ph_[4], pl_[4];
                ph_[0] = pack_bf16x2(sacc[2 * j][0],     sacc[2 * j][1]);
                ph_[1] = pack_bf16x2(sacc[2 * j][2],     sacc[2 * j][3]);
                ph_[2] = pack_bf16x2(sacc[2 * j + 1][0], sacc[2 * j + 1][1]);
                ph_[3] = pack_bf16x2(sacc[2 * j + 1][2], sacc[2 * j + 1][3]);
                pl_[0] = pack_bf16x2(sacc[2 * j][0]     - bf16lo_f(ph_[0]),
                                     sacc[2 * j][1]     - bf16hi_f(ph_[0]));
                pl_[1] = pack_bf16x2(sacc[2 * j][2]     - bf16lo_f(ph_[1]),
                                     sacc[2 * j][3]     - bf16hi_f(ph_[1]));
                pl_[2] = pack_bf16x2(sacc[2 * j + 1][0] - bf16lo_f(ph_[2]),
                                     sacc[2 * j + 1][1] - bf16hi_f(ph_[2]));
                pl_[3] = pack_bf16x2(sacc[2 * j + 1][2] - bf16lo_f(ph_[3]),
                                     sacc[2 * j + 1][3] - bf16hi_f(ph_[3]));
#pragma unroll
                for (int np = 0; np < 8; np++) {
                    uint32_t vh_[4], vl_[4];
                    uint32_t vo = (uint32_t)((j * 16 + (lane & 7)
                                              + ((lane >> 3) & 1) * 8) * AROWB
                                             + (np * 16 + ((lane >> 4) << 3)) * 2);
                    ldsm_x4t(vh_[0], vh_[1], vh_[2], vh_[3], sb + A_VH + vo);
                    ldsm_x4t(vl_[0], vl_[1], vl_[2], vl_[3], sb + A_VL + vo);
                    mma16816(oacc[2 * np],     ph_, vh_);
                    mma16816(oacc[2 * np],     ph_, vl_);
                    mma16816(oacc[2 * np],     pl_, vh_);
                    mma16816(oacc[2 * np + 1], ph_, vh_ + 2);
                    mma16816(oacc[2 * np + 1], ph_, vl_ + 2);
                    mma16816(oacc[2 * np + 1], pl_, vh_ + 2);
                }
            }
        }
        __syncthreads();
    }

    float inv0 = 1.0f / lrow[0];
    float inv1 = 1.0f / lrow[1];
    int r1 = q0 + 16 * w + (lane >> 2);
    size_t base1 = (size_t)r1 * HID + h * HD + (lane & 3) * 2;
    size_t base2 = base1 + (size_t)8 * HID;
#pragma unroll
    for (int nt = 0; nt < 16; nt++) {
        float v0 = oacc[nt][0] * inv0;
        float v1 = oacc[nt][1] * inv0;
        uint32_t hiw = pack_bf16x2(v0, v1);
        uint32_t low = pack_bf16x2(v0 - bf16lo_f(hiw), v1 - bf16hi_f(hiw));
        *(uint32_t*)(ohi + base1 + nt * 8) = hiw;
        *(uint32_t*)(olo + base1 + nt * 8) = low;
        float v2 = oacc[nt][2] * inv1;
        float v3 = oacc[nt][3] * inv1;
        uint32_t hiw2 = pack_bf16x2(v2, v3);
        uint32_t low2 = pack_bf16x2(v2 - bf16lo_f(hiw2), v3 - bf16hi_f(hiw2));
        *(uint32_t*)(ohi + base2 + nt * 8) = hiw2;
        *(uint32_t*)(olo + base2 + nt * 8) = low2;
    }
}

// ---------------------------------------------------------------------------
// Launch
// ---------------------------------------------------------------------------
extern "C" void kernel_launch(void* const* d_in, const int* in_sizes, int n_in,
                              void* d_out, int out_size)
{
    (void)in_sizes; (void)n_in; (void)out_size;
    const float* x     = (const float*)d_in[0];
    const int*   pos   = (const int*)d_in[1];
    const float* w_qkv = (const float*)d_in[2];
    const float* w_o   = (const float*)d_in[3];
    float*       out   = (float*)d_out;

    void *p_qkv, *p_xh, *p_xl, *p_wqh, *p_wql, *p_woh, *p_wol;
    void *p_sph, *p_spl, *p_ah, *p_al;
    cudaGetSymbolAddress(&p_qkv, g_qkv);
    cudaGetSymbolAddress(&p_xh, g_x_hi);
    cudaGetSymbolAddress(&p_xl, g_x_lo);
    cudaGetSymbolAddress(&p_wqh, g_wqkv_hi);
    cudaGetSymbolAddress(&p_wql, g_wqkv_lo);
    cudaGetSymbolAddress(&p_woh, g_wo_hi);
    cudaGetSymbolAddress(&p_wol, g_wo_lo);
    cudaGetSymbolAddress(&p_sph, g_qkvsp_hi);
    cudaGetSymbolAddress(&p_spl, g_qkvsp_lo);
    cudaGetSymbolAddress(&p_ah, g_attn_hi);
    cudaGetSymbolAddress(&p_al, g_attn_lo);
    float* qkv = (float*)p_qkv;

    cudaFuncSetAttribute(gemm_mma_split_kernel,
                         cudaFuncAttributeMaxDynamicSharedMemorySize, GEMM_SMEM);
    cudaFuncSetAttribute(attn_mma_kernel,
                         cudaFuncAttributeMaxDynamicSharedMemorySize, ATTN_SMEM);

    // RoPE table
    rope_table_kernel<<<(S_LEN * 64 + 255) / 256, 256>>>(pos);

    // Split inputs to bf16 hi/lo
    {
        int n1 = S_LEN * HID / 4;
        convert_split_kernel<<<(n1 + 255) / 256, 256>>>(
            x, (__nv_bfloat16*)p_xh, (__nv_bfloat16*)p_xl, n1);
        int n2 = QKV_DIM * HID / 4;
        convert_split_kernel<<<(n2 + 255) / 256, 256>>>(
            w_qkv, (__nv_bfloat16*)p_wqh, (__nv_bfloat16*)p_wql, n2);
        int n3 = HID * HID / 4;
        convert_split_kernel<<<(n3 + 255) / 256, 256>>>(
            w_o, (__nv_bfloat16*)p_woh, (__nv_bfloat16*)p_wol, n3);
    }

    // QKV projection
    gemm_mma_split_kernel<<<dim3(S_LEN / 256, QKV_DIM / 128), 256, GEMM_SMEM>>>(
        (const __nv_bfloat16*)p_xh, (const __nv_bfloat16*)p_xl,
        (const __nv_bfloat16*)p_wqh, (const __nv_bfloat16*)p_wql,
        qkv, HID, QKV_DIM);

    // RoPE + scale + split qkv
    postqkv_kernel<<<(S_LEN * 48 * 64 + 255) / 256, 256>>>(
        qkv, (__nv_bfloat16*)p_sph, (__nv_bfloat16*)p_spl);

    // Tensor-core flash attention
    attn_mma_kernel<<<dim3(S_LEN / 128, NH), 256, ATTN_SMEM>>>(
        (const __nv_bfloat16*)p_sph, (const __nv_bfloat16*)p_spl,
        (__nv_bfloat16*)p_ah, (__nv_bfloat16*)p_al);

    // Output projection
    gemm_mma_split_kernel<<<dim3(S_LEN / 256, HID / 128), 256, GEMM_SMEM>>>(
        (const __nv_bfloat16*)p_ah, (const __nv_bfloat16*)p_al,
        (const __nv_bfloat16*)p_woh, (const __nv_bfloat16*)p_wol,
        out, HID, HID);
}

// round 6
// speedup vs baseline: 3.7651x; 1.3488x over previous
#include <cuda_runtime.h>
#include <cuda_fp16.h>
#include <math.h>
#include <stdint.h>

// Problem constants
#define S_LEN   2048
#define HID     4096
#define NH      32
#define NKV     8
#define HD      128
#define QKV_DIM 6144   // NH*HD + 2*NKV*HD
#define GROUPS  4
#define SCALE   0.08838834764831845f   // 1/sqrt(128)

// ---------------------------------------------------------------------------
// Device scratch (no allocations allowed)
// ---------------------------------------------------------------------------
__device__ float g_qkv[S_LEN * QKV_DIM];   // fp32 QKV GEMM out
__device__ float g_cos[S_LEN * 64];
__device__ float g_sin[S_LEN * 64];

__device__ __align__(128) __half g_x_hi[S_LEN * HID];
__device__ __align__(128) __half g_x_lo[S_LEN * HID];
__device__ __align__(128) __half g_wqkv[QKV_DIM * HID];
__device__ __align__(128) __half g_wo[HID * HID];
__device__ __align__(128) __half g_qkvsp_hi[S_LEN * QKV_DIM];
__device__ __align__(128) __half g_qkvsp_lo[S_LEN * QKV_DIM];   // lo used for Q heads only
__device__ __align__(128) __half g_attn_hi[S_LEN * HID];
__device__ __align__(128) __half g_attn_lo[S_LEN * HID];

// ---------------------------------------------------------------------------
// Helpers
// ---------------------------------------------------------------------------
static __device__ __forceinline__ uint32_t smem_u32(const void* p) {
    uint32_t a;
    asm("{ .reg .u64 t; cvta.to.shared.u64 t, %1; cvt.u32.u64 %0, t; }"
        : "=r"(a) : "l"(p));
    return a;
}

static __device__ __forceinline__ void cp16(uint32_t dst, const void* src) {
    asm volatile("cp.async.cg.shared.global [%0], [%1], 16;"
                 :: "r"(dst), "l"(src));
}

static __device__ __forceinline__ void ldsm_x4(uint32_t& r0, uint32_t& r1,
                                               uint32_t& r2, uint32_t& r3,
                                               uint32_t addr) {
    asm volatile("ldmatrix.sync.aligned.m8n8.x4.shared.b16 {%0,%1,%2,%3}, [%4];"
                 : "=r"(r0), "=r"(r1), "=r"(r2), "=r"(r3) : "r"(addr));
}

static __device__ __forceinline__ void ldsm_x4t(uint32_t& r0, uint32_t& r1,
                                                uint32_t& r2, uint32_t& r3,
                                                uint32_t addr) {
    asm volatile("ldmatrix.sync.aligned.m8n8.x4.trans.shared.b16 {%0,%1,%2,%3}, [%4];"
                 : "=r"(r0), "=r"(r1), "=r"(r2), "=r"(r3) : "r"(addr));
}

static __device__ __forceinline__ void mma16816(float* d, const uint32_t* a,
                                                const uint32_t* b) {
    asm volatile(
        "mma.sync.aligned.m16n8k16.row.col.f32.f16.f16.f32 "
        "{%0,%1,%2,%3}, {%4,%5,%6,%7}, {%8,%9}, {%0,%1,%2,%3};"
        : "+f"(d[0]), "+f"(d[1]), "+f"(d[2]), "+f"(d[3])
        : "r"(a[0]), "r"(a[1]), "r"(a[2]), "r"(a[3]), "r"(b[0]), "r"(b[1]));
}

// pack two fp32 into f16x2: low half <- lo, high half <- hi
static __device__ __forceinline__ uint32_t pack_f16x2(float lo, float hi) {
    uint32_t d;
    asm("cvt.rn.f16x2.f32 %0, %1, %2;" : "=r"(d) : "f"(hi), "f"(lo));
    return d;
}
static __device__ __forceinline__ float f16lo_f(uint32_t u) {
    return __half2float(__ushort_as_half((unsigned short)(u & 0xffffu)));
}
static __device__ __forceinline__ float f16hi_f(uint32_t u) {
    return __half2float(__ushort_as_half((unsigned short)(u >> 16)));
}

// ---------------------------------------------------------------------------
// fp32 -> fp16 hi/lo split (4 elems/thread)
// ---------------------------------------------------------------------------
__global__ void convert_split_kernel(const float* __restrict__ src,
                                     __half* __restrict__ hi,
                                     __half* __restrict__ lo, int n4) {
    int i = blockIdx.x * blockDim.x + threadIdx.x;
    if (i >= n4) return;
    float4 x = *(const float4*)(src + (size_t)i * 4);
    uint32_t h0 = pack_f16x2(x.x, x.y);
    uint32_t h1 = pack_f16x2(x.z, x.w);
    uint32_t l0 = pack_f16x2(x.x - f16lo_f(h0), x.y - f16hi_f(h0));
    uint32_t l1 = pack_f16x2(x.z - f16lo_f(h1), x.w - f16hi_f(h1));
    *(uint2*)(hi + (size_t)i * 4) = make_uint2(h0, h1);
    *(uint2*)(lo + (size_t)i * 4) = make_uint2(l0, l1);
}

// fp32 -> single fp16 (4 elems/thread)
__global__ void convert_half_kernel(const float* __restrict__ src,
                                    __half* __restrict__ dst, int n4) {
    int i = blockIdx.x * blockDim.x + threadIdx.x;
    if (i >= n4) return;
    float4 x = *(const float4*)(src + (size_t)i * 4);
    *(uint2*)(dst + (size_t)i * 4) =
        make_uint2(pack_f16x2(x.x, x.y), pack_f16x2(x.z, x.w));
}

// ---------------------------------------------------------------------------
// RoPE table (verified)
// ---------------------------------------------------------------------------
__global__ void rope_table_kernel(const int* __restrict__ pos_ids) {
    int idx = blockIdx.x * blockDim.x + threadIdx.x;
    if (idx >= S_LEN * 64) return;
    int s = idx >> 6;
    int d = idx & 63;
    float expo = (float)(2 * d) * (1.0f / 128.0f);
    float invf = exp2f(-expo * 16.609640474436813f);   // log2(100000)
    float a = (float)((double)pos_ids[s] * (double)invf);
    double ar = (double)a;
    double k  = rint(ar * 0.15915494309189535);
    ar -= k * 6.283185307179586;
    float r = (float)ar;
    g_cos[idx] = cosf(r);
    g_sin[idx] = sinf(r);
}

// ---------------------------------------------------------------------------
// Post-QKV: RoPE on q,k (NO scale folding), fp16 hi for all, lo for Q heads
// ---------------------------------------------------------------------------
__global__ void postqkv_kernel(const float* __restrict__ qkv,
                               __half* __restrict__ hi,
                               __half* __restrict__ lo) {
    int idx = blockIdx.x * blockDim.x + threadIdx.x;
    if (idx >= S_LEN * 48 * 64) return;
    int d    = idx & 63;
    int rem  = idx >> 6;
    int head = rem % 48;
    int s    = rem / 48;
    size_t base = (size_t)s * QKV_DIM + head * 128;
    const float* b = qkv + base;
    float x1 = b[d];
    float x2 = b[d + 64];
    if (head < 40) {
        float c  = g_cos[(s << 6) + d];
        float sn = g_sin[(s << 6) + d];
        float y1 = x1 * c - x2 * sn;
        float y2 = x2 * c + x1 * sn;
        x1 = y1; x2 = y2;
    }
    __half h1 = __float2half_rn(x1);
    __half h2 = __float2half_rn(x2);
    hi[base + d]      = h1;
    hi[base + d + 64] = h2;
    if (head < 32) {
        lo[base + d]      = __float2half_rn(x1 - __half2float(h1));
        lo[base + d + 64] = __float2half_rn(x2 - __half2float(h2));
    }
}

// ---------------------------------------------------------------------------
// fp16-split GEMM via mma.sync (NT): C = (Ah + Al) . B^T, 2 passes.
// CTA 256x128, BK=32, 256 threads (4x2 warps, warp tile 64x64), 3-stage pipe.
// ---------------------------------------------------------------------------
#define ROWB 80                         // 64B data + 16B pad
#define G_AHI 0
#define G_ALO (256 * ROWB)              // 20480
#define G_B   (2 * 256 * ROWB)          // 40960
#define G_STAGE (G_B + 128 * ROWB)      // 51200
#define GEMM_SMEM (3 * G_STAGE)         // 153600

__global__ __launch_bounds__(256, 1) void gemm_mma_split_kernel(
    const __half* __restrict__ Ahi, const __half* __restrict__ Alo,
    const __half* __restrict__ B,
    float* __restrict__ C, int K, int N)
{
    extern __shared__ char smc[];
    uint32_t sb = smem_u32(smc);
    int tid  = threadIdx.x;
    int wid  = tid >> 5;
    int lane = tid & 31;
    int wm = wid >> 1;     // 0..3
    int wn = wid & 1;      // 0..1
    int m0 = blockIdx.x * 256;
    int n0 = blockIdx.y * 128;

    const size_t rs = (size_t)K * 2;
    const char* pAhi = (const char*)Ahi + (size_t)m0 * rs;
    const char* pAlo = (const char*)Alo + (size_t)m0 * rs;
    const char* pB   = (const char*)B   + (size_t)n0 * rs;

    auto load_chunk = [&](int stage, int c) {
        uint32_t base = sb + stage * G_STAGE;
        size_t kb = (size_t)c * 64;
        // A: 2048 chunks (hi 0..1023, lo 1024..2047)
#pragma unroll
        for (int i = 0; i < 8; i++) {
            int f   = tid + i * 256;
            int arr = f >> 10;
            int rem = f & 1023;
            int row = rem >> 2;
            int seg = (rem & 3) * 16;
            uint32_t so = (uint32_t)(row * ROWB + seg) + (arr ? G_ALO : G_AHI);
            const char* p = (arr ? pAlo : pAhi) + (size_t)row * rs + kb + seg;
            cp16(base + so, p);
        }
        // B: 512 chunks
#pragma unroll
        for (int i = 0; i < 2; i++) {
            int f   = tid + i * 256;
            int row = f >> 2;
            int seg = (f & 3) * 16;
            cp16(base + G_B + (uint32_t)(row * ROWB + seg),
                 pB + (size_t)row * rs + kb + seg);
        }
        asm volatile("cp.async.commit_group;" ::: "memory");
    };

    float acc[32][4];
#pragma unroll
    for (int t = 0; t < 32; t++)
#pragma unroll
        for (int j = 0; j < 4; j++) acc[t][j] = 0.0f;

    uint32_t a_off  = (uint32_t)((wm * 64 + (lane & 15)) * ROWB + (lane >> 4) * 16);
    uint32_t b_base = (uint32_t)((wn * 64 + (lane & 7) + ((lane >> 4) << 3)) * ROWB
                                 + ((lane >> 3) & 1) * 16);

    int nch = K / 32;
    load_chunk(0, 0);
    load_chunk(1, 1);

    for (int c = 0; c < nch; c++) {
        if (c < nch - 1) {
            asm volatile("cp.async.wait_group 1;" ::: "memory");
        } else {
            asm volatile("cp.async.wait_group 0;" ::: "memory");
        }
        __syncthreads();
        if (c + 2 < nch) load_chunk((c + 2) % 3, c + 2);

        uint32_t tb = sb + (c % 3) * G_STAGE;
#pragma unroll
        for (int ks = 0; ks < 2; ks++) {
            uint32_t ko = (uint32_t)(ks * 32);
            uint32_t bh[4][4];
#pragma unroll
            for (int np = 0; np < 4; np++) {
                uint32_t bo = b_base + ko + (uint32_t)(np * 16 * ROWB);
                ldsm_x4(bh[np][0], bh[np][1], bh[np][2], bh[np][3], tb + G_B + bo);
            }
#pragma unroll
            for (int mt = 0; mt < 4; mt++) {
                uint32_t ah[4];
                uint32_t ao = a_off + ko + (uint32_t)(mt * 16 * ROWB);
                ldsm_x4(ah[0], ah[1], ah[2], ah[3], tb + G_AHI + ao);
#pragma unroll
                for (int np = 0; np < 4; np++) {
                    mma16816(acc[mt * 8 + 2 * np],     ah, bh[np]);
                    mma16816(acc[mt * 8 + 2 * np + 1], ah, bh[np] + 2);
                }
            }
#pragma unroll
            for (int mt = 0; mt < 4; mt++) {
                uint32_t al[4];
                uint32_t ao = a_off + ko + (uint32_t)(mt * 16 * ROWB);
                ldsm_x4(al[0], al[1], al[2], al[3], tb + G_ALO + ao);
#pragma unroll
                for (int np = 0; np < 4; np++) {
                    mma16816(acc[mt * 8 + 2 * np],     al, bh[np]);
                    mma16816(acc[mt * 8 + 2 * np + 1], al, bh[np] + 2);
                }
            }
        }
    }

    // Epilogue
    int mbase = m0 + wm * 64 + (lane >> 2);
    int nbase = n0 + wn * 64 + (lane & 3) * 2;
#pragma unroll
    for (int mt = 0; mt < 4; mt++) {
#pragma unroll
        for (int nt = 0; nt < 8; nt++) {
            float* d = acc[mt * 8 + nt];
            int r = mbase + mt * 16;
            int cc = nbase + nt * 8;
            *(float2*)(C + (size_t)r * N + cc)       = make_float2(d[0], d[1]);
            *(float2*)(C + (size_t)(r + 8) * N + cc) = make_float2(d[2], d[3]);
        }
    }
}

// ---------------------------------------------------------------------------
// Tensor-core flash attention (causal, GQA), fp16 2-pass split.
// S = (Qh + Ql).K^T (K single fp16), scale applied to S in registers.
// O += (Ph + Pl).V   (V single fp16).
// ---------------------------------------------------------------------------
#define AROWB 272
#define A_QH 0
#define A_QL (128 * AROWB)                  // 34816
#define A_KH (2 * 128 * AROWB)              // 69632
#define A_VH (A_KH + 64 * AROWB)            // 87040
#define ATTN_SMEM (A_VH + 64 * AROWB)       // 104448

__global__ __launch_bounds__(256, 1) void attn_mma_kernel(
    const __half* __restrict__ qhi, const __half* __restrict__ qlo,
    __half* __restrict__ ohi, __half* __restrict__ olo)
{
    extern __shared__ char smc[];
    uint32_t sb = smem_u32(smc);
    int tid  = threadIdx.x;
    int w    = tid >> 5;
    int lane = tid & 31;
    int h    = blockIdx.y;
    int bx   = (int)gridDim.x - 1 - (int)blockIdx.x;   // heavy tiles first
    int q0   = bx * 128;
    int kvh  = h >> 2;

    // Q tile hi+lo: 4096 cp16
#pragma unroll
    for (int i = 0; i < 16; i++) {
        int f   = tid + i * 256;
        int arr = f >> 11;
        int rem = f & 2047;
        int row = rem >> 4;
        int seg = rem & 15;
        const __half* src =
            (arr ? qlo : qhi) + (size_t)(q0 + row) * QKV_DIM + h * HD + seg * 8;
        cp16(sb + (arr ? A_QL : A_QH) + row * AROWB + seg * 16, src);
    }

    float oacc[16][4];
#pragma unroll
    for (int t = 0; t < 16; t++)
#pragma unroll
        for (int j = 0; j < 4; j++) oacc[t][j] = 0.0f;
    float mrow[2] = {-1e30f, -1e30f};
    float lrow[2] = {0.0f, 0.0f};

    int wmin = q0 + 16 * w;
    int nkt  = 2 * (bx + 1);

    for (int kt = 0; kt < nkt; kt++) {
        int k0 = kt * 64;
        // K/V tile (hi only): 2048 cp16
#pragma unroll
        for (int i = 0; i < 8; i++) {
            int f   = tid + i * 256;
            int arr = f >> 10;      // 0 K, 1 V
            int rem = f & 1023;
            int row = rem >> 4;
            int seg = rem & 15;
            int off = arr ? (HID + NKV * HD) : HID;
            const __half* src =
                qhi + (size_t)(k0 + row) * QKV_DIM + off + kvh * HD + seg * 8;
            cp16(sb + (arr ? A_VH : A_KH) + row * AROWB + seg * 16, src);
        }
        asm volatile("cp.async.commit_group;\n\tcp.async.wait_group 0;" ::: "memory");
        __syncthreads();

        if (k0 <= wmin + 15) {
            float sacc[8][4];
#pragma unroll
            for (int t = 0; t < 8; t++)
#pragma unroll
                for (int j = 0; j < 4; j++) sacc[t][j] = 0.0f;

            // ---- S = Q . K^T (2 passes)
#pragma unroll
            for (int ks = 0; ks < 8; ks++) {
                uint32_t qh_[4], ql_[4];
                uint32_t ao = (uint32_t)((16 * w + (lane & 15)) * AROWB
                                         + ks * 32 + (lane >> 4) * 16);
                ldsm_x4(qh_[0], qh_[1], qh_[2], qh_[3], sb + A_QH + ao);
                ldsm_x4(ql_[0], ql_[1], ql_[2], ql_[3], sb + A_QL + ao);
#pragma unroll
                for (int np = 0; np < 4; np++) {
                    uint32_t kh_[4];
                    uint32_t bo = (uint32_t)((np * 16 + (lane & 7)
                                              + ((lane >> 4) << 3)) * AROWB
                                             + ks * 32 + ((lane >> 3) & 1) * 16);
                    ldsm_x4(kh_[0], kh_[1], kh_[2], kh_[3], sb + A_KH + bo);
                    mma16816(sacc[2 * np],     qh_, kh_);
                    mma16816(sacc[2 * np],     ql_, kh_);
                    mma16816(sacc[2 * np + 1], qh_, kh_ + 2);
                    mma16816(sacc[2 * np + 1], ql_, kh_ + 2);
                }
            }

            // ---- apply softmax scale
#pragma unroll
            for (int nt = 0; nt < 8; nt++)
#pragma unroll
                for (int j = 0; j < 4; j++) sacc[nt][j] *= SCALE;

            // ---- causal mask
            int r1 = wmin + (lane >> 2);
            if (k0 + 63 > wmin) {
#pragma unroll
                for (int nt = 0; nt < 8; nt++) {
                    int c0 = k0 + nt * 8 + (lane & 3) * 2;
                    if (c0     > r1)     sacc[nt][0] = -1e30f;
                    if (c0 + 1 > r1)     sacc[nt][1] = -1e30f;
                    if (c0     > r1 + 8) sacc[nt][2] = -1e30f;
                    if (c0 + 1 > r1 + 8) sacc[nt][3] = -1e30f;
                }
            }

            // ---- online softmax
#pragma unroll
            for (int hf = 0; hf < 2; hf++) {
                float mx = -1e30f;
#pragma unroll
                for (int nt = 0; nt < 8; nt++)
                    mx = fmaxf(mx, fmaxf(sacc[nt][2 * hf], sacc[nt][2 * hf + 1]));
                mx = fmaxf(mx, __shfl_xor_sync(0xffffffffu, mx, 1));
                mx = fmaxf(mx, __shfl_xor_sync(0xffffffffu, mx, 2));
                float mn   = fmaxf(mrow[hf], mx);
                float corr = __expf(mrow[hf] - mn);
                mrow[hf] = mn;
                float sum = 0.0f;
#pragma unroll
                for (int nt = 0; nt < 8; nt++) {
                    float p0 = __expf(sacc[nt][2 * hf]     - mn);
                    float p1 = __expf(sacc[nt][2 * hf + 1] - mn);
                    sacc[nt][2 * hf]     = p0;
                    sacc[nt][2 * hf + 1] = p1;
                    sum += p0 + p1;
                }
                sum += __shfl_xor_sync(0xffffffffu, sum, 1);
                sum += __shfl_xor_sync(0xffffffffu, sum, 2);
                lrow[hf] = lrow[hf] * corr + sum;
#pragma unroll
                for (int nt = 0; nt < 16; nt++) {
                    oacc[nt][2 * hf]     *= corr;
                    oacc[nt][2 * hf + 1] *= corr;
                }
            }

            // ---- O += P . V (2 passes)
#pragma unroll
            for (int j = 0; j < 4; j++) {
                uint32_t ph_[4], pl_[4];
                ph_[0] = pack_f16x2(sacc[2 * j][0],     sacc[2 * j][1]);
                ph_[1] = pack_f16x2(sacc[2 * j][2],     sacc[2 * j][3]);
                ph_[2] = pack_f16x2(sacc[2 * j + 1][0], sacc[2 * j + 1][1]);
                ph_[3] = pack_f16x2(sacc[2 * j + 1][2], sacc[2 * j + 1][3]);
                pl_[0] = pack_f16x2(sacc[2 * j][0]     - f16lo_f(ph_[0]),
                                    sacc[2 * j][1]     - f16hi_f(ph_[0]));
                pl_[1] = pack_f16x2(sacc[2 * j][2]     - f16lo_f(ph_[1]),
                                    sacc[2 * j][3]     - f16hi_f(ph_[1]));
                pl_[2] = pack_f16x2(sacc[2 * j + 1][0] - f16lo_f(ph_[2]),
                                    sacc[2 * j + 1][1] - f16hi_f(ph_[2]));
                pl_[3] = pack_f16x2(sacc[2 * j + 1][2] - f16lo_f(ph_[3]),
                                    sacc[2 * j + 1][3] - f16hi_f(ph_[3]));
#pragma unroll
                for (int np = 0; np < 8; np++) {
                    uint32_t vh_[4];
                    uint32_t vo = (uint32_t)((j * 16 + (lane & 7)
                                              + ((lane >> 3) & 1) * 8) * AROWB
                                             + (np * 16 + ((lane >> 4) << 3)) * 2);
                    ldsm_x4t(vh_[0], vh_[1], vh_[2], vh_[3], sb + A_VH + vo);
                    mma16816(oacc[2 * np],     ph_, vh_);
                    mma16816(oacc[2 * np],     pl_, vh_);
                    mma16816(oacc[2 * np + 1], ph_, vh_ + 2);
                    mma16816(oacc[2 * np + 1], pl_, vh_ + 2);
                }
            }
        }
        __syncthreads();
    }

    // ---- epilogue: normalize + split fp16 hi/lo write
    float inv0 = 1.0f / lrow[0];
    float inv1 = 1.0f / lrow[1];
    int r1 = q0 + 16 * w + (lane >> 2);
    size_t base1 = (size_t)r1 * HID + h * HD + (lane & 3) * 2;
    size_t base2 = base1 + (size_t)8 * HID;
#pragma unroll
    for (int nt = 0; nt < 16; nt++) {
        float v0 = oacc[nt][0] * inv0;
        float v1 = oacc[nt][1] * inv0;
        uint32_t hiw = pack_f16x2(v0, v1);
        uint32_t low = pack_f16x2(v0 - f16lo_f(hiw), v1 - f16hi_f(hiw));
        *(uint32_t*)(ohi + base1 + nt * 8) = hiw;
        *(uint32_t*)(olo + base1 + nt * 8) = low;
        float v2 = oacc[nt][2] * inv1;
        float v3 = oacc[nt][3] * inv1;
        uint32_t hiw2 = pack_f16x2(v2, v3);
        uint32_t low2 = pack_f16x2(v2 - f16lo_f(hiw2), v3 - f16hi_f(hiw2));
        *(uint32_t*)(ohi + base2 + nt * 8) = hiw2;
        *(uint32_t*)(olo + base2 + nt * 8) = low2;
    }
}

// ---------------------------------------------------------------------------
// Launch
// ---------------------------------------------------------------------------
extern "C" void kernel_launch(void* const* d_in, const int* in_sizes, int n_in,
                              void* d_out, int out_size)
{
    (void)in_sizes; (void)n_in; (void)out_size;
    const float* x     = (const float*)d_in[0];
    const int*   pos   = (const int*)d_in[1];
    const float* w_qkv = (const float*)d_in[2];
    const float* w_o   = (const float*)d_in[3];
    float*       out   = (float*)d_out;

    void *p_qkv, *p_xh, *p_xl, *p_wq, *p_wo, *p_sph, *p_spl, *p_ah, *p_al;
    cudaGetSymbolAddress(&p_qkv, g_qkv);
    cudaGetSymbolAddress(&p_xh, g_x_hi);
    cudaGetSymbolAddress(&p_xl, g_x_lo);
    cudaGetSymbolAddress(&p_wq, g_wqkv);
    cudaGetSymbolAddress(&p_wo, g_wo);
    cudaGetSymbolAddress(&p_sph, g_qkvsp_hi);
    cudaGetSymbolAddress(&p_spl, g_qkvsp_lo);
    cudaGetSymbolAddress(&p_ah, g_attn_hi);
    cudaGetSymbolAddress(&p_al, g_attn_lo);
    float* qkv = (float*)p_qkv;

    cudaFuncSetAttribute(gemm_mma_split_kernel,
                         cudaFuncAttributeMaxDynamicSharedMemorySize, GEMM_SMEM);
    cudaFuncSetAttribute(attn_mma_kernel,
                         cudaFuncAttributeMaxDynamicSharedMemorySize, ATTN_SMEM);

    // RoPE table
    rope_table_kernel<<<(S_LEN * 64 + 255) / 256, 256>>>(pos);

    // Converts
    {
        int n1 = S_LEN * HID / 4;
        convert_split_kernel<<<(n1 + 255) / 256, 256>>>(
            x, (__half*)p_xh, (__half*)p_xl, n1);
        int n2 = QKV_DIM * HID / 4;
        convert_half_kernel<<<(n2 + 255) / 256, 256>>>(w_qkv, (__half*)p_wq, n2);
        int n3 = HID * HID / 4;
        convert_half_kernel<<<(n3 + 255) / 256, 256>>>(w_o, (__half*)p_wo, n3);
    }

    // QKV projection
    gemm_mma_split_kernel<<<dim3(S_LEN / 256, QKV_DIM / 128), 256, GEMM_SMEM>>>(
        (const __half*)p_xh, (const __half*)p_xl, (const __half*)p_wq,
        qkv, HID, QKV_DIM);

    // RoPE + split qkv
    postqkv_kernel<<<(S_LEN * 48 * 64 + 255) / 256, 256>>>(
        qkv, (__half*)p_sph, (__half*)p_spl);

    // Tensor-core flash attention
    attn_mma_kernel<<<dim3(S_LEN / 128, NH), 256, ATTN_SMEM>>>(
        (const __half*)p_sph, (const __half*)p_spl,
        (__half*)p_ah, (__half*)p_al);

    // Output projection
    gemm_mma_split_kernel<<<dim3(S_LEN / 256, HID / 128), 256, GEMM_SMEM>>>(
        (const __half*)p_ah, (const __half*)p_al, (const __half*)p_wo,
        out, HID, HID);
}

// round 7
// speedup vs baseline: 3.8554x; 1.0240x over previous
#include <cuda_runtime.h>
#include <cuda_fp16.h>
#include <math.h>
#include <stdint.h>

// Problem constants
#define S_LEN   2048
#define HID     4096
#define NH      32
#define NKV     8
#define HD      128
#define QKV_DIM 6144   // NH*HD + 2*NKV*HD
#define GROUPS  4
#define SCALE   0.08838834764831845f   // 1/sqrt(128)

// ---------------------------------------------------------------------------
// Device scratch (no allocations allowed)
// ---------------------------------------------------------------------------
__device__ float g_qkv[S_LEN * QKV_DIM];   // fp32 QKV GEMM out
__device__ float g_cos[S_LEN * 64];
__device__ float g_sin[S_LEN * 64];

__device__ __align__(128) __half g_x_hi[S_LEN * HID];
__device__ __align__(128) __half g_x_lo[S_LEN * HID];
__device__ __align__(128) __half g_wqkv[QKV_DIM * HID];
__device__ __align__(128) __half g_wo[HID * HID];
__device__ __align__(128) __half g_qkvsp_hi[S_LEN * QKV_DIM];
__device__ __align__(128) __half g_qkvsp_lo[S_LEN * QKV_DIM];   // lo: Q heads only
__device__ __align__(128) __half g_attn_hi[S_LEN * HID];
__device__ __align__(128) __half g_attn_lo[S_LEN * HID];

// ---------------------------------------------------------------------------
// Helpers
// ---------------------------------------------------------------------------
static __device__ __forceinline__ uint32_t smem_u32(const void* p) {
    uint32_t a;
    asm("{ .reg .u64 t; cvta.to.shared.u64 t, %1; cvt.u32.u64 %0, t; }"
        : "=r"(a) : "l"(p));
    return a;
}

static __device__ __forceinline__ void cp16(uint32_t dst, const void* src) {
    asm volatile("cp.async.cg.shared.global [%0], [%1], 16;"
                 :: "r"(dst), "l"(src));
}

static __device__ __forceinline__ void ldsm_x4(uint32_t& r0, uint32_t& r1,
                                               uint32_t& r2, uint32_t& r3,
                                               uint32_t addr) {
    asm volatile("ldmatrix.sync.aligned.m8n8.x4.shared.b16 {%0,%1,%2,%3}, [%4];"
                 : "=r"(r0), "=r"(r1), "=r"(r2), "=r"(r3) : "r"(addr));
}

static __device__ __forceinline__ void ldsm_x4t(uint32_t& r0, uint32_t& r1,
                                                uint32_t& r2, uint32_t& r3,
                                                uint32_t addr) {
    asm volatile("ldmatrix.sync.aligned.m8n8.x4.trans.shared.b16 {%0,%1,%2,%3}, [%4];"
                 : "=r"(r0), "=r"(r1), "=r"(r2), "=r"(r3) : "r"(addr));
}

static __device__ __forceinline__ void mma16816(float* d, const uint32_t* a,
                                                const uint32_t* b) {
    asm volatile(
        "mma.sync.aligned.m16n8k16.row.col.f32.f16.f16.f32 "
        "{%0,%1,%2,%3}, {%4,%5,%6,%7}, {%8,%9}, {%0,%1,%2,%3};"
        : "+f"(d[0]), "+f"(d[1]), "+f"(d[2]), "+f"(d[3])
        : "r"(a[0]), "r"(a[1]), "r"(a[2]), "r"(a[3]), "r"(b[0]), "r"(b[1]));
}

static __device__ __forceinline__ uint32_t pack_f16x2(float lo, float hi) {
    uint32_t d;
    asm("cvt.rn.f16x2.f32 %0, %1, %2;" : "=r"(d) : "f"(hi), "f"(lo));
    return d;
}
static __device__ __forceinline__ float f16lo_f(uint32_t u) {
    return __half2float(__ushort_as_half((unsigned short)(u & 0xffffu)));
}
static __device__ __forceinline__ float f16hi_f(uint32_t u) {
    return __half2float(__ushort_as_half((unsigned short)(u >> 16)));
}

// ---------------------------------------------------------------------------
// fp32 -> fp16 hi/lo split (8 elems/thread)
// ---------------------------------------------------------------------------
__global__ void convert_split_kernel(const float* __restrict__ src,
                                     __half* __restrict__ hi,
                                     __half* __restrict__ lo, int n8) {
    int i = blockIdx.x * blockDim.x + threadIdx.x;
    if (i >= n8) return;
    size_t o = (size_t)i * 8;
#pragma unroll
    for (int half8 = 0; half8 < 2; half8++) {
        float4 x = *(const float4*)(src + o + half8 * 4);
        uint32_t h0 = pack_f16x2(x.x, x.y);
        uint32_t h1 = pack_f16x2(x.z, x.w);
        uint32_t l0 = pack_f16x2(x.x - f16lo_f(h0), x.y - f16hi_f(h0));
        uint32_t l1 = pack_f16x2(x.z - f16lo_f(h1), x.w - f16hi_f(h1));
        *(uint2*)(hi + o + half8 * 4) = make_uint2(h0, h1);
        *(uint2*)(lo + o + half8 * 4) = make_uint2(l0, l1);
    }
}

// fp32 -> single fp16 (8 elems/thread)
__global__ void convert_half_kernel(const float* __restrict__ src,
                                    __half* __restrict__ dst, int n8) {
    int i = blockIdx.x * blockDim.x + threadIdx.x;
    if (i >= n8) return;
    size_t o = (size_t)i * 8;
    float4 x = *(const float4*)(src + o);
    float4 y = *(const float4*)(src + o + 4);
    *(uint4*)(dst + o) = make_uint4(pack_f16x2(x.x, x.y), pack_f16x2(x.z, x.w),
                                    pack_f16x2(y.x, y.y), pack_f16x2(y.z, y.w));
}

// ---------------------------------------------------------------------------
// RoPE table (verified)
// ---------------------------------------------------------------------------
__global__ void rope_table_kernel(const int* __restrict__ pos_ids) {
    int idx = blockIdx.x * blockDim.x + threadIdx.x;
    if (idx >= S_LEN * 64) return;
    int s = idx >> 6;
    int d = idx & 63;
    float expo = (float)(2 * d) * (1.0f / 128.0f);
    float invf = exp2f(-expo * 16.609640474436813f);   // log2(100000)
    float a = (float)((double)pos_ids[s] * (double)invf);
    double ar = (double)a;
    double k  = rint(ar * 0.15915494309189535);
    ar -= k * 6.283185307179586;
    float r = (float)ar;
    g_cos[idx] = cosf(r);
    g_sin[idx] = sinf(r);
}

// ---------------------------------------------------------------------------
// Post-QKV: RoPE on q,k (no scale folding), fp16 hi for all, lo for Q heads.
// 2 d-values per thread (vectorized loads/stores).
// ---------------------------------------------------------------------------
__global__ void postqkv_kernel(const float* __restrict__ qkv,
                               __half* __restrict__ hi,
                               __half* __restrict__ lo) {
    int idx = blockIdx.x * blockDim.x + threadIdx.x;
    if (idx >= S_LEN * 48 * 32) return;
    int d    = (idx & 31) * 2;
    int rem  = idx >> 5;
    int head = rem % 48;
    int s    = rem / 48;
    size_t base = (size_t)s * QKV_DIM + head * 128;
    float2 x1 = *(const float2*)(qkv + base + d);
    float2 x2 = *(const float2*)(qkv + base + d + 64);
    if (head < 40) {
        float2 c  = *(const float2*)(g_cos + (s << 6) + d);
        float2 sn = *(const float2*)(g_sin + (s << 6) + d);
        float y1x = x1.x * c.x - x2.x * sn.x;
        float y1y = x1.y * c.y - x2.y * sn.y;
        float y2x = x2.x * c.x + x1.x * sn.x;
        float y2y = x2.y * c.y + x1.y * sn.y;
        x1 = make_float2(y1x, y1y);
        x2 = make_float2(y2x, y2y);
    }
    uint32_t h1 = pack_f16x2(x1.x, x1.y);
    uint32_t h2 = pack_f16x2(x2.x, x2.y);
    *(uint32_t*)(hi + base + d)      = h1;
    *(uint32_t*)(hi + base + d + 64) = h2;
    if (head < 32) {
        *(uint32_t*)(lo + base + d) =
            pack_f16x2(x1.x - f16lo_f(h1), x1.y - f16hi_f(h1));
        *(uint32_t*)(lo + base + d + 64) =
            pack_f16x2(x2.x - f16lo_f(h2), x2.y - f16hi_f(h2));
    }
}

// ---------------------------------------------------------------------------
// fp16-split GEMM via mma.sync (NT): C = (Ah + Al) . B^T, 2 passes.
// CTA 256x128, BK=32, 256 threads (4x2 warps, warp tile 64x64), 4-stage pipe.
// ---------------------------------------------------------------------------
#define ROWB 80                         // 64B data + 16B pad
#define G_AHI 0
#define G_ALO (256 * ROWB)              // 20480
#define G_B   (2 * 256 * ROWB)          // 40960
#define G_STAGE (G_B + 128 * ROWB)      // 51200
#define GEMM_SMEM (4 * G_STAGE)         // 204800

__global__ __launch_bounds__(256, 1) void gemm_mma_split_kernel(
    const __half* __restrict__ Ahi, const __half* __restrict__ Alo,
    const __half* __restrict__ B,
    float* __restrict__ C, int K, int N)
{
    extern __shared__ char smc[];
    uint32_t sb = smem_u32(smc);
    int tid  = threadIdx.x;
    int wid  = tid >> 5;
    int lane = tid & 31;
    int wm = wid >> 1;     // 0..3
    int wn = wid & 1;      // 0..1
    int m0 = blockIdx.x * 256;
    int n0 = blockIdx.y * 128;

    const size_t rs = (size_t)K * 2;
    const char* pAhi = (const char*)Ahi + (size_t)m0 * rs;
    const char* pAlo = (const char*)Alo + (size_t)m0 * rs;
    const char* pB   = (const char*)B   + (size_t)n0 * rs;

    auto load_chunk = [&](int stage, int c) {
        uint32_t base = sb + stage * G_STAGE;
        size_t kb = (size_t)c * 64;
#pragma unroll
        for (int i = 0; i < 8; i++) {
            int f   = tid + i * 256;
            int arr = f >> 10;
            int rem = f & 1023;
            int row = rem >> 2;
            int seg = (rem & 3) * 16;
            uint32_t so = (uint32_t)(row * ROWB + seg) + (arr ? G_ALO : G_AHI);
            const char* p = (arr ? pAlo : pAhi) + (size_t)row * rs + kb + seg;
            cp16(base + so, p);
        }
#pragma unroll
        for (int i = 0; i < 2; i++) {
            int f   = tid + i * 256;
            int row = f >> 2;
            int seg = (f & 3) * 16;
            cp16(base + G_B + (uint32_t)(row * ROWB + seg),
                 pB + (size_t)row * rs + kb + seg);
        }
        asm volatile("cp.async.commit_group;" ::: "memory");
    };

    float acc[32][4];
#pragma unroll
    for (int t = 0; t < 32; t++)
#pragma unroll
        for (int j = 0; j < 4; j++) acc[t][j] = 0.0f;

    uint32_t a_off  = (uint32_t)((wm * 64 + (lane & 15)) * ROWB + (lane >> 4) * 16);
    uint32_t b_base = (uint32_t)((wn * 64 + (lane & 7) + ((lane >> 4) << 3)) * ROWB
                                 + ((lane >> 3) & 1) * 16);

    int nch = K / 32;                       // 128
    load_chunk(0, 0);
    load_chunk(1, 1);
    load_chunk(2, 2);

    for (int c = 0; c < nch; c++) {
        // chunk c is commit #(c+1); commits so far = c+3 -> pending allowed = 2
        asm volatile("cp.async.wait_group 2;" ::: "memory");
        __syncthreads();
        if (c + 3 < nch) load_chunk((c + 3) & 3, c + 3);
        else asm volatile("cp.async.commit_group;" ::: "memory");

        uint32_t tb = sb + (c & 3) * G_STAGE;
#pragma unroll
        for (int ks = 0; ks < 2; ks++) {
            uint32_t ko = (uint32_t)(ks * 32);
            uint32_t bh[4][4];
#pragma unroll
            for (int np = 0; np < 4; np++) {
                uint32_t bo = b_base + ko + (uint32_t)(np * 16 * ROWB);
                ldsm_x4(bh[np][0], bh[np][1], bh[np][2], bh[np][3], tb + G_B + bo);
            }
#pragma unroll
            for (int mt = 0; mt < 4; mt++) {
                uint32_t ah[4];
                uint32_t ao = a_off + ko + (uint32_t)(mt * 16 * ROWB);
                ldsm_x4(ah[0], ah[1], ah[2], ah[3], tb + G_AHI + ao);
#pragma unroll
                for (int np = 0; np < 4; np++) {
                    mma16816(acc[mt * 8 + 2 * np],     ah, bh[np]);
                    mma16816(acc[mt * 8 + 2 * np + 1], ah, bh[np] + 2);
                }
            }
#pragma unroll
            for (int mt = 0; mt < 4; mt++) {
                uint32_t al[4];
                uint32_t ao = a_off + ko + (uint32_t)(mt * 16 * ROWB);
                ldsm_x4(al[0], al[1], al[2], al[3], tb + G_ALO + ao);
#pragma unroll
                for (int np = 0; np < 4; np++) {
                    mma16816(acc[mt * 8 + 2 * np],     al, bh[np]);
                    mma16816(acc[mt * 8 + 2 * np + 1], al, bh[np] + 2);
                }
            }
        }
    }

    // Epilogue
    int mbase = m0 + wm * 64 + (lane >> 2);
    int nbase = n0 + wn * 64 + (lane & 3) * 2;
#pragma unroll
    for (int mt = 0; mt < 4; mt++) {
#pragma unroll
        for (int nt = 0; nt < 8; nt++) {
            float* d = acc[mt * 8 + nt];
            int r = mbase + mt * 16;
            int cc = nbase + nt * 8;
            *(float2*)(C + (size_t)r * N + cc)       = make_float2(d[0], d[1]);
            *(float2*)(C + (size_t)(r + 8) * N + cc) = make_float2(d[2], d[3]);
        }
    }
}

// ---------------------------------------------------------------------------
// Tensor-core flash attention (causal, GQA), fp16 2-pass split,
// double-buffered K/V tiles.
// ---------------------------------------------------------------------------
#define AROWB 272
#define A_QH 0
#define A_QL (128 * AROWB)                  // 34816
#define A_KV0 (2 * 128 * AROWB)             // 69632
#define KV_VOFF (64 * AROWB)                // 17408
#define KV_STAGE (128 * AROWB)              // 34816 (K 64 rows + V 64 rows)
#define ATTN_SMEM (A_KV0 + 2 * KV_STAGE)    // 139264

__global__ __launch_bounds__(256, 1) void attn_mma_kernel(
    const __half* __restrict__ qhi, const __half* __restrict__ qlo,
    __half* __restrict__ ohi, __half* __restrict__ olo)
{
    extern __shared__ char smc[];
    uint32_t sb = smem_u32(smc);
    int tid  = threadIdx.x;
    int w    = tid >> 5;
    int lane = tid & 31;
    int h    = blockIdx.y;
    int bx   = (int)gridDim.x - 1 - (int)blockIdx.x;   // heavy tiles first
    int q0   = bx * 128;
    int kvh  = h >> 2;

    auto load_kv = [&](int stage, int kt) {
        int k0 = kt * 64;
        uint32_t kbase = sb + A_KV0 + stage * KV_STAGE;
#pragma unroll
        for (int i = 0; i < 8; i++) {
            int f   = tid + i * 256;
            int arr = f >> 10;          // 0 K, 1 V
            int rem = f & 1023;
            int row = rem >> 4;
            int seg = rem & 15;
            int off = arr ? (HID + NKV * HD) : HID;
            const __half* src =
                qhi + (size_t)(k0 + row) * QKV_DIM + off + kvh * HD + seg * 8;
            cp16(kbase + (arr ? KV_VOFF : 0) + row * AROWB + seg * 16, src);
        }
        asm volatile("cp.async.commit_group;" ::: "memory");
    };

    // Q tile hi+lo (committed together with KV tile 0)
#pragma unroll
    for (int i = 0; i < 16; i++) {
        int f   = tid + i * 256;
        int arr = f >> 11;
        int rem = f & 2047;
        int row = rem >> 4;
        int seg = rem & 15;
        const __half* src =
            (arr ? qlo : qhi) + (size_t)(q0 + row) * QKV_DIM + h * HD + seg * 8;
        cp16(sb + (arr ? A_QL : A_QH) + row * AROWB + seg * 16, src);
    }
    load_kv(0, 0);   // commit #1 (Q + KV0)

    float oacc[16][4];
#pragma unroll
    for (int t = 0; t < 16; t++)
#pragma unroll
        for (int j = 0; j < 4; j++) oacc[t][j] = 0.0f;
    float mrow[2] = {-1e30f, -1e30f};
    float lrow[2] = {0.0f, 0.0f};

    int wmin = q0 + 16 * w;
    int nkt  = 2 * (bx + 1);

    for (int kt = 0; kt < nkt; kt++) {
        int buf = kt & 1;
        int k0  = kt * 64;
        if (kt + 1 < nkt) {
            load_kv(buf ^ 1, kt + 1);
            asm volatile("cp.async.wait_group 1;" ::: "memory");
        } else {
            asm volatile("cp.async.wait_group 0;" ::: "memory");
        }
        __syncthreads();

        if (k0 <= wmin + 15) {
            uint32_t kvb = sb + A_KV0 + buf * KV_STAGE;
            float sacc[8][4];
#pragma unroll
            for (int t = 0; t < 8; t++)
#pragma unroll
                for (int j = 0; j < 4; j++) sacc[t][j] = 0.0f;

            // ---- S = Q . K^T (2 passes)
#pragma unroll
            for (int ks = 0; ks < 8; ks++) {
                uint32_t qh_[4], ql_[4];
                uint32_t ao = (uint32_t)((16 * w + (lane & 15)) * AROWB
                                         + ks * 32 + (lane >> 4) * 16);
                ldsm_x4(qh_[0], qh_[1], qh_[2], qh_[3], sb + A_QH + ao);
                ldsm_x4(ql_[0], ql_[1], ql_[2], ql_[3], sb + A_QL + ao);
#pragma unroll
                for (int np = 0; np < 4; np++) {
                    uint32_t kh_[4];
                    uint32_t bo = (uint32_t)((np * 16 + (lane & 7)
                                              + ((lane >> 4) << 3)) * AROWB
                                             + ks * 32 + ((lane >> 3) & 1) * 16);
                    ldsm_x4(kh_[0], kh_[1], kh_[2], kh_[3], kvb + bo);
                    mma16816(sacc[2 * np],     qh_, kh_);
                    mma16816(sacc[2 * np],     ql_, kh_);
                    mma16816(sacc[2 * np + 1], qh_, kh_ + 2);
                    mma16816(sacc[2 * np + 1], ql_, kh_ + 2);
                }
            }

            // ---- scale
#pragma unroll
            for (int nt = 0; nt < 8; nt++)
#pragma unroll
                for (int j = 0; j < 4; j++) sacc[nt][j] *= SCALE;

            // ---- causal mask
            int r1 = wmin + (lane >> 2);
            if (k0 + 63 > wmin) {
#pragma unroll
                for (int nt = 0; nt < 8; nt++) {
                    int c0 = k0 + nt * 8 + (lane & 3) * 2;
                    if (c0     > r1)     sacc[nt][0] = -1e30f;
                    if (c0 + 1 > r1)     sacc[nt][1] = -1e30f;
                    if (c0     > r1 + 8) sacc[nt][2] = -1e30f;
                    if (c0 + 1 > r1 + 8) sacc[nt][3] = -1e30f;
                }
            }

            // ---- online softmax
#pragma unroll
            for (int hf = 0; hf < 2; hf++) {
                float mx = -1e30f;
#pragma unroll
                for (int nt = 0; nt < 8; nt++)
                    mx = fmaxf(mx, fmaxf(sacc[nt][2 * hf], sacc[nt][2 * hf + 1]));
                mx = fmaxf(mx, __shfl_xor_sync(0xffffffffu, mx, 1));
                mx = fmaxf(mx, __shfl_xor_sync(0xffffffffu, mx, 2));
                float mn   = fmaxf(mrow[hf], mx);
                float corr = __expf(mrow[hf] - mn);
                mrow[hf] = mn;
                float sum = 0.0f;
#pragma unroll
                for (int nt = 0; nt < 8; nt++) {
                    float p0 = __expf(sacc[nt][2 * hf]     - mn);
                    float p1 = __expf(sacc[nt][2 * hf + 1] - mn);
                    sacc[nt][2 * hf]     = p0;
                    sacc[nt][2 * hf + 1] = p1;
                    sum += p0 + p1;
                }
                sum += __shfl_xor_sync(0xffffffffu, sum, 1);
                sum += __shfl_xor_sync(0xffffffffu, sum, 2);
                lrow[hf] = lrow[hf] * corr + sum;
#pragma unroll
                for (int nt = 0; nt < 16; nt++) {
                    oacc[nt][2 * hf]     *= corr;
                    oacc[nt][2 * hf + 1] *= corr;
                }
            }

            // ---- O += P . V (2 passes)
#pragma unroll
            for (int j = 0; j < 4; j++) {
                uint32_t ph_[4], pl_[4];
                ph_[0] = pack_f16x2(sacc[2 * j][0],     sacc[2 * j][1]);
                ph_[1] = pack_f16x2(sacc[2 * j][2],     sacc[2 * j][3]);
                ph_[2] = pack_f16x2(sacc[2 * j + 1][0], sacc[2 * j + 1][1]);
                ph_[3] = pack_f16x2(sacc[2 * j + 1][2], sacc[2 * j + 1][3]);
                pl_[0] = pack_f16x2(sacc[2 * j][0]     - f16lo_f(ph_[0]),
                                    sacc[2 * j][1]     - f16hi_f(ph_[0]));
                pl_[1] = pack_f16x2(sacc[2 * j][2]     - f16lo_f(ph_[1]),
                                    sacc[2 * j][3]     - f16hi_f(ph_[1]));
                pl_[2] = pack_f16x2(sacc[2 * j + 1][0] - f16lo_f(ph_[2]),
                                    sacc[2 * j + 1][1] - f16hi_f(ph_[2]));
                pl_[3] = pack_f16x2(sacc[2 * j + 1][2] - f16lo_f(ph_[3]),
                                    sacc[2 * j + 1][3] - f16hi_f(ph_[3]));
#pragma unroll
                for (int np = 0; np < 8; np++) {
                    uint32_t vh_[4];
                    uint32_t vo = (uint32_t)((j * 16 + (lane & 7)
                                              + ((lane >> 3) & 1) * 8) * AROWB
                                             + (np * 16 + ((lane >> 4) << 3)) * 2);
                    ldsm_x4t(vh_[0], vh_[1], vh_[2], vh_[3], kvb + KV_VOFF + vo);
                    mma16816(oacc[2 * np],     ph_, vh_);
                    mma16816(oacc[2 * np],     pl_, vh_);
                    mma16816(oacc[2 * np + 1], ph_, vh_ + 2);
                    mma16816(oacc[2 * np + 1], pl_, vh_ + 2);
                }
            }
        }
        __syncthreads();
    }

    // ---- epilogue
    float inv0 = 1.0f / lrow[0];
    float inv1 = 1.0f / lrow[1];
    int r1 = q0 + 16 * w + (lane >> 2);
    size_t base1 = (size_t)r1 * HID + h * HD + (lane & 3) * 2;
    size_t base2 = base1 + (size_t)8 * HID;
#pragma unroll
    for (int nt = 0; nt < 16; nt++) {
        float v0 = oacc[nt][0] * inv0;
        float v1 = oacc[nt][1] * inv0;
        uint32_t hiw = pack_f16x2(v0, v1);
        uint32_t low = pack_f16x2(v0 - f16lo_f(hiw), v1 - f16hi_f(hiw));
        *(uint32_t*)(ohi + base1 + nt * 8) = hiw;
        *(uint32_t*)(olo + base1 + nt * 8) = low;
        float v2 = oacc[nt][2] * inv1;
        float v3 = oacc[nt][3] * inv1;
        uint32_t hiw2 = pack_f16x2(v2, v3);
        uint32_t low2 = pack_f16x2(v2 - f16lo_f(hiw2), v3 - f16hi_f(hiw2));
        *(uint32_t*)(ohi + base2 + nt * 8) = hiw2;
        *(uint32_t*)(olo + base2 + nt * 8) = low2;
    }
}

// ---------------------------------------------------------------------------
// Launch
// ---------------------------------------------------------------------------
extern "C" void kernel_launch(void* const* d_in, const int* in_sizes, int n_in,
                              void* d_out, int out_size)
{
    (void)in_sizes; (void)n_in; (void)out_size;
    const float* x     = (const float*)d_in[0];
    const int*   pos   = (const int*)d_in[1];
    const float* w_qkv = (const float*)d_in[2];
    const float* w_o   = (const float*)d_in[3];
    float*       out   = (float*)d_out;

    void *p_qkv, *p_xh, *p_xl, *p_wq, *p_wo, *p_sph, *p_spl, *p_ah, *p_al;
    cudaGetSymbolAddress(&p_qkv, g_qkv);
    cudaGetSymbolAddress(&p_xh, g_x_hi);
    cudaGetSymbolAddress(&p_xl, g_x_lo);
    cudaGetSymbolAddress(&p_wq, g_wqkv);
    cudaGetSymbolAddress(&p_wo, g_wo);
    cudaGetSymbolAddress(&p_sph, g_qkvsp_hi);
    cudaGetSymbolAddress(&p_spl, g_qkvsp_lo);
    cudaGetSymbolAddress(&p_ah, g_attn_hi);
    cudaGetSymbolAddress(&p_al, g_attn_lo);
    float* qkv = (float*)p_qkv;

    cudaFuncSetAttribute(gemm_mma_split_kernel,
                         cudaFuncAttributeMaxDynamicSharedMemorySize, GEMM_SMEM);
    cudaFuncSetAttribute(attn_mma_kernel,
                         cudaFuncAttributeMaxDynamicSharedMemorySize, ATTN_SMEM);

    // RoPE table
    rope_table_kernel<<<(S_LEN * 64 + 255) / 256, 256>>>(pos);

    // Converts
    {
        int n1 = S_LEN * HID / 8;
        convert_split_kernel<<<(n1 + 255) / 256, 256>>>(
            x, (__half*)p_xh, (__half*)p_xl, n1);
        int n2 = QKV_DIM * HID / 8;
        convert_half_kernel<<<(n2 + 255) / 256, 256>>>(w_qkv, (__half*)p_wq, n2);
        int n3 = HID * HID / 8;
        convert_half_kernel<<<(n3 + 255) / 256, 256>>>(w_o, (__half*)p_wo, n3);
    }

    // QKV projection
    gemm_mma_split_kernel<<<dim3(S_LEN / 256, QKV_DIM / 128), 256, GEMM_SMEM>>>(
        (const __half*)p_xh, (const __half*)p_xl, (const __half*)p_wq,
        qkv, HID, QKV_DIM);

    // RoPE + split qkv
    postqkv_kernel<<<(S_LEN * 48 * 32 + 255) / 256, 256>>>(
        qkv, (__half*)p_sph, (__half*)p_spl);

    // Tensor-core flash attention
    attn_mma_kernel<<<dim3(S_LEN / 128, NH), 256, ATTN_SMEM>>>(
        (const __half*)p_sph, (const __half*)p_spl,
        (__half*)p_ah, (__half*)p_al);

    // Output projection
    gemm_mma_split_kernel<<<dim3(S_LEN / 256, HID / 128), 256, GEMM_SMEM>>>(
        (const __half*)p_ah, (const __half*)p_al, (const __half*)p_wo,
        out, HID, HID);
}

// round 8
// speedup vs baseline: 3.8576x; 1.0006x over previous
#include <cuda_runtime.h>
#include <cuda_fp16.h>
#include <math.h>
#include <stdint.h>

// Problem constants
#define S_LEN   2048
#define HID     4096
#define NH      32
#define NKV     8
#define HD      128
#define QKV_DIM 6144   // NH*HD + 2*NKV*HD
#define GROUPS  4
#define SCALE   0.08838834764831845f   // 1/sqrt(128)

// ---------------------------------------------------------------------------
// Device scratch (no allocations allowed)
// ---------------------------------------------------------------------------
__device__ float g_qkv[S_LEN * QKV_DIM];   // fp32 QKV GEMM out
__device__ float g_cos[S_LEN * 64];
__device__ float g_sin[S_LEN * 64];

__device__ __align__(128) __half g_x_hi[S_LEN * HID];
__device__ __align__(128) __half g_x_lo[S_LEN * HID];
__device__ __align__(128) __half g_wqkv[QKV_DIM * HID];
__device__ __align__(128) __half g_wo[HID * HID];
__device__ __align__(128) __half g_qkvsp_hi[S_LEN * QKV_DIM];
__device__ __align__(128) __half g_qkvsp_lo[S_LEN * QKV_DIM];   // lo: Q heads only
__device__ __align__(128) __half g_attn_hi[S_LEN * HID];
__device__ __align__(128) __half g_attn_lo[S_LEN * HID];

// ---------------------------------------------------------------------------
// Helpers
// ---------------------------------------------------------------------------
static __device__ __forceinline__ uint32_t smem_u32(const void* p) {
    uint32_t a;
    asm("{ .reg .u64 t; cvta.to.shared.u64 t, %1; cvt.u32.u64 %0, t; }"
        : "=r"(a) : "l"(p));
    return a;
}

static __device__ __forceinline__ void cp16(uint32_t dst, const void* src) {
    asm volatile("cp.async.cg.shared.global [%0], [%1], 16;"
                 :: "r"(dst), "l"(src));
}

static __device__ __forceinline__ void ldsm_x4(uint32_t& r0, uint32_t& r1,
                                               uint32_t& r2, uint32_t& r3,
                                               uint32_t addr) {
    asm volatile("ldmatrix.sync.aligned.m8n8.x4.shared.b16 {%0,%1,%2,%3}, [%4];"
                 : "=r"(r0), "=r"(r1), "=r"(r2), "=r"(r3) : "r"(addr));
}

static __device__ __forceinline__ void ldsm_x4t(uint32_t& r0, uint32_t& r1,
                                                uint32_t& r2, uint32_t& r3,
                                                uint32_t addr) {
    asm volatile("ldmatrix.sync.aligned.m8n8.x4.trans.shared.b16 {%0,%1,%2,%3}, [%4];"
                 : "=r"(r0), "=r"(r1), "=r"(r2), "=r"(r3) : "r"(addr));
}

static __device__ __forceinline__ void mma16816(float* d, const uint32_t* a,
                                                const uint32_t* b) {
    asm volatile(
        "mma.sync.aligned.m16n8k16.row.col.f32.f16.f16.f32 "
        "{%0,%1,%2,%3}, {%4,%5,%6,%7}, {%8,%9}, {%0,%1,%2,%3};"
        : "+f"(d[0]), "+f"(d[1]), "+f"(d[2]), "+f"(d[3])
        : "r"(a[0]), "r"(a[1]), "r"(a[2]), "r"(a[3]), "r"(b[0]), "r"(b[1]));
}

static __device__ __forceinline__ uint32_t pack_f16x2(float lo, float hi) {
    uint32_t d;
    asm("cvt.rn.f16x2.f32 %0, %1, %2;" : "=r"(d) : "f"(hi), "f"(lo));
    return d;
}
static __device__ __forceinline__ float f16lo_f(uint32_t u) {
    return __half2float(__ushort_as_half((unsigned short)(u & 0xffffu)));
}
static __device__ __forceinline__ float f16hi_f(uint32_t u) {
    return __half2float(__ushort_as_half((unsigned short)(u >> 16)));
}

// ---------------------------------------------------------------------------
// fp32 -> fp16 hi/lo split (8 elems/thread)
// ---------------------------------------------------------------------------
__global__ void convert_split_kernel(const float* __restrict__ src,
                                     __half* __restrict__ hi,
                                     __half* __restrict__ lo, int n8) {
    int i = blockIdx.x * blockDim.x + threadIdx.x;
    if (i >= n8) return;
    size_t o = (size_t)i * 8;
#pragma unroll
    for (int half8 = 0; half8 < 2; half8++) {
        float4 x = *(const float4*)(src + o + half8 * 4);
        uint32_t h0 = pack_f16x2(x.x, x.y);
        uint32_t h1 = pack_f16x2(x.z, x.w);
        uint32_t l0 = pack_f16x2(x.x - f16lo_f(h0), x.y - f16hi_f(h0));
        uint32_t l1 = pack_f16x2(x.z - f16lo_f(h1), x.w - f16hi_f(h1));
        *(uint2*)(hi + o + half8 * 4) = make_uint2(h0, h1);
        *(uint2*)(lo + o + half8 * 4) = make_uint2(l0, l1);
    }
}

// fp32 -> single fp16 (8 elems/thread)
__global__ void convert_half_kernel(const float* __restrict__ src,
                                    __half* __restrict__ dst, int n8) {
    int i = blockIdx.x * blockDim.x + threadIdx.x;
    if (i >= n8) return;
    size_t o = (size_t)i * 8;
    float4 x = *(const float4*)(src + o);
    float4 y = *(const float4*)(src + o + 4);
    *(uint4*)(dst + o) = make_uint4(pack_f16x2(x.x, x.y), pack_f16x2(x.z, x.w),
                                    pack_f16x2(y.x, y.y), pack_f16x2(y.z, y.w));
}

// ---------------------------------------------------------------------------
// RoPE table (verified)
// ---------------------------------------------------------------------------
__global__ void rope_table_kernel(const int* __restrict__ pos_ids) {
    int idx = blockIdx.x * blockDim.x + threadIdx.x;
    if (idx >= S_LEN * 64) return;
    int s = idx >> 6;
    int d = idx & 63;
    float expo = (float)(2 * d) * (1.0f / 128.0f);
    float invf = exp2f(-expo * 16.609640474436813f);   // log2(100000)
    float a = (float)((double)pos_ids[s] * (double)invf);
    double ar = (double)a;
    double k  = rint(ar * 0.15915494309189535);
    ar -= k * 6.283185307179586;
    float r = (float)ar;
    g_cos[idx] = cosf(r);
    g_sin[idx] = sinf(r);
}

// ---------------------------------------------------------------------------
// Post-QKV: RoPE on q,k (no scale folding), fp16 hi for all, lo for Q heads.
// ---------------------------------------------------------------------------
__global__ void postqkv_kernel(const float* __restrict__ qkv,
                               __half* __restrict__ hi,
                               __half* __restrict__ lo) {
    int idx = blockIdx.x * blockDim.x + threadIdx.x;
    if (idx >= S_LEN * 48 * 32) return;
    int d    = (idx & 31) * 2;
    int rem  = idx >> 5;
    int head = rem % 48;
    int s    = rem / 48;
    size_t base = (size_t)s * QKV_DIM + head * 128;
    float2 x1 = *(const float2*)(qkv + base + d);
    float2 x2 = *(const float2*)(qkv + base + d + 64);
    if (head < 40) {
        float2 c  = *(const float2*)(g_cos + (s << 6) + d);
        float2 sn = *(const float2*)(g_sin + (s << 6) + d);
        float y1x = x1.x * c.x - x2.x * sn.x;
        float y1y = x1.y * c.y - x2.y * sn.y;
        float y2x = x2.x * c.x + x1.x * sn.x;
        float y2y = x2.y * c.y + x1.y * sn.y;
        x1 = make_float2(y1x, y1y);
        x2 = make_float2(y2x, y2y);
    }
    uint32_t h1 = pack_f16x2(x1.x, x1.y);
    uint32_t h2 = pack_f16x2(x2.x, x2.y);
    *(uint32_t*)(hi + base + d)      = h1;
    *(uint32_t*)(hi + base + d + 64) = h2;
    if (head < 32) {
        *(uint32_t*)(lo + base + d) =
            pack_f16x2(x1.x - f16lo_f(h1), x1.y - f16hi_f(h1));
        *(uint32_t*)(lo + base + d + 64) =
            pack_f16x2(x2.x - f16lo_f(h2), x2.y - f16hi_f(h2));
    }
}

// ---------------------------------------------------------------------------
// fp16-split GEMM via mma.sync (NT): C = (Ah + Al) . B^T, 2 passes.
// CTA 256x128, BK=32, 256 threads (4x2 warps, warp tile 64x64), 4-stage pipe.
// (unchanged from round 7 — verified)
// ---------------------------------------------------------------------------
#define ROWB 80                         // 64B data + 16B pad
#define G_AHI 0
#define G_ALO (256 * ROWB)              // 20480
#define G_B   (2 * 256 * ROWB)          // 40960
#define G_STAGE (G_B + 128 * ROWB)      // 51200
#define GEMM_SMEM (4 * G_STAGE)         // 204800

__global__ __launch_bounds__(256, 1) void gemm_mma_split_kernel(
    const __half* __restrict__ Ahi, const __half* __restrict__ Alo,
    const __half* __restrict__ B,
    float* __restrict__ C, int K, int N)
{
    extern __shared__ char smc[];
    uint32_t sb = smem_u32(smc);
    int tid  = threadIdx.x;
    int wid  = tid >> 5;
    int lane = tid & 31;
    int wm = wid >> 1;     // 0..3
    int wn = wid & 1;      // 0..1
    int m0 = blockIdx.x * 256;
    int n0 = blockIdx.y * 128;

    const size_t rs = (size_t)K * 2;
    const char* pAhi = (const char*)Ahi + (size_t)m0 * rs;
    const char* pAlo = (const char*)Alo + (size_t)m0 * rs;
    const char* pB   = (const char*)B   + (size_t)n0 * rs;

    auto load_chunk = [&](int stage, int c) {
        uint32_t base = sb + stage * G_STAGE;
        size_t kb = (size_t)c * 64;
#pragma unroll
        for (int i = 0; i < 8; i++) {
            int f   = tid + i * 256;
            int arr = f >> 10;
            int rem = f & 1023;
            int row = rem >> 2;
            int seg = (rem & 3) * 16;
            uint32_t so = (uint32_t)(row * ROWB + seg) + (arr ? G_ALO : G_AHI);
            const char* p = (arr ? pAlo : pAhi) + (size_t)row * rs + kb + seg;
            cp16(base + so, p);
        }
#pragma unroll
        for (int i = 0; i < 2; i++) {
            int f   = tid + i * 256;
            int row = f >> 2;
            int seg = (f & 3) * 16;
            cp16(base + G_B + (uint32_t)(row * ROWB + seg),
                 pB + (size_t)row * rs + kb + seg);
        }
        asm volatile("cp.async.commit_group;" ::: "memory");
    };

    float acc[32][4];
#pragma unroll
    for (int t = 0; t < 32; t++)
#pragma unroll
        for (int j = 0; j < 4; j++) acc[t][j] = 0.0f;

    uint32_t a_off  = (uint32_t)((wm * 64 + (lane & 15)) * ROWB + (lane >> 4) * 16);
    uint32_t b_base = (uint32_t)((wn * 64 + (lane & 7) + ((lane >> 4) << 3)) * ROWB
                                 + ((lane >> 3) & 1) * 16);

    int nch = K / 32;                       // 128
    load_chunk(0, 0);
    load_chunk(1, 1);
    load_chunk(2, 2);

    for (int c = 0; c < nch; c++) {
        asm volatile("cp.async.wait_group 2;" ::: "memory");
        __syncthreads();
        if (c + 3 < nch) load_chunk((c + 3) & 3, c + 3);
        else asm volatile("cp.async.commit_group;" ::: "memory");

        uint32_t tb = sb + (c & 3) * G_STAGE;
#pragma unroll
        for (int ks = 0; ks < 2; ks++) {
            uint32_t ko = (uint32_t)(ks * 32);
            uint32_t bh[4][4];
#pragma unroll
            for (int np = 0; np < 4; np++) {
                uint32_t bo = b_base + ko + (uint32_t)(np * 16 * ROWB);
                ldsm_x4(bh[np][0], bh[np][1], bh[np][2], bh[np][3], tb + G_B + bo);
            }
#pragma unroll
            for (int mt = 0; mt < 4; mt++) {
                uint32_t ah[4];
                uint32_t ao = a_off + ko + (uint32_t)(mt * 16 * ROWB);
                ldsm_x4(ah[0], ah[1], ah[2], ah[3], tb + G_AHI + ao);
#pragma unroll
                for (int np = 0; np < 4; np++) {
                    mma16816(acc[mt * 8 + 2 * np],     ah, bh[np]);
                    mma16816(acc[mt * 8 + 2 * np + 1], ah, bh[np] + 2);
                }
            }
#pragma unroll
            for (int mt = 0; mt < 4; mt++) {
                uint32_t al[4];
                uint32_t ao = a_off + ko + (uint32_t)(mt * 16 * ROWB);
                ldsm_x4(al[0], al[1], al[2], al[3], tb + G_ALO + ao);
#pragma unroll
                for (int np = 0; np < 4; np++) {
                    mma16816(acc[mt * 8 + 2 * np],     al, bh[np]);
                    mma16816(acc[mt * 8 + 2 * np + 1], al, bh[np] + 2);
                }
            }
        }
    }

    int mbase = m0 + wm * 64 + (lane >> 2);
    int nbase = n0 + wn * 64 + (lane & 3) * 2;
#pragma unroll
    for (int mt = 0; mt < 4; mt++) {
#pragma unroll
        for (int nt = 0; nt < 8; nt++) {
            float* d = acc[mt * 8 + nt];
            int r = mbase + mt * 16;
            int cc = nbase + nt * 8;
            *(float2*)(C + (size_t)r * N + cc)       = make_float2(d[0], d[1]);
            *(float2*)(C + (size_t)(r + 8) * N + cc) = make_float2(d[2], d[3]);
        }
    }
}

// ---------------------------------------------------------------------------
// Tensor-core flash attention (causal, GQA), fp16 2-pass split,
// double-buffered K/V tiles, Q fragments cached in registers.
// ---------------------------------------------------------------------------
#define AROWB 272
#define A_QH 0
#define A_QL (128 * AROWB)                  // 34816
#define A_KV0 (2 * 128 * AROWB)             // 69632
#define KV_VOFF (64 * AROWB)                // 17408
#define KV_STAGE (128 * AROWB)              // 34816 (K 64 rows + V 64 rows)
#define ATTN_SMEM (A_KV0 + 2 * KV_STAGE)    // 139264

__global__ __launch_bounds__(256, 1) void attn_mma_kernel(
    const __half* __restrict__ qhi, const __half* __restrict__ qlo,
    __half* __restrict__ ohi, __half* __restrict__ olo)
{
    extern __shared__ char smc[];
    uint32_t sb = smem_u32(smc);
    int tid  = threadIdx.x;
    int w    = tid >> 5;
    int lane = tid & 31;
    int h    = blockIdx.y;
    int bx   = (int)gridDim.x - 1 - (int)blockIdx.x;   // heavy tiles first
    int q0   = bx * 128;
    int kvh  = h >> 2;

    auto load_kv = [&](int stage, int kt) {
        int k0 = kt * 64;
        uint32_t kbase = sb + A_KV0 + stage * KV_STAGE;
#pragma unroll
        for (int i = 0; i < 8; i++) {
            int f   = tid + i * 256;
            int arr = f >> 10;          // 0 K, 1 V
            int rem = f & 1023;
            int row = rem >> 4;
            int seg = rem & 15;
            int off = arr ? (HID + NKV * HD) : HID;
            const __half* src =
                qhi + (size_t)(k0 + row) * QKV_DIM + off + kvh * HD + seg * 8;
            cp16(kbase + (arr ? KV_VOFF : 0) + row * AROWB + seg * 16, src);
        }
        asm volatile("cp.async.commit_group;" ::: "memory");
    };

    // Q tile hi+lo, committed together with KV tile 0
#pragma unroll
    for (int i = 0; i < 16; i++) {
        int f   = tid + i * 256;
        int arr = f >> 11;
        int rem = f & 2047;
        int row = rem >> 4;
        int seg = rem & 15;
        const __half* src =
            (arr ? qlo : qhi) + (size_t)(q0 + row) * QKV_DIM + h * HD + seg * 8;
        cp16(sb + (arr ? A_QL : A_QH) + row * AROWB + seg * 16, src);
    }
    load_kv(0, 0);     // commit #1 (Q + KV0)
    load_kv(1, 1);     // commit #2 (KV1)   [nkt >= 2 always]

    // Wait Q + KV0 resident (KV1 stays in flight)
    asm volatile("cp.async.wait_group 1;" ::: "memory");
    __syncthreads();

    // ---- cache Q fragments in registers (loaded ONCE)
    uint32_t qfh[8][4], qfl[8][4];
#pragma unroll
    for (int ks = 0; ks < 8; ks++) {
        uint32_t ao = (uint32_t)((16 * w + (lane & 15)) * AROWB
                                 + ks * 32 + (lane >> 4) * 16);
        ldsm_x4(qfh[ks][0], qfh[ks][1], qfh[ks][2], qfh[ks][3], sb + A_QH + ao);
        ldsm_x4(qfl[ks][0], qfl[ks][1], qfl[ks][2], qfl[ks][3], sb + A_QL + ao);
    }

    float oacc[16][4];
#pragma unroll
    for (int t = 0; t < 16; t++)
#pragma unroll
        for (int j = 0; j < 4; j++) oacc[t][j] = 0.0f;
    float mrow[2] = {-1e30f, -1e30f};
    float lrow[2] = {0.0f, 0.0f};

    int wmin = q0 + 16 * w;
    int nkt  = 2 * (bx + 1);

    for (int kt = 0; kt < nkt; kt++) {
        int buf = kt & 1;
        int k0  = kt * 64;
        // invariant: tile kt resident; tile kt+1 in flight (if it exists)

        if (k0 <= wmin + 15) {
            uint32_t kvb = sb + A_KV0 + buf * KV_STAGE;
            float sacc[8][4];
#pragma unroll
            for (int t = 0; t < 8; t++)
#pragma unroll
                for (int j = 0; j < 4; j++) sacc[t][j] = 0.0f;

            // ---- S = Q . K^T (2 passes, Q from registers)
#pragma unroll
            for (int ks = 0; ks < 8; ks++) {
#pragma unroll
                for (int np = 0; np < 4; np++) {
                    uint32_t kh_[4];
                    uint32_t bo = (uint32_t)((np * 16 + (lane & 7)
                                              + ((lane >> 4) << 3)) * AROWB
                                             + ks * 32 + ((lane >> 3) & 1) * 16);
                    ldsm_x4(kh_[0], kh_[1], kh_[2], kh_[3], kvb + bo);
                    mma16816(sacc[2 * np],     qfh[ks], kh_);
                    mma16816(sacc[2 * np],     qfl[ks], kh_);
                    mma16816(sacc[2 * np + 1], qfh[ks], kh_ + 2);
                    mma16816(sacc[2 * np + 1], qfl[ks], kh_ + 2);
                }
            }

            // ---- scale
#pragma unroll
            for (int nt = 0; nt < 8; nt++)
#pragma unroll
                for (int j = 0; j < 4; j++) sacc[nt][j] *= SCALE;

            // ---- causal mask
            int r1 = wmin + (lane >> 2);
            if (k0 + 63 > wmin) {
#pragma unroll
                for (int nt = 0; nt < 8; nt++) {
                    int c0 = k0 + nt * 8 + (lane & 3) * 2;
                    if (c0     > r1)     sacc[nt][0] = -1e30f;
                    if (c0 + 1 > r1)     sacc[nt][1] = -1e30f;
                    if (c0     > r1 + 8) sacc[nt][2] = -1e30f;
                    if (c0 + 1 > r1 + 8) sacc[nt][3] = -1e30f;
                }
            }

            // ---- online softmax
#pragma unroll
            for (int hf = 0; hf < 2; hf++) {
                float mx = -1e30f;
#pragma unroll
                for (int nt = 0; nt < 8; nt++)
                    mx = fmaxf(mx, fmaxf(sacc[nt][2 * hf], sacc[nt][2 * hf + 1]));
                mx = fmaxf(mx, __shfl_xor_sync(0xffffffffu, mx, 1));
                mx = fmaxf(mx, __shfl_xor_sync(0xffffffffu, mx, 2));
                float mn   = fmaxf(mrow[hf], mx);
                float corr = __expf(mrow[hf] - mn);
                mrow[hf] = mn;
                float sum = 0.0f;
#pragma unroll
                for (int nt = 0; nt < 8; nt++) {
                    float p0 = __expf(sacc[nt][2 * hf]     - mn);
                    float p1 = __expf(sacc[nt][2 * hf + 1] - mn);
                    sacc[nt][2 * hf]     = p0;
                    sacc[nt][2 * hf + 1] = p1;
                    sum += p0 + p1;
                }
                sum += __shfl_xor_sync(0xffffffffu, sum, 1);
                sum += __shfl_xor_sync(0xffffffffu, sum, 2);
                lrow[hf] = lrow[hf] * corr + sum;
#pragma unroll
                for (int nt = 0; nt < 16; nt++) {
                    oacc[nt][2 * hf]     *= corr;
                    oacc[nt][2 * hf + 1] *= corr;
                }
            }

            // ---- O += P . V (2 passes)
#pragma unroll
            for (int j = 0; j < 4; j++) {
                uint32_t ph_[4], pl_[4];
                ph_[0] = pack_f16x2(sacc[2 * j][0],     sacc[2 * j][1]);
                ph_[1] = pack_f16x2(sacc[2 * j][2],     sacc[2 * j][3]);
                ph_[2] = pack_f16x2(sacc[2 * j + 1][0], sacc[2 * j + 1][1]);
                ph_[3] = pack_f16x2(sacc[2 * j + 1][2], sacc[2 * j + 1][3]);
                pl_[0] = pack_f16x2(sacc[2 * j][0]     - f16lo_f(ph_[0]),
                                    sacc[2 * j][1]     - f16hi_f(ph_[0]));
                pl_[1] = pack_f16x2(sacc[2 * j][2]     - f16lo_f(ph_[1]),
                                    sacc[2 * j][3]     - f16hi_f(ph_[1]));
                pl_[2] = pack_f16x2(sacc[2 * j + 1][0] - f16lo_f(ph_[2]),
                                    sacc[2 * j + 1][1] - f16hi_f(ph_[2]));
                pl_[3] = pack_f16x2(sacc[2 * j + 1][2] - f16lo_f(ph_[3]),
                                    sacc[2 * j + 1][3] - f16hi_f(ph_[3]));
#pragma unroll
                for (int np = 0; np < 8; np++) {
                    uint32_t vh_[4];
                    uint32_t vo = (uint32_t)((j * 16 + (lane & 7)
                                              + ((lane >> 3) & 1) * 8) * AROWB
                                             + (np * 16 + ((lane >> 4) << 3)) * 2);
                    ldsm_x4t(vh_[0], vh_[1], vh_[2], vh_[3], kvb + KV_VOFF + vo);
                    mma16816(oacc[2 * np],     ph_, vh_);
                    mma16816(oacc[2 * np],     pl_, vh_);
                    mma16816(oacc[2 * np + 1], ph_, vh_ + 2);
                    mma16816(oacc[2 * np + 1], pl_, vh_ + 2);
                }
            }
        }
        __syncthreads();   // all warps done reading buf

        if (kt + 2 < nkt) load_kv(buf, kt + 2);
        if (kt + 1 < nkt) {
            asm volatile("cp.async.wait_group %0;" :: "n"(1) : "memory");
            // NOTE: if kt+2 was not loaded, one group may remain uncommitted;
            // handle both cases:
        }
        if (kt + 1 < nkt && kt + 2 >= nkt) {
            asm volatile("cp.async.wait_group 0;" ::: "memory");
        }
        if (kt + 1 < nkt) __syncthreads();   // tile kt+1 visible to all
    }

    // ---- epilogue
    float inv0 = 1.0f / lrow[0];
    float inv1 = 1.0f / lrow[1];
    int r1 = q0 + 16 * w + (lane >> 2);
    size_t base1 = (size_t)r1 * HID + h * HD + (lane & 3) * 2;
    size_t base2 = base1 + (size_t)8 * HID;
#pragma unroll
    for (int nt = 0; nt < 16; nt++) {
        float v0 = oacc[nt][0] * inv0;
        float v1 = oacc[nt][1] * inv0;
        uint32_t hiw = pack_f16x2(v0, v1);
        uint32_t low = pack_f16x2(v0 - f16lo_f(hiw), v1 - f16hi_f(hiw));
        *(uint32_t*)(ohi + base1 + nt * 8) = hiw;
        *(uint32_t*)(olo + base1 + nt * 8) = low;
        float v2 = oacc[nt][2] * inv1;
        float v3 = oacc[nt][3] * inv1;
        uint32_t hiw2 = pack_f16x2(v2, v3);
        uint32_t low2 = pack_f16x2(v2 - f16lo_f(hiw2), v3 - f16hi_f(hiw2));
        *(uint32_t*)(ohi + base2 + nt * 8) = hiw2;
        *(uint32_t*)(olo + base2 + nt * 8) = low2;
    }
}

// ---------------------------------------------------------------------------
// Launch
// ---------------------------------------------------------------------------
extern "C" void kernel_launch(void* const* d_in, const int* in_sizes, int n_in,
                              void* d_out, int out_size)
{
    (void)in_sizes; (void)n_in; (void)out_size;
    const float* x     = (const float*)d_in[0];
    const int*   pos   = (const int*)d_in[1];
    const float* w_qkv = (const float*)d_in[2];
    const float* w_o   = (const float*)d_in[3];
    float*       out   = (float*)d_out;

    void *p_qkv, *p_xh, *p_xl, *p_wq, *p_wo, *p_sph, *p_spl, *p_ah, *p_al;
    cudaGetSymbolAddress(&p_qkv, g_qkv);
    cudaGetSymbolAddress(&p_xh, g_x_hi);
    cudaGetSymbolAddress(&p_xl, g_x_lo);
    cudaGetSymbolAddress(&p_wq, g_wqkv);
    cudaGetSymbolAddress(&p_wo, g_wo);
    cudaGetSymbolAddress(&p_sph, g_qkvsp_hi);
    cudaGetSymbolAddress(&p_spl, g_qkvsp_lo);
    cudaGetSymbolAddress(&p_ah, g_attn_hi);
    cudaGetSymbolAddress(&p_al, g_attn_lo);
    float* qkv = (float*)p_qkv;

    cudaFuncSetAttribute(gemm_mma_split_kernel,
                         cudaFuncAttributeMaxDynamicSharedMemorySize, GEMM_SMEM);
    cudaFuncSetAttribute(attn_mma_kernel,
                         cudaFuncAttributeMaxDynamicSharedMemorySize, ATTN_SMEM);

    // RoPE table
    rope_table_kernel<<<(S_LEN * 64 + 255) / 256, 256>>>(pos);

    // Converts
    {
        int n1 = S_LEN * HID / 8;
        convert_split_kernel<<<(n1 + 255) / 256, 256>>>(
            x, (__half*)p_xh, (__half*)p_xl, n1);
        int n2 = QKV_DIM * HID / 8;
        convert_half_kernel<<<(n2 + 255) / 256, 256>>>(w_qkv, (__half*)p_wq, n2);
        int n3 = HID * HID / 8;
        convert_half_kernel<<<(n3 + 255) / 256, 256>>>(w_o, (__half*)p_wo, n3);
    }

    // QKV projection
    gemm_mma_split_kernel<<<dim3(S_LEN / 256, QKV_DIM / 128), 256, GEMM_SMEM>>>(
        (const __half*)p_xh, (const __half*)p_xl, (const __half*)p_wq,
        qkv, HID, QKV_DIM);

    // RoPE + split qkv
    postqkv_kernel<<<(S_LEN * 48 * 32 + 255) / 256, 256>>>(
        qkv, (__half*)p_sph, (__half*)p_spl);

    // Tensor-core flash attention
    attn_mma_kernel<<<dim3(S_LEN / 128, NH), 256, ATTN_SMEM>>>(
        (const __half*)p_sph, (const __half*)p_spl,
        (__half*)p_ah, (__half*)p_al);

    // Output projection
    gemm_mma_split_kernel<<<dim3(S_LEN / 256, HID / 128), 256, GEMM_SMEM>>>(
        (const __half*)p_ah, (const __half*)p_al, (const __half*)p_wo,
        out, HID, HID);
}

// round 9
// speedup vs baseline: 4.6347x; 1.2014x over previous
#include <cuda_runtime.h>
#include <cuda_fp16.h>
#include <math.h>
#include <stdint.h>

// Problem constants
#define S_LEN   2048
#define HID     4096
#define NH      32
#define NKV     8
#define HD      128
#define QKV_DIM 6144   // NH*HD + 2*NKV*HD
#define GROUPS  4
#define SCALE   0.08838834764831845f   // 1/sqrt(128)

// ---------------------------------------------------------------------------
// Device scratch (no allocations allowed)
// ---------------------------------------------------------------------------
__device__ float g_qkv[S_LEN * QKV_DIM];   // fp32 QKV GEMM out
__device__ float g_cos[S_LEN * 64];
__device__ float g_sin[S_LEN * 64];

__device__ __align__(128) __half g_x_hi[S_LEN * HID];
__device__ __align__(128) __half g_x_lo[S_LEN * HID];
__device__ __align__(128) __half g_wqkv[QKV_DIM * HID];
__device__ __align__(128) __half g_wo[HID * HID];
__device__ __align__(128) __half g_qkvsp_hi[S_LEN * QKV_DIM];
__device__ __align__(128) __half g_qkvsp_lo[S_LEN * QKV_DIM];   // lo: Q heads only
__device__ __align__(128) __half g_attn[S_LEN * HID];           // single fp16

// ---------------------------------------------------------------------------
// Helpers
// ---------------------------------------------------------------------------
static __device__ __forceinline__ uint32_t smem_u32(const void* p) {
    uint32_t a;
    asm("{ .reg .u64 t; cvta.to.shared.u64 t, %1; cvt.u32.u64 %0, t; }"
        : "=r"(a) : "l"(p));
    return a;
}

static __device__ __forceinline__ void cp16(uint32_t dst, const void* src) {
    asm volatile("cp.async.cg.shared.global [%0], [%1], 16;"
                 :: "r"(dst), "l"(src));
}

static __device__ __forceinline__ void ldsm_x4(uint32_t& r0, uint32_t& r1,
                                               uint32_t& r2, uint32_t& r3,
                                               uint32_t addr) {
    asm volatile("ldmatrix.sync.aligned.m8n8.x4.shared.b16 {%0,%1,%2,%3}, [%4];"
                 : "=r"(r0), "=r"(r1), "=r"(r2), "=r"(r3) : "r"(addr));
}

static __device__ __forceinline__ void ldsm_x4t(uint32_t& r0, uint32_t& r1,
                                                uint32_t& r2, uint32_t& r3,
                                                uint32_t addr) {
    asm volatile("ldmatrix.sync.aligned.m8n8.x4.trans.shared.b16 {%0,%1,%2,%3}, [%4];"
                 : "=r"(r0), "=r"(r1), "=r"(r2), "=r"(r3) : "r"(addr));
}

static __device__ __forceinline__ void mma16816(float* d, const uint32_t* a,
                                                const uint32_t* b) {
    asm volatile(
        "mma.sync.aligned.m16n8k16.row.col.f32.f16.f16.f32 "
        "{%0,%1,%2,%3}, {%4,%5,%6,%7}, {%8,%9}, {%0,%1,%2,%3};"
        : "+f"(d[0]), "+f"(d[1]), "+f"(d[2]), "+f"(d[3])
        : "r"(a[0]), "r"(a[1]), "r"(a[2]), "r"(a[3]), "r"(b[0]), "r"(b[1]));
}

static __device__ __forceinline__ uint32_t pack_f16x2(float lo, float hi) {
    uint32_t d;
    asm("cvt.rn.f16x2.f32 %0, %1, %2;" : "=r"(d) : "f"(hi), "f"(lo));
    return d;
}
static __device__ __forceinline__ float f16lo_f(uint32_t u) {
    return __half2float(__ushort_as_half((unsigned short)(u & 0xffffu)));
}
static __device__ __forceinline__ float f16hi_f(uint32_t u) {
    return __half2float(__ushort_as_half((unsigned short)(u >> 16)));
}

// ---------------------------------------------------------------------------
// fp32 -> fp16 hi/lo split (8 elems/thread)
// ---------------------------------------------------------------------------
__global__ void convert_split_kernel(const float* __restrict__ src,
                                     __half* __restrict__ hi,
                                     __half* __restrict__ lo, int n8) {
    int i = blockIdx.x * blockDim.x + threadIdx.x;
    if (i >= n8) return;
    size_t o = (size_t)i * 8;
#pragma unroll
    for (int half8 = 0; half8 < 2; half8++) {
        float4 x = *(const float4*)(src + o + half8 * 4);
        uint32_t h0 = pack_f16x2(x.x, x.y);
        uint32_t h1 = pack_f16x2(x.z, x.w);
        uint32_t l0 = pack_f16x2(x.x - f16lo_f(h0), x.y - f16hi_f(h0));
        uint32_t l1 = pack_f16x2(x.z - f16lo_f(h1), x.w - f16hi_f(h1));
        *(uint2*)(hi + o + half8 * 4) = make_uint2(h0, h1);
        *(uint2*)(lo + o + half8 * 4) = make_uint2(l0, l1);
    }
}

// fp32 -> single fp16 (8 elems/thread)
__global__ void convert_half_kernel(const float* __restrict__ src,
                                    __half* __restrict__ dst, int n8) {
    int i = blockIdx.x * blockDim.x + threadIdx.x;
    if (i >= n8) return;
    size_t o = (size_t)i * 8;
    float4 x = *(const float4*)(src + o);
    float4 y = *(const float4*)(src + o + 4);
    *(uint4*)(dst + o) = make_uint4(pack_f16x2(x.x, x.y), pack_f16x2(x.z, x.w),
                                    pack_f16x2(y.x, y.y), pack_f16x2(y.z, y.w));
}

// ---------------------------------------------------------------------------
// RoPE table (verified)
// ---------------------------------------------------------------------------
__global__ void rope_table_kernel(const int* __restrict__ pos_ids) {
    int idx = blockIdx.x * blockDim.x + threadIdx.x;
    if (idx >= S_LEN * 64) return;
    int s = idx >> 6;
    int d = idx & 63;
    float expo = (float)(2 * d) * (1.0f / 128.0f);
    float invf = exp2f(-expo * 16.609640474436813f);   // log2(100000)
    float a = (float)((double)pos_ids[s] * (double)invf);
    double ar = (double)a;
    double k  = rint(ar * 0.15915494309189535);
    ar -= k * 6.283185307179586;
    float r = (float)ar;
    g_cos[idx] = cosf(r);
    g_sin[idx] = sinf(r);
}

// ---------------------------------------------------------------------------
// Post-QKV: RoPE on q,k (no scale folding), fp16 hi for all, lo for Q heads.
// ---------------------------------------------------------------------------
__global__ void postqkv_kernel(const float* __restrict__ qkv,
                               __half* __restrict__ hi,
                               __half* __restrict__ lo) {
    int idx = blockIdx.x * blockDim.x + threadIdx.x;
    if (idx >= S_LEN * 48 * 32) return;
    int d    = (idx & 31) * 2;
    int rem  = idx >> 5;
    int head = rem % 48;
    int s    = rem / 48;
    size_t base = (size_t)s * QKV_DIM + head * 128;
    float2 x1 = *(const float2*)(qkv + base + d);
    float2 x2 = *(const float2*)(qkv + base + d + 64);
    if (head < 40) {
        float2 c  = *(const float2*)(g_cos + (s << 6) + d);
        float2 sn = *(const float2*)(g_sin + (s << 6) + d);
        float y1x = x1.x * c.x - x2.x * sn.x;
        float y1y = x1.y * c.y - x2.y * sn.y;
        float y2x = x2.x * c.x + x1.x * sn.x;
        float y2y = x2.y * c.y + x1.y * sn.y;
        x1 = make_float2(y1x, y1y);
        x2 = make_float2(y2x, y2y);
    }
    uint32_t h1 = pack_f16x2(x1.x, x1.y);
    uint32_t h2 = pack_f16x2(x2.x, x2.y);
    *(uint32_t*)(hi + base + d)      = h1;
    *(uint32_t*)(hi + base + d + 64) = h2;
    if (head < 32) {
        *(uint32_t*)(lo + base + d) =
            pack_f16x2(x1.x - f16lo_f(h1), x1.y - f16hi_f(h1));
        *(uint32_t*)(lo + base + d + 64) =
            pack_f16x2(x2.x - f16lo_f(h2), x2.y - f16hi_f(h2));
    }
}

// ---------------------------------------------------------------------------
// fp16-split GEMM via mma.sync (NT): C = (Ah + Al) . B^T, 2 passes.  [QKV]
// CTA 256x128, BK=32, 256 threads (4x2 warps, warp tile 64x64), 4-stage pipe.
// ---------------------------------------------------------------------------
#define ROWB 80                         // 64B data + 16B pad
#define G_AHI 0
#define G_ALO (256 * ROWB)              // 20480
#define G_B   (2 * 256 * ROWB)          // 40960
#define G_STAGE (G_B + 128 * ROWB)      // 51200
#define GEMM_SMEM (4 * G_STAGE)         // 204800

__global__ __launch_bounds__(256, 1) void gemm_mma_split_kernel(
    const __half* __restrict__ Ahi, const __half* __restrict__ Alo,
    const __half* __restrict__ B,
    float* __restrict__ C, int K, int N)
{
    extern __shared__ char smc[];
    uint32_t sb = smem_u32(smc);
    int tid  = threadIdx.x;
    int wid  = tid >> 5;
    int lane = tid & 31;
    int wm = wid >> 1;     // 0..3
    int wn = wid & 1;      // 0..1
    int m0 = blockIdx.x * 256;
    int n0 = blockIdx.y * 128;

    const size_t rs = (size_t)K * 2;
    const char* pAhi = (const char*)Ahi + (size_t)m0 * rs;
    const char* pAlo = (const char*)Alo + (size_t)m0 * rs;
    const char* pB   = (const char*)B   + (size_t)n0 * rs;

    auto load_chunk = [&](int stage, int c) {
        uint32_t base = sb + stage * G_STAGE;
        size_t kb = (size_t)c * 64;
#pragma unroll
        for (int i = 0; i < 8; i++) {
            int f   = tid + i * 256;
            int arr = f >> 10;
            int rem = f & 1023;
            int row = rem >> 2;
            int seg = (rem & 3) * 16;
            uint32_t so = (uint32_t)(row * ROWB + seg) + (arr ? G_ALO : G_AHI);
            const char* p = (arr ? pAlo : pAhi) + (size_t)row * rs + kb + seg;
            cp16(base + so, p);
        }
#pragma unroll
        for (int i = 0; i < 2; i++) {
            int f   = tid + i * 256;
            int row = f >> 2;
            int seg = (f & 3) * 16;
            cp16(base + G_B + (uint32_t)(row * ROWB + seg),
                 pB + (size_t)row * rs + kb + seg);
        }
        asm volatile("cp.async.commit_group;" ::: "memory");
    };

    float acc[32][4];
#pragma unroll
    for (int t = 0; t < 32; t++)
#pragma unroll
        for (int j = 0; j < 4; j++) acc[t][j] = 0.0f;

    uint32_t a_off  = (uint32_t)((wm * 64 + (lane & 15)) * ROWB + (lane >> 4) * 16);
    uint32_t b_base = (uint32_t)((wn * 64 + (lane & 7) + ((lane >> 4) << 3)) * ROWB
                                 + ((lane >> 3) & 1) * 16);

    int nch = K / 32;
    load_chunk(0, 0);
    load_chunk(1, 1);
    load_chunk(2, 2);

    for (int c = 0; c < nch; c++) {
        asm volatile("cp.async.wait_group 2;" ::: "memory");
        __syncthreads();
        if (c + 3 < nch) load_chunk((c + 3) & 3, c + 3);
        else asm volatile("cp.async.commit_group;" ::: "memory");

        uint32_t tb = sb + (c & 3) * G_STAGE;
#pragma unroll
        for (int ks = 0; ks < 2; ks++) {
            uint32_t ko = (uint32_t)(ks * 32);
            uint32_t bh[4][4];
#pragma unroll
            for (int np = 0; np < 4; np++) {
                uint32_t bo = b_base + ko + (uint32_t)(np * 16 * ROWB);
                ldsm_x4(bh[np][0], bh[np][1], bh[np][2], bh[np][3], tb + G_B + bo);
            }
#pragma unroll
            for (int mt = 0; mt < 4; mt++) {
                uint32_t ah[4];
                uint32_t ao = a_off + ko + (uint32_t)(mt * 16 * ROWB);
                ldsm_x4(ah[0], ah[1], ah[2], ah[3], tb + G_AHI + ao);
#pragma unroll
                for (int np = 0; np < 4; np++) {
                    mma16816(acc[mt * 8 + 2 * np],     ah, bh[np]);
                    mma16816(acc[mt * 8 + 2 * np + 1], ah, bh[np] + 2);
                }
            }
#pragma unroll
            for (int mt = 0; mt < 4; mt++) {
                uint32_t al[4];
                uint32_t ao = a_off + ko + (uint32_t)(mt * 16 * ROWB);
                ldsm_x4(al[0], al[1], al[2], al[3], tb + G_ALO + ao);
#pragma unroll
                for (int np = 0; np < 4; np++) {
                    mma16816(acc[mt * 8 + 2 * np],     al, bh[np]);
                    mma16816(acc[mt * 8 + 2 * np + 1], al, bh[np] + 2);
                }
            }
        }
    }

    int mbase = m0 + wm * 64 + (lane >> 2);
    int nbase = n0 + wn * 64 + (lane & 3) * 2;
#pragma unroll
    for (int mt = 0; mt < 4; mt++) {
#pragma unroll
        for (int nt = 0; nt < 8; nt++) {
            float* d = acc[mt * 8 + nt];
            int r = mbase + mt * 16;
            int cc = nbase + nt * 8;
            *(float2*)(C + (size_t)r * N + cc)       = make_float2(d[0], d[1]);
            *(float2*)(C + (size_t)(r + 8) * N + cc) = make_float2(d[2], d[3]);
        }
    }
}

// ---------------------------------------------------------------------------
// 1-pass fp16 GEMM via mma.sync (NT): C = A . B^T.   [O-projection]
// Same tiling, 4-stage pipe, smaller stage (no A-lo).
// ---------------------------------------------------------------------------
#define H_A 0
#define H_B (256 * ROWB)                // 20480
#define H_STAGE (H_B + 128 * ROWB)      // 30720
#define GEMM1_SMEM (4 * H_STAGE)        // 122880

__global__ __launch_bounds__(256, 1) void gemm_mma_kernel(
    const __half* __restrict__ A, const __half* __restrict__ B,
    float* __restrict__ C, int K, int N)
{
    extern __shared__ char smc[];
    uint32_t sb = smem_u32(smc);
    int tid  = threadIdx.x;
    int wid  = tid >> 5;
    int lane = tid & 31;
    int wm = wid >> 1;
    int wn = wid & 1;
    int m0 = blockIdx.x * 256;
    int n0 = blockIdx.y * 128;

    const size_t rs = (size_t)K * 2;
    const char* pA = (const char*)A + (size_t)m0 * rs;
    const char* pB = (const char*)B + (size_t)n0 * rs;

    auto load_chunk = [&](int stage, int c) {
        uint32_t base = sb + stage * H_STAGE;
        size_t kb = (size_t)c * 64;
#pragma unroll
        for (int i = 0; i < 4; i++) {
            int f   = tid + i * 256;
            int row = f >> 2;
            int seg = (f & 3) * 16;
            cp16(base + H_A + (uint32_t)(row * ROWB + seg),
                 pA + (size_t)row * rs + kb + seg);
        }
#pragma unroll
        for (int i = 0; i < 2; i++) {
            int f   = tid + i * 256;
            int row = f >> 2;
            int seg = (f & 3) * 16;
            cp16(base + H_B + (uint32_t)(row * ROWB + seg),
                 pB + (size_t)row * rs + kb + seg);
        }
        asm volatile("cp.async.commit_group;" ::: "memory");
    };

    float acc[32][4];
#pragma unroll
    for (int t = 0; t < 32; t++)
#pragma unroll
        for (int j = 0; j < 4; j++) acc[t][j] = 0.0f;

    uint32_t a_off  = (uint32_t)((wm * 64 + (lane & 15)) * ROWB + (lane >> 4) * 16);
    uint32_t b_base = (uint32_t)((wn * 64 + (lane & 7) + ((lane >> 4) << 3)) * ROWB
                                 + ((lane >> 3) & 1) * 16);

    int nch = K / 32;
    load_chunk(0, 0);
    load_chunk(1, 1);
    load_chunk(2, 2);

    for (int c = 0; c < nch; c++) {
        asm volatile("cp.async.wait_group 2;" ::: "memory");
        __syncthreads();
        if (c + 3 < nch) load_chunk((c + 3) & 3, c + 3);
        else asm volatile("cp.async.commit_group;" ::: "memory");

        uint32_t tb = sb + (c & 3) * H_STAGE;
#pragma unroll
        for (int ks = 0; ks < 2; ks++) {
            uint32_t ko = (uint32_t)(ks * 32);
            uint32_t bh[4][4];
#pragma unroll
            for (int np = 0; np < 4; np++) {
                uint32_t bo = b_base + ko + (uint32_t)(np * 16 * ROWB);
                ldsm_x4(bh[np][0], bh[np][1], bh[np][2], bh[np][3], tb + H_B + bo);
            }
#pragma unroll
            for (int mt = 0; mt < 4; mt++) {
                uint32_t ah[4];
                uint32_t ao = a_off + ko + (uint32_t)(mt * 16 * ROWB);
                ldsm_x4(ah[0], ah[1], ah[2], ah[3], tb + H_A + ao);
#pragma unroll
                for (int np = 0; np < 4; np++) {
                    mma16816(acc[mt * 8 + 2 * np],     ah, bh[np]);
                    mma16816(acc[mt * 8 + 2 * np + 1], ah, bh[np] + 2);
                }
            }
        }
    }

    int mbase = m0 + wm * 64 + (lane >> 2);
    int nbase = n0 + wn * 64 + (lane & 3) * 2;
#pragma unroll
    for (int mt = 0; mt < 4; mt++) {
#pragma unroll
        for (int nt = 0; nt < 8; nt++) {
            float* d = acc[mt * 8 + nt];
            int r = mbase + mt * 16;
            int cc = nbase + nt * 8;
            *(float2*)(C + (size_t)r * N + cc)       = make_float2(d[0], d[1]);
            *(float2*)(C + (size_t)(r + 8) * N + cc) = make_float2(d[2], d[3]);
        }
    }
}

// ---------------------------------------------------------------------------
// Tensor-core flash attention (causal, GQA).
// QK^T: 2-pass (Q hi+lo, K single).  PV: 1-pass (P single fp16, V single).
// Double-buffered K/V, Q fragments register-cached.  Output: single fp16.
// ---------------------------------------------------------------------------
#define AROWB 272
#define A_QH 0
#define A_QL (128 * AROWB)                  // 34816
#define A_KV0 (2 * 128 * AROWB)             // 69632
#define KV_VOFF (64 * AROWB)                // 17408
#define KV_STAGE (128 * AROWB)              // 34816
#define ATTN_SMEM (A_KV0 + 2 * KV_STAGE)    // 139264

__global__ __launch_bounds__(256, 1) void attn_mma_kernel(
    const __half* __restrict__ qhi, const __half* __restrict__ qlo,
    __half* __restrict__ o)
{
    extern __shared__ char smc[];
    uint32_t sb = smem_u32(smc);
    int tid  = threadIdx.x;
    int w    = tid >> 5;
    int lane = tid & 31;
    int h    = blockIdx.y;
    int bx   = (int)gridDim.x - 1 - (int)blockIdx.x;   // heavy tiles first
    int q0   = bx * 128;
    int kvh  = h >> 2;

    auto load_kv = [&](int stage, int kt) {
        int k0 = kt * 64;
        uint32_t kbase = sb + A_KV0 + stage * KV_STAGE;
#pragma unroll
        for (int i = 0; i < 8; i++) {
            int f   = tid + i * 256;
            int arr = f >> 10;          // 0 K, 1 V
            int rem = f & 1023;
            int row = rem >> 4;
            int seg = rem & 15;
            int off = arr ? (HID + NKV * HD) : HID;
            const __half* src =
                qhi + (size_t)(k0 + row) * QKV_DIM + off + kvh * HD + seg * 8;
            cp16(kbase + (arr ? KV_VOFF : 0) + row * AROWB + seg * 16, src);
        }
        asm volatile("cp.async.commit_group;" ::: "memory");
    };

    // Q tile hi+lo, committed together with KV tile 0
#pragma unroll
    for (int i = 0; i < 16; i++) {
        int f   = tid + i * 256;
        int arr = f >> 11;
        int rem = f & 2047;
        int row = rem >> 4;
        int seg = rem & 15;
        const __half* src =
            (arr ? qlo : qhi) + (size_t)(q0 + row) * QKV_DIM + h * HD + seg * 8;
        cp16(sb + (arr ? A_QL : A_QH) + row * AROWB + seg * 16, src);
    }
    load_kv(0, 0);     // commit #1 (Q + KV0)
    load_kv(1, 1);     // commit #2 (KV1)   [nkt >= 2 always]

    asm volatile("cp.async.wait_group 1;" ::: "memory");
    __syncthreads();

    // cache Q fragments in registers (loaded once)
    uint32_t qfh[8][4], qfl[8][4];
#pragma unroll
    for (int ks = 0; ks < 8; ks++) {
        uint32_t ao = (uint32_t)((16 * w + (lane & 15)) * AROWB
                                 + ks * 32 + (lane >> 4) * 16);
        ldsm_x4(qfh[ks][0], qfh[ks][1], qfh[ks][2], qfh[ks][3], sb + A_QH + ao);
        ldsm_x4(qfl[ks][0], qfl[ks][1], qfl[ks][2], qfl[ks][3], sb + A_QL + ao);
    }

    float oacc[16][4];
#pragma unroll
    for (int t = 0; t < 16; t++)
#pragma unroll
        for (int j = 0; j < 4; j++) oacc[t][j] = 0.0f;
    float mrow[2] = {-1e30f, -1e30f};
    float lrow[2] = {0.0f, 0.0f};

    int wmin = q0 + 16 * w;
    int nkt  = 2 * (bx + 1);

    for (int kt = 0; kt < nkt; kt++) {
        int buf = kt & 1;
        int k0  = kt * 64;

        if (k0 <= wmin + 15) {
            uint32_t kvb = sb + A_KV0 + buf * KV_STAGE;
            float sacc[8][4];
#pragma unroll
            for (int t = 0; t < 8; t++)
#pragma unroll
                for (int j = 0; j < 4; j++) sacc[t][j] = 0.0f;

            // ---- S = Q . K^T (2 passes, Q from registers)
#pragma unroll
            for (int ks = 0; ks < 8; ks++) {
#pragma unroll
                for (int np = 0; np < 4; np++) {
                    uint32_t kh_[4];
                    uint32_t bo = (uint32_t)((np * 16 + (lane & 7)
                                              + ((lane >> 4) << 3)) * AROWB
                                             + ks * 32 + ((lane >> 3) & 1) * 16);
                    ldsm_x4(kh_[0], kh_[1], kh_[2], kh_[3], kvb + bo);
                    mma16816(sacc[2 * np],     qfh[ks], kh_);
                    mma16816(sacc[2 * np],     qfl[ks], kh_);
                    mma16816(sacc[2 * np + 1], qfh[ks], kh_ + 2);
                    mma16816(sacc[2 * np + 1], qfl[ks], kh_ + 2);
                }
            }

            // ---- scale
#pragma unroll
            for (int nt = 0; nt < 8; nt++)
#pragma unroll
                for (int j = 0; j < 4; j++) sacc[nt][j] *= SCALE;

            // ---- causal mask
            int r1 = wmin + (lane >> 2);
            if (k0 + 63 > wmin) {
#pragma unroll
                for (int nt = 0; nt < 8; nt++) {
                    int c0 = k0 + nt * 8 + (lane & 3) * 2;
                    if (c0     > r1)     sacc[nt][0] = -1e30f;
                    if (c0 + 1 > r1)     sacc[nt][1] = -1e30f;
                    if (c0     > r1 + 8) sacc[nt][2] = -1e30f;
                    if (c0 + 1 > r1 + 8) sacc[nt][3] = -1e30f;
                }
            }

            // ---- online softmax
#pragma unroll
            for (int hf = 0; hf < 2; hf++) {
                float mx = -1e30f;
#pragma unroll
                for (int nt = 0; nt < 8; nt++)
                    mx = fmaxf(mx, fmaxf(sacc[nt][2 * hf], sacc[nt][2 * hf + 1]));
                mx = fmaxf(mx, __shfl_xor_sync(0xffffffffu, mx, 1));
                mx = fmaxf(mx, __shfl_xor_sync(0xffffffffu, mx, 2));
                float mn   = fmaxf(mrow[hf], mx);
                float corr = __expf(mrow[hf] - mn);
                mrow[hf] = mn;
                float sum = 0.0f;
#pragma unroll
                for (int nt = 0; nt < 8; nt++) {
                    float p0 = __expf(sacc[nt][2 * hf]     - mn);
                    float p1 = __expf(sacc[nt][2 * hf + 1] - mn);
                    sacc[nt][2 * hf]     = p0;
                    sacc[nt][2 * hf + 1] = p1;
                    sum += p0 + p1;
                }
                sum += __shfl_xor_sync(0xffffffffu, sum, 1);
                sum += __shfl_xor_sync(0xffffffffu, sum, 2);
                lrow[hf] = lrow[hf] * corr + sum;
#pragma unroll
                for (int nt = 0; nt < 16; nt++) {
                    oacc[nt][2 * hf]     *= corr;
                    oacc[nt][2 * hf + 1] *= corr;
                }
            }

            // ---- O += P . V (1 pass, P single fp16)
#pragma unroll
            for (int j = 0; j < 4; j++) {
                uint32_t ph_[4];
                ph_[0] = pack_f16x2(sacc[2 * j][0],     sacc[2 * j][1]);
                ph_[1] = pack_f16x2(sacc[2 * j][2],     sacc[2 * j][3]);
                ph_[2] = pack_f16x2(sacc[2 * j + 1][0], sacc[2 * j + 1][1]);
                ph_[3] = pack_f16x2(sacc[2 * j + 1][2], sacc[2 * j + 1][3]);
#pragma unroll
                for (int np = 0; np < 8; np++) {
                    uint32_t vh_[4];
                    uint32_t vo = (uint32_t)((j * 16 + (lane & 7)
                                              + ((lane >> 3) & 1) * 8) * AROWB
                                             + (np * 16 + ((lane >> 4) << 3)) * 2);
                    ldsm_x4t(vh_[0], vh_[1], vh_[2], vh_[3], kvb + KV_VOFF + vo);
                    mma16816(oacc[2 * np],     ph_, vh_);
                    mma16816(oacc[2 * np + 1], ph_, vh_ + 2);
                }
            }
        }
        __syncthreads();   // all warps done reading buf

        if (kt + 2 < nkt) load_kv(buf, kt + 2);
        if (kt + 1 < nkt) {
            asm volatile("cp.async.wait_group %0;" :: "n"(1) : "memory");
        }
        if (kt + 1 < nkt && kt + 2 >= nkt) {
            asm volatile("cp.async.wait_group 0;" ::: "memory");
        }
        if (kt + 1 < nkt) __syncthreads();
    }

    // ---- epilogue: normalize + single fp16 write
    float inv0 = 1.0f / lrow[0];
    float inv1 = 1.0f / lrow[1];
    int r1 = q0 + 16 * w + (lane >> 2);
    size_t base1 = (size_t)r1 * HID + h * HD + (lane & 3) * 2;
    size_t base2 = base1 + (size_t)8 * HID;
#pragma unroll
    for (int nt = 0; nt < 16; nt++) {
        *(uint32_t*)(o + base1 + nt * 8) =
            pack_f16x2(oacc[nt][0] * inv0, oacc[nt][1] * inv0);
        *(uint32_t*)(o + base2 + nt * 8) =
            pack_f16x2(oacc[nt][2] * inv1, oacc[nt][3] * inv1);
    }
}

// ---------------------------------------------------------------------------
// Launch
// ---------------------------------------------------------------------------
extern "C" void kernel_launch(void* const* d_in, const int* in_sizes, int n_in,
                              void* d_out, int out_size)
{
    (void)in_sizes; (void)n_in; (void)out_size;
    const float* x     = (const float*)d_in[0];
    const int*   pos   = (const int*)d_in[1];
    const float* w_qkv = (const float*)d_in[2];
    const float* w_o   = (const float*)d_in[3];
    float*       out   = (float*)d_out;

    void *p_qkv, *p_xh, *p_xl, *p_wq, *p_wo, *p_sph, *p_spl, *p_attn;
    cudaGetSymbolAddress(&p_qkv, g_qkv);
    cudaGetSymbolAddress(&p_xh, g_x_hi);
    cudaGetSymbolAddress(&p_xl, g_x_lo);
    cudaGetSymbolAddress(&p_wq, g_wqkv);
    cudaGetSymbolAddress(&p_wo, g_wo);
    cudaGetSymbolAddress(&p_sph, g_qkvsp_hi);
    cudaGetSymbolAddress(&p_spl, g_qkvsp_lo);
    cudaGetSymbolAddress(&p_attn, g_attn);
    float* qkv = (float*)p_qkv;

    cudaFuncSetAttribute(gemm_mma_split_kernel,
                         cudaFuncAttributeMaxDynamicSharedMemorySize, GEMM_SMEM);
    cudaFuncSetAttribute(gemm_mma_kernel,
                         cudaFuncAttributeMaxDynamicSharedMemorySize, GEMM1_SMEM);
    cudaFuncSetAttribute(attn_mma_kernel,
                         cudaFuncAttributeMaxDynamicSharedMemorySize, ATTN_SMEM);

    // RoPE table
    rope_table_kernel<<<(S_LEN * 64 + 255) / 256, 256>>>(pos);

    // Converts
    {
        int n1 = S_LEN * HID / 8;
        convert_split_kernel<<<(n1 + 255) / 256, 256>>>(
            x, (__half*)p_xh, (__half*)p_xl, n1);
        int n2 = QKV_DIM * HID / 8;
        convert_half_kernel<<<(n2 + 255) / 256, 256>>>(w_qkv, (__half*)p_wq, n2);
        int n3 = HID * HID / 8;
        convert_half_kernel<<<(n3 + 255) / 256, 256>>>(w_o, (__half*)p_wo, n3);
    }

    // QKV projection (2-pass split)
    gemm_mma_split_kernel<<<dim3(S_LEN / 256, QKV_DIM / 128), 256, GEMM_SMEM>>>(
        (const __half*)p_xh, (const __half*)p_xl, (const __half*)p_wq,
        qkv, HID, QKV_DIM);

    // RoPE + split qkv
    postqkv_kernel<<<(S_LEN * 48 * 32 + 255) / 256, 256>>>(
        qkv, (__half*)p_sph, (__half*)p_spl);

    // Tensor-core flash attention (single-fp16 output)
    attn_mma_kernel<<<dim3(S_LEN / 128, NH), 256, ATTN_SMEM>>>(
        (const __half*)p_sph, (const __half*)p_spl, (__half*)p_attn);

    // Output projection (1-pass)
    gemm_mma_kernel<<<dim3(S_LEN / 256, HID / 128), 256, GEMM1_SMEM>>>(
        (const __half*)p_attn, (const __half*)p_wo, out, HID, HID);
}